// round 5
// baseline (speedup 1.0000x reference)
#include <cuda_runtime.h>
#include <math.h>

// Problem constants
constexpr int B_  = 2;
constexpr int C_  = 768;
constexpr int N_  = 2744;          // 14^3 tokens
constexpr int NH  = 12;
constexpr int DH  = 64;
constexpr int M_  = B_ * N_;       // 5488 total tokens

// Scratch (device globals; no allocation allowed)
__device__ float g_tn[M_ * C_];                 // layernormed tokens [m][c]
__device__ float g_q [B_ * NH * N_ * DH];       // [b][h][n][e]
__device__ float g_k [B_ * NH * N_ * DH];
__device__ float g_v [B_ * NH * N_ * DH];
__device__ float g_ao[M_ * C_];                 // attention output [m][c]

// ---------------------------------------------------------------------------
// Kernel 1: transpose b c n -> (b n) c  + LayerNorm over c
// ---------------------------------------------------------------------------
__global__ void ln_kernel(const float* __restrict__ x,
                          const float* __restrict__ w,
                          const float* __restrict__ bnorm) {
    __shared__ float tile[14 * 769];
    int b  = blockIdx.x / 196;          // 2744/14 = 196 tiles per batch
    int t0 = (blockIdx.x % 196) * 14;
    const float* xb = x + (size_t)b * C_ * N_;

    for (int idx = threadIdx.x; idx < C_ * 14; idx += 256) {
        int c = idx / 14, t = idx % 14;
        tile[t * 769 + c] = xb[c * N_ + t0 + t];
    }
    __syncthreads();

    int warp = threadIdx.x >> 5, lane = threadIdx.x & 31;
    for (int t = warp; t < 14; t += 8) {
        float s1 = 0.f, s2 = 0.f;
        for (int c = lane; c < C_; c += 32) {
            float v = tile[t * 769 + c];
            s1 += v; s2 += v * v;
        }
        #pragma unroll
        for (int off = 16; off; off >>= 1) {
            s1 += __shfl_xor_sync(0xffffffffu, s1, off);
            s2 += __shfl_xor_sync(0xffffffffu, s2, off);
        }
        float mu  = s1 * (1.f / C_);
        float var = s2 * (1.f / C_) - mu * mu;
        float inv = rsqrtf(var + 1e-5f);
        float* out = g_tn + (size_t)(b * N_ + t0 + t) * C_;
        for (int c = lane; c < C_; c += 32)
            out[c] = (tile[t * 769 + c] - mu) * inv * w[c] + bnorm[c];
    }
}

// ---------------------------------------------------------------------------
// Kernel 2: QKV GEMM.  out[m][j] = sum_k tn[m][k] * wqkv[j][k]
// ---------------------------------------------------------------------------
__global__ void qkv_kernel(const float* __restrict__ wqkv) {
    __shared__ float As[16 * 68];   // [k][m], padded
    __shared__ float Bs[16 * 68];   // [k][j], padded
    int m0 = blockIdx.y * 64;
    int j0 = blockIdx.x * 64;
    int tid = threadIdx.x;
    int ty = tid >> 4, tx = tid & 15;
    int arow = tid >> 2;            // 0..63
    int akq  = (tid & 3) * 4;       // 0,4,8,12
    float acc[4][4] = {};

    for (int k0 = 0; k0 < C_; k0 += 16) {
        float4 av = make_float4(0.f, 0.f, 0.f, 0.f);
        int m = m0 + arow;
        if (m < M_) av = *(const float4*)(g_tn + (size_t)m * C_ + k0 + akq);
        As[(akq + 0) * 68 + arow] = av.x;
        As[(akq + 1) * 68 + arow] = av.y;
        As[(akq + 2) * 68 + arow] = av.z;
        As[(akq + 3) * 68 + arow] = av.w;
        float4 bv = *(const float4*)(wqkv + (size_t)(j0 + arow) * C_ + k0 + akq);
        Bs[(akq + 0) * 68 + arow] = bv.x;
        Bs[(akq + 1) * 68 + arow] = bv.y;
        Bs[(akq + 2) * 68 + arow] = bv.z;
        Bs[(akq + 3) * 68 + arow] = bv.w;
        __syncthreads();

        #pragma unroll
        for (int k = 0; k < 16; ++k) {
            float4 a4 = *(const float4*)(As + k * 68 + ty * 4);
            float4 b4 = *(const float4*)(Bs + k * 68 + tx * 4);
            float a[4] = {a4.x, a4.y, a4.z, a4.w};
            float b[4] = {b4.x, b4.y, b4.z, b4.w};
            #pragma unroll
            for (int i = 0; i < 4; ++i)
                #pragma unroll
                for (int j = 0; j < 4; ++j)
                    acc[i][j] = fmaf(a[i], b[j], acc[i][j]);
        }
        __syncthreads();
    }

    int s = j0 / C_;
    int h = (j0 % C_) / DH;
    float* outp = (s == 0) ? g_q : ((s == 1) ? g_k : g_v);
    #pragma unroll
    for (int i = 0; i < 4; ++i) {
        int m = m0 + ty * 4 + i;
        if (m < M_) {
            int b = m / N_, n = m % N_;
            float4 v4 = make_float4(acc[i][0], acc[i][1], acc[i][2], acc[i][3]);
            *(float4*)(outp + (size_t)((b * NH + h) * N_ + n) * DH + tx * 4) = v4;
        }
    }
}

// ---------------------------------------------------------------------------
// Kernel 3: NAIVE attention — structurally trivial, fully decorrelated from
// the previous flash-style kernel. One warp per query. Keys strided across
// the 32 lanes; q cached in per-warp smem; o[64] in registers; l and o
// reduced ONCE at the end with full-warp xor shuffles; single division.
// Logits |s*scale| < ~4 so plain exp (no max subtraction) is exact in fp32.
// 2744 = 8*343, so every block's 8 queries are in range.
// ---------------------------------------------------------------------------
__global__ void attn_naive_kernel() {
    __shared__ float sq[8][64];
    int bh = blockIdx.x;                 // 0..23 = b*NH + h
    int w  = threadIdx.x >> 5;           // warp = local query 0..7
    int lane = threadIdx.x & 31;
    int n = blockIdx.y * 8 + w;          // global query index, always < N_

    const float* qp = g_q + ((size_t)bh * N_ + n) * DH;
    const float* kp = g_k + (size_t)bh * N_ * DH;
    const float* vp = g_v + (size_t)bh * N_ * DH;

    sq[w][lane]      = qp[lane];
    sq[w][lane + 32] = qp[lane + 32];
    __syncwarp();

    float o[64];
    #pragma unroll
    for (int e = 0; e < 64; ++e) o[e] = 0.f;
    float l = 0.f;

    for (int y = lane; y < N_; y += 32) {
        const float4* kr = (const float4*)(kp + (size_t)y * DH);
        float s0 = 0.f, s1 = 0.f, s2 = 0.f, s3 = 0.f;
        #pragma unroll
        for (int e4 = 0; e4 < 16; e4 += 4) {
            float4 k0 = kr[e4 + 0];
            float4 k1 = kr[e4 + 1];
            float4 k2 = kr[e4 + 2];
            float4 k3 = kr[e4 + 3];
            s0 = fmaf(sq[w][(e4+0)*4+0], k0.x, s0); s0 = fmaf(sq[w][(e4+0)*4+1], k0.y, s0);
            s0 = fmaf(sq[w][(e4+0)*4+2], k0.z, s0); s0 = fmaf(sq[w][(e4+0)*4+3], k0.w, s0);
            s1 = fmaf(sq[w][(e4+1)*4+0], k1.x, s1); s1 = fmaf(sq[w][(e4+1)*4+1], k1.y, s1);
            s1 = fmaf(sq[w][(e4+1)*4+2], k1.z, s1); s1 = fmaf(sq[w][(e4+1)*4+3], k1.w, s1);
            s2 = fmaf(sq[w][(e4+2)*4+0], k2.x, s2); s2 = fmaf(sq[w][(e4+2)*4+1], k2.y, s2);
            s2 = fmaf(sq[w][(e4+2)*4+2], k2.z, s2); s2 = fmaf(sq[w][(e4+2)*4+3], k2.w, s2);
            s3 = fmaf(sq[w][(e4+3)*4+0], k3.x, s3); s3 = fmaf(sq[w][(e4+3)*4+1], k3.y, s3);
            s3 = fmaf(sq[w][(e4+3)*4+2], k3.z, s3); s3 = fmaf(sq[w][(e4+3)*4+3], k3.w, s3);
        }
        float s = (s0 + s1) + (s2 + s3);
        float p = expf(s * 0.125f);      // scale = 64^-0.5
        l += p;

        const float4* vr = (const float4*)(vp + (size_t)y * DH);
        #pragma unroll
        for (int e4 = 0; e4 < 16; ++e4) {
            float4 vv = vr[e4];
            o[e4*4+0] = fmaf(p, vv.x, o[e4*4+0]);
            o[e4*4+1] = fmaf(p, vv.y, o[e4*4+1]);
            o[e4*4+2] = fmaf(p, vv.z, o[e4*4+2]);
            o[e4*4+3] = fmaf(p, vv.w, o[e4*4+3]);
        }
    }

    // Full-warp reductions (all 32 lanes, offsets 16..1).
    #pragma unroll
    for (int off = 16; off; off >>= 1)
        l += __shfl_xor_sync(0xffffffffu, l, off);
    #pragma unroll
    for (int e = 0; e < 64; ++e) {
        #pragma unroll
        for (int off = 16; off; off >>= 1)
            o[e] += __shfl_xor_sync(0xffffffffu, o[e], off);
    }

    if (lane == 0) {
        float invl = 1.f / l;
        int b = bh / NH, h = bh % NH;
        float* ao = g_ao + (size_t)(b * N_ + n) * C_ + h * DH;
        #pragma unroll
        for (int e = 0; e < 64; ++e)
            ao[e] = o[e] * invl;
    }
}

// ---------------------------------------------------------------------------
// Kernel 4: out projection + bias + residual + transpose back to [b][c][n]
// ---------------------------------------------------------------------------
__global__ void proj_kernel(const float* __restrict__ wout,
                            const float* __restrict__ bout,
                            const float* __restrict__ x,
                            float* __restrict__ out) {
    __shared__ float As[16 * 68];
    __shared__ float Bs[16 * 68];
    __shared__ float Ts[64 * 65];   // [token_local][c_local]
    int m0 = blockIdx.y * 64;
    int c0 = blockIdx.x * 64;
    int tid = threadIdx.x;
    int ty = tid >> 4, tx = tid & 15;
    int arow = tid >> 2;
    int akq  = (tid & 3) * 4;
    float acc[4][4] = {};

    for (int k0 = 0; k0 < C_; k0 += 16) {
        float4 av = make_float4(0.f, 0.f, 0.f, 0.f);
        int m = m0 + arow;
        if (m < M_) av = *(const float4*)(g_ao + (size_t)m * C_ + k0 + akq);
        As[(akq + 0) * 68 + arow] = av.x;
        As[(akq + 1) * 68 + arow] = av.y;
        As[(akq + 2) * 68 + arow] = av.z;
        As[(akq + 3) * 68 + arow] = av.w;
        float4 bv = *(const float4*)(wout + (size_t)(c0 + arow) * C_ + k0 + akq);
        Bs[(akq + 0) * 68 + arow] = bv.x;
        Bs[(akq + 1) * 68 + arow] = bv.y;
        Bs[(akq + 2) * 68 + arow] = bv.z;
        Bs[(akq + 3) * 68 + arow] = bv.w;
        __syncthreads();

        #pragma unroll
        for (int k = 0; k < 16; ++k) {
            float4 a4 = *(const float4*)(As + k * 68 + ty * 4);
            float4 b4 = *(const float4*)(Bs + k * 68 + tx * 4);
            float a[4] = {a4.x, a4.y, a4.z, a4.w};
            float b[4] = {b4.x, b4.y, b4.z, b4.w};
            #pragma unroll
            for (int i = 0; i < 4; ++i)
                #pragma unroll
                for (int j = 0; j < 4; ++j)
                    acc[i][j] = fmaf(a[i], b[j], acc[i][j]);
        }
        __syncthreads();
    }

    #pragma unroll
    for (int i = 0; i < 4; ++i)
        #pragma unroll
        for (int j = 0; j < 4; ++j)
            Ts[(ty * 4 + i) * 65 + tx * 4 + j] = acc[i][j] + bout[c0 + tx * 4 + j];
    __syncthreads();

    for (int t = tid; t < 64 * 64; t += 256) {
        int cl = t >> 6, ml = t & 63;
        int m = m0 + ml;
        if (m < M_) {
            int b = m / N_, n = m % N_;
            size_t gi = (size_t)(b * C_ + c0 + cl) * N_ + n;
            out[gi] = Ts[ml * 65 + cl] + x[gi];
        }
    }
}

// ---------------------------------------------------------------------------
extern "C" void kernel_launch(void* const* d_in, const int* in_sizes, int n_in,
                              void* d_out, int out_size) {
    // Robust input dispatch: identify tensors by element count; the three
    // 768-length vectors are taken in order of appearance (norm_w, norm_b, out_b).
    const float* x      = nullptr;
    const float* norm_w = nullptr;
    const float* norm_b = nullptr;
    const float* qkv_w  = nullptr;
    const float* out_w  = nullptr;
    const float* out_b  = nullptr;
    int small_seen = 0;
    for (int i = 0; i < n_in; ++i) {
        const float* p = (const float*)d_in[i];
        int sz = in_sizes[i];
        if      (sz == B_ * C_ * N_)     x     = p;   // 4214784
        else if (sz == 3 * C_ * C_)      qkv_w = p;   // 1769472
        else if (sz == C_ * C_)          out_w = p;   // 589824
        else if (sz == C_) {
            if      (small_seen == 0) norm_w = p;
            else if (small_seen == 1) norm_b = p;
            else                      out_b  = p;
            ++small_seen;
        }
    }
    float* out = (float*)d_out;
    (void)out_size;

    ln_kernel<<<B_ * 196, 256>>>(x, norm_w, norm_b);
    qkv_kernel<<<dim3(3 * C_ / 64, (M_ + 63) / 64), 256>>>(qkv_w);
    attn_naive_kernel<<<dim3(B_ * NH, N_ / 8), 256>>>();
    proj_kernel<<<dim3(C_ / 64, (M_ + 63) / 64), 256>>>(out_w, out_b, x, out);
}

// round 6
// speedup vs baseline: 9.8812x; 9.8812x over previous
#include <cuda_runtime.h>
#include <math.h>

// Problem constants
constexpr int B_  = 2;
constexpr int C_  = 768;
constexpr int N_  = 2744;          // 14^3 tokens
constexpr int NH  = 12;
constexpr int DH  = 64;
constexpr int M_  = B_ * N_;       // 5488 total tokens

// Scratch (device globals; no allocation allowed)
__device__ float g_tn[M_ * C_];                 // layernormed tokens [m][c]
__device__ float g_q [B_ * NH * N_ * DH];       // [b][h][n][e]
__device__ float g_k [B_ * NH * N_ * DH];
__device__ float g_v [B_ * NH * N_ * DH];
__device__ float g_ao[M_ * C_];                 // attention output [m][c]

// ---------------------------------------------------------------------------
// Kernel 1: transpose b c n -> (b n) c  + LayerNorm over c
// ---------------------------------------------------------------------------
__global__ void ln_kernel(const float* __restrict__ x,
                          const float* __restrict__ w,
                          const float* __restrict__ bnorm) {
    __shared__ float tile[14 * 769];
    int b  = blockIdx.x / 196;          // 2744/14 = 196 tiles per batch
    int t0 = (blockIdx.x % 196) * 14;
    const float* xb = x + (size_t)b * C_ * N_;

    for (int idx = threadIdx.x; idx < C_ * 14; idx += 256) {
        int c = idx / 14, t = idx % 14;
        tile[t * 769 + c] = xb[c * N_ + t0 + t];
    }
    __syncthreads();

    int warp = threadIdx.x >> 5, lane = threadIdx.x & 31;
    for (int t = warp; t < 14; t += 8) {
        float s1 = 0.f, s2 = 0.f;
        for (int c = lane; c < C_; c += 32) {
            float v = tile[t * 769 + c];
            s1 += v; s2 += v * v;
        }
        #pragma unroll
        for (int off = 16; off; off >>= 1) {
            s1 += __shfl_xor_sync(0xffffffffu, s1, off);
            s2 += __shfl_xor_sync(0xffffffffu, s2, off);
        }
        float mu  = s1 * (1.f / C_);
        float var = s2 * (1.f / C_) - mu * mu;
        float inv = rsqrtf(var + 1e-5f);
        float* out = g_tn + (size_t)(b * N_ + t0 + t) * C_;
        for (int c = lane; c < C_; c += 32)
            out[c] = (tile[t * 769 + c] - mu) * inv * w[c] + bnorm[c];
    }
}

// ---------------------------------------------------------------------------
// Kernel 2: QKV GEMM.  out[m][j] = sum_k tn[m][k] * wqkv[j][k]
// ---------------------------------------------------------------------------
__global__ void qkv_kernel(const float* __restrict__ wqkv) {
    __shared__ float As[16 * 68];   // [k][m], padded
    __shared__ float Bs[16 * 68];   // [k][j], padded
    int m0 = blockIdx.y * 64;
    int j0 = blockIdx.x * 64;
    int tid = threadIdx.x;
    int ty = tid >> 4, tx = tid & 15;
    int arow = tid >> 2;            // 0..63
    int akq  = (tid & 3) * 4;       // 0,4,8,12  (K-chunk is only 16 wide: full coverage)
    float acc[4][4] = {};

    for (int k0 = 0; k0 < C_; k0 += 16) {
        float4 av = make_float4(0.f, 0.f, 0.f, 0.f);
        int m = m0 + arow;
        if (m < M_) av = *(const float4*)(g_tn + (size_t)m * C_ + k0 + akq);
        As[(akq + 0) * 68 + arow] = av.x;
        As[(akq + 1) * 68 + arow] = av.y;
        As[(akq + 2) * 68 + arow] = av.z;
        As[(akq + 3) * 68 + arow] = av.w;
        float4 bv = *(const float4*)(wqkv + (size_t)(j0 + arow) * C_ + k0 + akq);
        Bs[(akq + 0) * 68 + arow] = bv.x;
        Bs[(akq + 1) * 68 + arow] = bv.y;
        Bs[(akq + 2) * 68 + arow] = bv.z;
        Bs[(akq + 3) * 68 + arow] = bv.w;
        __syncthreads();

        #pragma unroll
        for (int k = 0; k < 16; ++k) {
            float4 a4 = *(const float4*)(As + k * 68 + ty * 4);
            float4 b4 = *(const float4*)(Bs + k * 68 + tx * 4);
            float a[4] = {a4.x, a4.y, a4.z, a4.w};
            float b[4] = {b4.x, b4.y, b4.z, b4.w};
            #pragma unroll
            for (int i = 0; i < 4; ++i)
                #pragma unroll
                for (int j = 0; j < 4; ++j)
                    acc[i][j] = fmaf(a[i], b[j], acc[i][j]);
        }
        __syncthreads();
    }

    int s = j0 / C_;
    int h = (j0 % C_) / DH;
    float* outp = (s == 0) ? g_q : ((s == 1) ? g_k : g_v);
    #pragma unroll
    for (int i = 0; i < 4; ++i) {
        int m = m0 + ty * 4 + i;
        if (m < M_) {
            int b = m / N_, n = m % N_;
            float4 v4 = make_float4(acc[i][0], acc[i][1], acc[i][2], acc[i][3]);
            *(float4*)(outp + (size_t)((b * NH + h) * N_ + n) * DH + tx * 4) = v4;
        }
    }
}

// ---------------------------------------------------------------------------
// Kernel 3: tiled attention (fixed staging).
// ROOT-CAUSE FIX vs rounds 0/3: staging previously wrote only e=0..15 of each
// 64x64 Q/K/V tile (256 threads x 4 floats = 1/4 of the tile); e=16..63 were
// uninitialized smem. Now each thread stages 4 float4s: e = (tid&3)*4 + 16*r,
// r=0..3 -> exact 64x64 coverage.
// Softmax: plain exp (logits bounded, shift-invariant), per-thread l,
// single 16-lane reduction at the end — logic validated by the naive kernel.
// ---------------------------------------------------------------------------
__global__ void attn_kernel() {
    extern __shared__ float sm[];
    float* Qs = sm;                 // [e][q]
    float* Ks = sm + 64 * 68;       // [e][kk]
    float* Vs = sm + 2 * 64 * 68;   // [kk][e]
    float* Ps = sm + 3 * 64 * 68;   // [kk][q]

    int bh = blockIdx.x;            // 0..23
    int q0 = blockIdx.y * 64;
    const float* qb = g_q + (size_t)bh * N_ * DH;
    const float* kb = g_k + (size_t)bh * N_ * DH;
    const float* vb = g_v + (size_t)bh * N_ * DH;

    int tid = threadIdx.x;
    int ty = tid >> 4, tx = tid & 15;   // ty: query group, tx: key/e group
    int lrow = tid >> 2;                // 0..63 tile row
    int lq4  = tid & 3;                 // quarter selector

    {   // Q tile, transposed into smem: Qs[e][q] — FULL 64 e coverage
        int n = q0 + lrow;
        bool ok = (n < N_);
        const float4* qr = (const float4*)(qb + (size_t)n * DH);
        #pragma unroll
        for (int r = 0; r < 4; ++r) {
            int e = lq4 * 4 + r * 16;
            float4 qv = make_float4(0.f, 0.f, 0.f, 0.f);
            if (ok) qv = qr[e >> 2];
            Qs[(e + 0) * 68 + lrow] = qv.x;
            Qs[(e + 1) * 68 + lrow] = qv.y;
            Qs[(e + 2) * 68 + lrow] = qv.z;
            Qs[(e + 3) * 68 + lrow] = qv.w;
        }
    }

    float o[4][4]  = {};
    float l4[4]    = {0.f, 0.f, 0.f, 0.f};
    const float scale = 0.125f;     // 64^-0.5

    for (int kb0 = 0; kb0 < N_; kb0 += 64) {
        __syncthreads();            // prev-iter readers of Ks/Vs/Ps done
        {   // K/V tiles — FULL 64 e coverage
            int n = kb0 + lrow;
            bool ok = (n < N_);
            const float4* kr = (const float4*)(kb + (size_t)n * DH);
            const float4* vr = (const float4*)(vb + (size_t)n * DH);
            #pragma unroll
            for (int r = 0; r < 4; ++r) {
                int e = lq4 * 4 + r * 16;
                float4 kv = make_float4(0.f, 0.f, 0.f, 0.f);
                float4 vv = kv;
                if (ok) { kv = kr[e >> 2]; vv = vr[e >> 2]; }
                Ks[(e + 0) * 68 + lrow] = kv.x;
                Ks[(e + 1) * 68 + lrow] = kv.y;
                Ks[(e + 2) * 68 + lrow] = kv.z;
                Ks[(e + 3) * 68 + lrow] = kv.w;
                *(float4*)(Vs + lrow * 68 + e) = vv;
            }
        }
        __syncthreads();

        // S = Q K^T  (full rank-64 accumulation)
        float s[4][4] = {};
        #pragma unroll 16
        for (int e = 0; e < 64; ++e) {
            float4 a4 = *(const float4*)(Qs + e * 68 + ty * 4);
            float4 b4 = *(const float4*)(Ks + e * 68 + tx * 4);
            float a[4] = {a4.x, a4.y, a4.z, a4.w};
            float b[4] = {b4.x, b4.y, b4.z, b4.w};
            #pragma unroll
            for (int i = 0; i < 4; ++i)
                #pragma unroll
                for (int j = 0; j < 4; ++j)
                    s[i][j] = fmaf(a[i], b[j], s[i][j]);
        }

        // p = exp(scale * s); out-of-range keys contribute exactly 0
        #pragma unroll
        for (int j = 0; j < 4; ++j) {
            bool bad = (kb0 + tx * 4 + j) >= N_;
            #pragma unroll
            for (int i = 0; i < 4; ++i) {
                float p = bad ? 0.f : __expf(s[i][j] * scale);
                l4[i] += p;
                Ps[(tx * 4 + j) * 68 + ty * 4 + i] = p;   // Ps[kk][q]
            }
        }
        __syncthreads();

        // O += P V
        #pragma unroll 16
        for (int kk = 0; kk < 64; ++kk) {
            float4 a4 = *(const float4*)(Ps + kk * 68 + ty * 4);
            float4 b4 = *(const float4*)(Vs + kk * 68 + tx * 4);
            float a[4] = {a4.x, a4.y, a4.z, a4.w};
            float b[4] = {b4.x, b4.y, b4.z, b4.w};
            #pragma unroll
            for (int i = 0; i < 4; ++i)
                #pragma unroll
                for (int j = 0; j < 4; ++j)
                    o[i][j] = fmaf(a[i], b[j], o[i][j]);
        }
    }

    // Final softmax-denominator reduction across the 16 lanes sharing ty.
    #pragma unroll
    for (int i = 0; i < 4; ++i)
        #pragma unroll
        for (int off = 1; off < 16; off <<= 1)
            l4[i] += __shfl_xor_sync(0xffffffffu, l4[i], off);

    // write to g_ao[b][n][h*64 + e]
    int b = bh / NH, h = bh % NH;
    #pragma unroll
    for (int i = 0; i < 4; ++i) {
        int n = q0 + ty * 4 + i;
        if (n < N_) {
            float invl = 1.f / l4[i];
            float4 v4 = make_float4(o[i][0] * invl, o[i][1] * invl,
                                    o[i][2] * invl, o[i][3] * invl);
            *(float4*)(g_ao + (size_t)(b * N_ + n) * C_ + h * DH + tx * 4) = v4;
        }
    }
}

// ---------------------------------------------------------------------------
// Kernel 4: out projection + bias + residual + transpose back to [b][c][n]
// ---------------------------------------------------------------------------
__global__ void proj_kernel(const float* __restrict__ wout,
                            const float* __restrict__ bout,
                            const float* __restrict__ x,
                            float* __restrict__ out) {
    __shared__ float As[16 * 68];
    __shared__ float Bs[16 * 68];
    __shared__ float Ts[64 * 65];   // [token_local][c_local]
    int m0 = blockIdx.y * 64;
    int c0 = blockIdx.x * 64;
    int tid = threadIdx.x;
    int ty = tid >> 4, tx = tid & 15;
    int arow = tid >> 2;
    int akq  = (tid & 3) * 4;
    float acc[4][4] = {};

    for (int k0 = 0; k0 < C_; k0 += 16) {
        float4 av = make_float4(0.f, 0.f, 0.f, 0.f);
        int m = m0 + arow;
        if (m < M_) av = *(const float4*)(g_ao + (size_t)m * C_ + k0 + akq);
        As[(akq + 0) * 68 + arow] = av.x;
        As[(akq + 1) * 68 + arow] = av.y;
        As[(akq + 2) * 68 + arow] = av.z;
        As[(akq + 3) * 68 + arow] = av.w;
        float4 bv = *(const float4*)(wout + (size_t)(c0 + arow) * C_ + k0 + akq);
        Bs[(akq + 0) * 68 + arow] = bv.x;
        Bs[(akq + 1) * 68 + arow] = bv.y;
        Bs[(akq + 2) * 68 + arow] = bv.z;
        Bs[(akq + 3) * 68 + arow] = bv.w;
        __syncthreads();

        #pragma unroll
        for (int k = 0; k < 16; ++k) {
            float4 a4 = *(const float4*)(As + k * 68 + ty * 4);
            float4 b4 = *(const float4*)(Bs + k * 68 + tx * 4);
            float a[4] = {a4.x, a4.y, a4.z, a4.w};
            float b[4] = {b4.x, b4.y, b4.z, b4.w};
            #pragma unroll
            for (int i = 0; i < 4; ++i)
                #pragma unroll
                for (int j = 0; j < 4; ++j)
                    acc[i][j] = fmaf(a[i], b[j], acc[i][j]);
        }
        __syncthreads();
    }

    #pragma unroll
    for (int i = 0; i < 4; ++i)
        #pragma unroll
        for (int j = 0; j < 4; ++j)
            Ts[(ty * 4 + i) * 65 + tx * 4 + j] = acc[i][j] + bout[c0 + tx * 4 + j];
    __syncthreads();

    for (int t = tid; t < 64 * 64; t += 256) {
        int cl = t >> 6, ml = t & 63;
        int m = m0 + ml;
        if (m < M_) {
            int b = m / N_, n = m % N_;
            size_t gi = (size_t)(b * C_ + c0 + cl) * N_ + n;
            out[gi] = Ts[ml * 65 + cl] + x[gi];
        }
    }
}

// ---------------------------------------------------------------------------
extern "C" void kernel_launch(void* const* d_in, const int* in_sizes, int n_in,
                              void* d_out, int out_size) {
    // Identify tensors by element count; the three 768-length vectors are
    // taken in order of appearance (norm_w, norm_b, out_b).
    const float* x      = nullptr;
    const float* norm_w = nullptr;
    const float* norm_b = nullptr;
    const float* qkv_w  = nullptr;
    const float* out_w  = nullptr;
    const float* out_b  = nullptr;
    int small_seen = 0;
    for (int i = 0; i < n_in; ++i) {
        const float* p = (const float*)d_in[i];
        int sz = in_sizes[i];
        if      (sz == B_ * C_ * N_)     x     = p;   // 4214784
        else if (sz == 3 * C_ * C_)      qkv_w = p;   // 1769472
        else if (sz == C_ * C_)          out_w = p;   // 589824
        else if (sz == C_) {
            if      (small_seen == 0) norm_w = p;
            else if (small_seen == 1) norm_b = p;
            else                      out_b  = p;
            ++small_seen;
        }
    }
    float* out = (float*)d_out;
    (void)out_size;

    // Idempotent, host-side, capture-safe.
    cudaFuncSetAttribute(attn_kernel,
                         cudaFuncAttributeMaxDynamicSharedMemorySize,
                         4 * 64 * 68 * (int)sizeof(float));

    ln_kernel<<<B_ * 196, 256>>>(x, norm_w, norm_b);
    qkv_kernel<<<dim3(3 * C_ / 64, (M_ + 63) / 64), 256>>>(qkv_w);
    attn_kernel<<<dim3(B_ * NH, (N_ + 63) / 64), 256,
                  4 * 64 * 68 * (int)sizeof(float)>>>();
    proj_kernel<<<dim3(C_ / 64, (M_ + 63) / 64), 256>>>(out_w, out_b, x, out);
}

// round 8
// speedup vs baseline: 16.9755x; 1.7180x over previous
#include <cuda_runtime.h>
#include <cuda_bf16.h>
#include <math.h>

// Problem constants
constexpr int B_  = 2;
constexpr int C_  = 768;
constexpr int N_  = 2744;          // 14^3 tokens
constexpr int NH  = 12;
constexpr int DH  = 64;
constexpr int M_  = B_ * N_;       // 5488 total tokens

// Scratch (device globals; no allocation allowed)
__device__ float g_tn[M_ * C_];                 // layernormed tokens [m][c]
__device__ float g_q [B_ * NH * N_ * DH];       // [b][h][n][e]
__device__ float g_k [B_ * NH * N_ * DH];
__device__ float g_v [B_ * NH * N_ * DH];
__device__ float g_ao[M_ * C_];                 // attention output [m][c]

// ---------------------------------------------------------------------------
// Helpers: bf16 packing + warp-level mma
// ---------------------------------------------------------------------------
__device__ __forceinline__ unsigned pack_bf16(float lo, float hi) {
    unsigned r;
    // cvt.bf16x2: first source -> upper half, second -> lower half
    asm("cvt.rn.bf16x2.f32 %0, %1, %2;" : "=r"(r) : "f"(hi), "f"(lo));
    return r;
}

// D(16x8,f32) += A(16x16,bf16,row) * B(16x8,bf16,col)
__device__ __forceinline__ void mma16816(float* d, const unsigned* a,
                                         unsigned b0, unsigned b1) {
    asm volatile(
        "mma.sync.aligned.m16n8k16.row.col.f32.bf16.bf16.f32 "
        "{%0,%1,%2,%3}, {%4,%5,%6,%7}, {%8,%9}, {%0,%1,%2,%3};"
        : "+f"(d[0]), "+f"(d[1]), "+f"(d[2]), "+f"(d[3])
        : "r"(a[0]), "r"(a[1]), "r"(a[2]), "r"(a[3]), "r"(b0), "r"(b1));
}

// ---------------------------------------------------------------------------
// Kernel 1: transpose b c n -> (b n) c  + LayerNorm over c
// ---------------------------------------------------------------------------
__global__ void ln_kernel(const float* __restrict__ x,
                          const float* __restrict__ w,
                          const float* __restrict__ bnorm) {
    __shared__ float tile[14 * 769];
    int b  = blockIdx.x / 196;
    int t0 = (blockIdx.x % 196) * 14;
    const float* xb = x + (size_t)b * C_ * N_;

    for (int idx = threadIdx.x; idx < C_ * 14; idx += 256) {
        int c = idx / 14, t = idx % 14;
        tile[t * 769 + c] = xb[c * N_ + t0 + t];
    }
    __syncthreads();

    int warp = threadIdx.x >> 5, lane = threadIdx.x & 31;
    for (int t = warp; t < 14; t += 8) {
        float s1 = 0.f, s2 = 0.f;
        for (int c = lane; c < C_; c += 32) {
            float v = tile[t * 769 + c];
            s1 += v; s2 += v * v;
        }
        #pragma unroll
        for (int off = 16; off; off >>= 1) {
            s1 += __shfl_xor_sync(0xffffffffu, s1, off);
            s2 += __shfl_xor_sync(0xffffffffu, s2, off);
        }
        float mu  = s1 * (1.f / C_);
        float var = s2 * (1.f / C_) - mu * mu;
        float inv = rsqrtf(var + 1e-5f);
        float* out = g_tn + (size_t)(b * N_ + t0 + t) * C_;
        for (int c = lane; c < C_; c += 32)
            out[c] = (tile[t * 769 + c] - mu) * inv * w[c] + bnorm[c];
    }
}

// ---------------------------------------------------------------------------
// Kernel 2: QKV GEMM (fp32 template, proven).
// ---------------------------------------------------------------------------
__global__ void qkv_kernel(const float* __restrict__ wqkv) {
    __shared__ float As[16 * 68];
    __shared__ float Bs[16 * 68];
    int m0 = blockIdx.y * 64;
    int j0 = blockIdx.x * 64;
    int tid = threadIdx.x;
    int ty = tid >> 4, tx = tid & 15;
    int arow = tid >> 2;
    int akq  = (tid & 3) * 4;
    float acc[4][4] = {};

    for (int k0 = 0; k0 < C_; k0 += 16) {
        float4 av = make_float4(0.f, 0.f, 0.f, 0.f);
        int m = m0 + arow;
        if (m < M_) av = *(const float4*)(g_tn + (size_t)m * C_ + k0 + akq);
        As[(akq + 0) * 68 + arow] = av.x;
        As[(akq + 1) * 68 + arow] = av.y;
        As[(akq + 2) * 68 + arow] = av.z;
        As[(akq + 3) * 68 + arow] = av.w;
        float4 bv = *(const float4*)(wqkv + (size_t)(j0 + arow) * C_ + k0 + akq);
        Bs[(akq + 0) * 68 + arow] = bv.x;
        Bs[(akq + 1) * 68 + arow] = bv.y;
        Bs[(akq + 2) * 68 + arow] = bv.z;
        Bs[(akq + 3) * 68 + arow] = bv.w;
        __syncthreads();

        #pragma unroll
        for (int k = 0; k < 16; ++k) {
            float4 a4 = *(const float4*)(As + k * 68 + ty * 4);
            float4 b4 = *(const float4*)(Bs + k * 68 + tx * 4);
            float a[4] = {a4.x, a4.y, a4.z, a4.w};
            float b[4] = {b4.x, b4.y, b4.z, b4.w};
            #pragma unroll
            for (int i = 0; i < 4; ++i)
                #pragma unroll
                for (int j = 0; j < 4; ++j)
                    acc[i][j] = fmaf(a[i], b[j], acc[i][j]);
        }
        __syncthreads();
    }

    int s = j0 / C_;
    int h = (j0 % C_) / DH;
    float* outp = (s == 0) ? g_q : ((s == 1) ? g_k : g_v);
    #pragma unroll
    for (int i = 0; i < 4; ++i) {
        int m = m0 + ty * 4 + i;
        if (m < M_) {
            int b = m / N_, n = m % N_;
            float4 v4 = make_float4(acc[i][0], acc[i][1], acc[i][2], acc[i][3]);
            *(float4*)(outp + (size_t)((b * NH + h) * N_ + n) * DH + tx * 4) = v4;
        }
    }
}

// ---------------------------------------------------------------------------
// Kernel 3: tensor-core attention (bf16 mma.sync m16n8k16, fp32 accum).
// 64q x 64k tiles, 8 warps. Warp w: m-tile rows mr=(w&3)*16, col half
// nb=(w>>2)*32 (keys for S / e for PV). Q cached in a-frags; K staged bf16
// [kk][e]; V staged transposed [e][kk]; P via smem bf16 [q][kk].
// Softmax: plain exp (logits bounded), per-thread l partials, single final
// reduce (quad shuffles + 2-way smem combine). Masking by explicit p=0.
// Smem rows padded to 72 halves (36 u32): frag loads are bank-conflict-free.
// ---------------------------------------------------------------------------
__global__ void __launch_bounds__(256) attn_mma_kernel() {
    __shared__ unsigned Qs[64 * 36];
    __shared__ unsigned Ks[64 * 36];
    __shared__ unsigned Vt[64 * 36];
    __shared__ unsigned Ps[64 * 36];
    __shared__ float    Lsm[2][64];

    int bh = blockIdx.x;            // 0..23
    int q0 = blockIdx.y * 64;
    const float* qb = g_q + (size_t)bh * N_ * DH;
    const float* kb = g_k + (size_t)bh * N_ * DH;
    const float* vb = g_v + (size_t)bh * N_ * DH;

    int tid  = threadIdx.x;
    int w    = tid >> 5, lane = tid & 31;
    int mr   = (w & 3) * 16;        // m-tile row base
    int nb   = (w >> 2) * 32;       // n half base
    int gr   = lane >> 2;           // group row 0..7
    int qd   = lane & 3;            // quad lane 0..3

    // ---- stage Q tile as bf16 [q][e] (stride 72 halves) ----
    {
        int row = tid >> 2, q4 = tid & 3;
        int n = q0 + row;
        unsigned* dst = Qs + row * 36 + q4 * 8;
        if (n < N_) {
            const float4* src = (const float4*)(qb + (size_t)n * DH + q4 * 16);
            #pragma unroll
            for (int r = 0; r < 4; ++r) {
                float4 v = src[r];
                dst[r * 2 + 0] = pack_bf16(v.x, v.y);
                dst[r * 2 + 1] = pack_bf16(v.z, v.w);
            }
        } else {
            #pragma unroll
            for (int r = 0; r < 8; ++r) dst[r] = 0u;
        }
    }
    __syncthreads();

    // ---- cache Q a-frags: qa[kstep][4] ----
    unsigned qa[4][4];
    #pragma unroll
    for (int ks = 0; ks < 4; ++ks) {
        int c = ks * 8 + qd;        // u32 column = (ks*16 + qd*2)/2
        qa[ks][0] = Qs[(mr + gr    ) * 36 + c];
        qa[ks][1] = Qs[(mr + gr + 8) * 36 + c];
        qa[ks][2] = Qs[(mr + gr    ) * 36 + c + 4];
        qa[ks][3] = Qs[(mr + gr + 8) * 36 + c + 4];
    }

    float of[4][4] = {};            // O accum, 4 n-tiles x 4
    float lp0 = 0.f, lp1 = 0.f;     // l partials for rows mr+gr, mr+gr+8

    for (int kb0 = 0; kb0 < N_; kb0 += 64) {
        __syncthreads();            // prev-iter consumers of Ks/Vt/Ps done
        // ---- stage K [kk][e] and Vt [e][kk] as bf16 ----
        {
            int row = tid >> 2, q4 = tid & 3;
            int n = kb0 + row;
            bool ok = (n < N_);
            unsigned* kd = Ks + row * 36 + q4 * 8;
            __nv_bfloat16* vt16 = reinterpret_cast<__nv_bfloat16*>(Vt);
            const float4* ksrc = (const float4*)(kb + (size_t)n * DH + q4 * 16);
            const float4* vsrc = (const float4*)(vb + (size_t)n * DH + q4 * 16);
            #pragma unroll
            for (int r = 0; r < 4; ++r) {
                float4 kv = make_float4(0.f, 0.f, 0.f, 0.f);
                float4 vv = kv;
                if (ok) { kv = ksrc[r]; vv = vsrc[r]; }
                kd[r * 2 + 0] = pack_bf16(kv.x, kv.y);
                kd[r * 2 + 1] = pack_bf16(kv.z, kv.w);
                int e = q4 * 16 + r * 4;
                vt16[(e + 0) * 72 + row] = __float2bfloat16(vv.x);
                vt16[(e + 1) * 72 + row] = __float2bfloat16(vv.y);
                vt16[(e + 2) * 72 + row] = __float2bfloat16(vv.z);
                vt16[(e + 3) * 72 + row] = __float2bfloat16(vv.w);
            }
        }
        __syncthreads();

        // ---- S = Q K^T for this warp's 4 n-tiles ----
        float sf[4][4] = {};
        #pragma unroll
        for (int ks = 0; ks < 4; ++ks) {
            #pragma unroll
            for (int t = 0; t < 4; ++t) {
                int n0 = nb + t * 8 + gr;
                unsigned b0 = Ks[n0 * 36 + ks * 8 + qd];
                unsigned b1 = Ks[n0 * 36 + ks * 8 + qd + 4];
                mma16816(sf[t], qa[ks], b0, b1);
            }
        }

        // ---- p = exp(scale*s), mask, accumulate l, store Ps bf16 ----
        #pragma unroll
        for (int t = 0; t < 4; ++t) {
            int kcol = nb + t * 8 + qd * 2;   // tile-local key col (even)
            int gk = kb0 + kcol;
            bool v0 = gk < N_, v1 = (gk + 1) < N_;
            float p0 = v0 ? __expf(sf[t][0] * 0.125f) : 0.f;
            float p1 = v1 ? __expf(sf[t][1] * 0.125f) : 0.f;
            float p2 = v0 ? __expf(sf[t][2] * 0.125f) : 0.f;
            float p3 = v1 ? __expf(sf[t][3] * 0.125f) : 0.f;
            lp0 += p0 + p1;
            lp1 += p2 + p3;
            Ps[(mr + gr    ) * 36 + (kcol >> 1)] = pack_bf16(p0, p1);
            Ps[(mr + gr + 8) * 36 + (kcol >> 1)] = pack_bf16(p2, p3);
        }
        __syncthreads();            // all warps' Ps ready

        // ---- O += P V (A from Ps, B from Vt) ----
        #pragma unroll
        for (int ks = 0; ks < 4; ++ks) {
            int c = ks * 8 + qd;
            unsigned a[4];
            a[0] = Ps[(mr + gr    ) * 36 + c];
            a[1] = Ps[(mr + gr + 8) * 36 + c];
            a[2] = Ps[(mr + gr    ) * 36 + c + 4];
            a[3] = Ps[(mr + gr + 8) * 36 + c + 4];
            #pragma unroll
            for (int t = 0; t < 4; ++t) {
                int e0 = nb + t * 8 + gr;
                unsigned b0 = Vt[e0 * 36 + ks * 8 + qd];
                unsigned b1 = Vt[e0 * 36 + ks * 8 + qd + 4];
                mma16816(of[t], a, b0, b1);
            }
        }
    }

    // ---- reduce l: over quad lanes, then over the two key-halves ----
    lp0 += __shfl_xor_sync(0xffffffffu, lp0, 1);
    lp0 += __shfl_xor_sync(0xffffffffu, lp0, 2);
    lp1 += __shfl_xor_sync(0xffffffffu, lp1, 1);
    lp1 += __shfl_xor_sync(0xffffffffu, lp1, 2);
    if (qd == 0) {
        Lsm[w >> 2][mr + gr]     = lp0;
        Lsm[w >> 2][mr + gr + 8] = lp1;
    }
    __syncthreads();

    // ---- write O / l to g_ao[b][n][h*64 + e] ----
    int b = bh / NH, h = bh % NH;
    float invl0 = 1.f / (Lsm[0][mr + gr]     + Lsm[1][mr + gr]);
    float invl1 = 1.f / (Lsm[0][mr + gr + 8] + Lsm[1][mr + gr + 8]);
    int n0 = q0 + mr + gr;
    int n1 = n0 + 8;
    #pragma unroll
    for (int t = 0; t < 4; ++t) {
        int e = nb + t * 8 + qd * 2;
        if (n0 < N_) {
            float* p = g_ao + (size_t)(b * N_ + n0) * C_ + h * DH + e;
            p[0] = of[t][0] * invl0;
            p[1] = of[t][1] * invl0;
        }
        if (n1 < N_) {
            float* p = g_ao + (size_t)(b * N_ + n1) * C_ + h * DH + e;
            p[0] = of[t][2] * invl1;
            p[1] = of[t][3] * invl1;
        }
    }
}

// ---------------------------------------------------------------------------
// Kernel 4: out projection + bias + residual + transpose back to [b][c][n]
// ---------------------------------------------------------------------------
__global__ void proj_kernel(const float* __restrict__ wout,
                            const float* __restrict__ bout,
                            const float* __restrict__ x,
                            float* __restrict__ out) {
    __shared__ float As[16 * 68];
    __shared__ float Bs[16 * 68];
    __shared__ float Ts[64 * 65];
    int m0 = blockIdx.y * 64;
    int c0 = blockIdx.x * 64;
    int tid = threadIdx.x;
    int ty = tid >> 4, tx = tid & 15;
    int arow = tid >> 2;
    int akq  = (tid & 3) * 4;
    float acc[4][4] = {};

    for (int k0 = 0; k0 < C_; k0 += 16) {
        float4 av = make_float4(0.f, 0.f, 0.f, 0.f);
        int m = m0 + arow;
        if (m < M_) av = *(const float4*)(g_ao + (size_t)m * C_ + k0 + akq);
        As[(akq + 0) * 68 + arow] = av.x;
        As[(akq + 1) * 68 + arow] = av.y;
        As[(akq + 2) * 68 + arow] = av.z;
        As[(akq + 3) * 68 + arow] = av.w;
        float4 bv = *(const float4*)(wout + (size_t)(c0 + arow) * C_ + k0 + akq);
        Bs[(akq + 0) * 68 + arow] = bv.x;
        Bs[(akq + 1) * 68 + arow] = bv.y;
        Bs[(akq + 2) * 68 + arow] = bv.z;
        Bs[(akq + 3) * 68 + arow] = bv.w;
        __syncthreads();

        #pragma unroll
        for (int k = 0; k < 16; ++k) {
            float4 a4 = *(const float4*)(As + k * 68 + ty * 4);
            float4 b4 = *(const float4*)(Bs + k * 68 + tx * 4);
            float a[4] = {a4.x, a4.y, a4.z, a4.w};
            float b[4] = {b4.x, b4.y, b4.z, b4.w};
            #pragma unroll
            for (int i = 0; i < 4; ++i)
                #pragma unroll
                for (int j = 0; j < 4; ++j)
                    acc[i][j] = fmaf(a[i], b[j], acc[i][j]);
        }
        __syncthreads();
    }

    #pragma unroll
    for (int i = 0; i < 4; ++i)
        #pragma unroll
        for (int j = 0; j < 4; ++j)
            Ts[(ty * 4 + i) * 65 + tx * 4 + j] = acc[i][j] + bout[c0 + tx * 4 + j];
    __syncthreads();

    for (int t = tid; t < 64 * 64; t += 256) {
        int cl = t >> 6, ml = t & 63;
        int m = m0 + ml;
        if (m < M_) {
            int b = m / N_, n = m % N_;
            size_t gi = (size_t)(b * C_ + c0 + cl) * N_ + n;
            out[gi] = Ts[ml * 65 + cl] + x[gi];
        }
    }
}

// ---------------------------------------------------------------------------
extern "C" void kernel_launch(void* const* d_in, const int* in_sizes, int n_in,
                              void* d_out, int out_size) {
    const float* x      = nullptr;
    const float* norm_w = nullptr;
    const float* norm_b = nullptr;
    const float* qkv_w  = nullptr;
    const float* out_w  = nullptr;
    const float* out_b  = nullptr;
    int small_seen = 0;
    for (int i = 0; i < n_in; ++i) {
        const float* p = (const float*)d_in[i];
        int sz = in_sizes[i];
        if      (sz == B_ * C_ * N_)     x     = p;
        else if (sz == 3 * C_ * C_)      qkv_w = p;
        else if (sz == C_ * C_)          out_w = p;
        else if (sz == C_) {
            if      (small_seen == 0) norm_w = p;
            else if (small_seen == 1) norm_b = p;
            else                      out_b  = p;
            ++small_seen;
        }
    }
    float* out = (float*)d_out;
    (void)out_size;

    ln_kernel<<<B_ * 196, 256>>>(x, norm_w, norm_b);
    qkv_kernel<<<dim3(3 * C_ / 64, (M_ + 63) / 64), 256>>>(qkv_w);
    attn_mma_kernel<<<dim3(B_ * NH, (N_ + 63) / 64), 256>>>();
    proj_kernel<<<dim3(C_ / 64, (M_ + 63) / 64), 256>>>(out_w, out_b, x, out);
}

// round 9
// speedup vs baseline: 31.2168x; 1.8389x over previous
#include <cuda_runtime.h>
#include <cuda_bf16.h>
#include <math.h>

// Problem constants
constexpr int B_  = 2;
constexpr int C_  = 768;
constexpr int N_  = 2744;          // 14^3 tokens
constexpr int NH  = 12;
constexpr int DH  = 64;
constexpr int M_  = B_ * N_;       // 5488 total tokens

// Scratch (device globals; no allocation allowed)
__device__ __nv_bfloat16 g_tn  [M_ * C_];       // layernormed tokens, bf16 [m][c]
__device__ __nv_bfloat16 g_ao  [M_ * C_];       // attention output, bf16 [m][c]
__device__ __nv_bfloat16 g_wqkv[3 * C_ * C_];   // bf16 weights
__device__ __nv_bfloat16 g_wout[C_ * C_];
__device__ float g_q [B_ * NH * N_ * DH];       // [b][h][n][e] fp32
__device__ float g_k [B_ * NH * N_ * DH];
__device__ float g_v [B_ * NH * N_ * DH];

// ---------------------------------------------------------------------------
// Helpers: bf16 packing + warp-level mma
// ---------------------------------------------------------------------------
__device__ __forceinline__ unsigned pack_bf16(float lo, float hi) {
    unsigned r;
    asm("cvt.rn.bf16x2.f32 %0, %1, %2;" : "=r"(r) : "f"(hi), "f"(lo));
    return r;
}

// D(16x8,f32) += A(16x16,bf16,row) * B(16x8,bf16,col)
__device__ __forceinline__ void mma16816(float* d, const unsigned* a,
                                         unsigned b0, unsigned b1) {
    asm volatile(
        "mma.sync.aligned.m16n8k16.row.col.f32.bf16.bf16.f32 "
        "{%0,%1,%2,%3}, {%4,%5,%6,%7}, {%8,%9}, {%0,%1,%2,%3};"
        : "+f"(d[0]), "+f"(d[1]), "+f"(d[2]), "+f"(d[3])
        : "r"(a[0]), "r"(a[1]), "r"(a[2]), "r"(a[3]), "r"(b0), "r"(b1));
}

// ---------------------------------------------------------------------------
// Kernel 0: fp32 -> bf16 weight conversion (2 elems/thread)
// ---------------------------------------------------------------------------
__global__ void cvt_kernel(const float* __restrict__ src,
                           __nv_bfloat16* __restrict__ dst, int n2) {
    int i = blockIdx.x * blockDim.x + threadIdx.x;
    if (i < n2) {
        float2 v = *(const float2*)(src + i * 2);
        *(unsigned*)((unsigned*)dst + i) = pack_bf16(v.x, v.y);
    }
}

// ---------------------------------------------------------------------------
// Kernel 1: transpose b c n -> (b n) c + LayerNorm over c, bf16 output
// ---------------------------------------------------------------------------
__global__ void ln_kernel(const float* __restrict__ x,
                          const float* __restrict__ w,
                          const float* __restrict__ bnorm) {
    __shared__ float tile[14 * 769];
    int b  = blockIdx.x / 196;
    int t0 = (blockIdx.x % 196) * 14;
    const float* xb = x + (size_t)b * C_ * N_;

    for (int idx = threadIdx.x; idx < C_ * 14; idx += 256) {
        int c = idx / 14, t = idx % 14;
        tile[t * 769 + c] = xb[c * N_ + t0 + t];
    }
    __syncthreads();

    int warp = threadIdx.x >> 5, lane = threadIdx.x & 31;
    for (int t = warp; t < 14; t += 8) {
        float s1 = 0.f, s2 = 0.f;
        for (int c = lane; c < C_; c += 32) {
            float v = tile[t * 769 + c];
            s1 += v; s2 += v * v;
        }
        #pragma unroll
        for (int off = 16; off; off >>= 1) {
            s1 += __shfl_xor_sync(0xffffffffu, s1, off);
            s2 += __shfl_xor_sync(0xffffffffu, s2, off);
        }
        float mu  = s1 * (1.f / C_);
        float var = s2 * (1.f / C_) - mu * mu;
        float inv = rsqrtf(var + 1e-5f);
        __nv_bfloat16* out = g_tn + (size_t)(b * N_ + t0 + t) * C_;
        for (int c = lane; c < C_; c += 32)
            out[c] = __float2bfloat16(
                (tile[t * 769 + c] - mu) * inv * w[c] + bnorm[c]);
    }
}

// ---------------------------------------------------------------------------
// Shared 64x64 HMMA GEMM tile: of += A[m0:+64] * B[j0:+64]^T (K-major bf16).
// Identical staging/frag layout to the validated attention kernel.
// ---------------------------------------------------------------------------
__device__ __forceinline__ void gemm_tile_64(
    const __nv_bfloat16* __restrict__ A, int Arows,
    const __nv_bfloat16* __restrict__ Bw,
    int m0, int j0, unsigned* As, unsigned* Bs,
    float of[4][4], int mr, int nb, int gr, int qd)
{
    int row = threadIdx.x >> 2, q4 = threadIdx.x & 3;
    for (int k0 = 0; k0 < C_; k0 += 64) {
        __syncthreads();            // protect prev-iter frag reads
        {   // stage A [row][k] bf16, stride 36 u32
            int m = m0 + row;
            uint4 v0 = make_uint4(0u,0u,0u,0u), v1 = v0;
            if (m < Arows) {
                const uint4* src = (const uint4*)(A + (size_t)m * C_ + k0 + q4 * 16);
                v0 = src[0]; v1 = src[1];
            }
            unsigned* d = As + row * 36 + q4 * 8;
            *(uint4*)(d)     = v0;
            *(uint4*)(d + 4) = v1;
        }
        {   // stage B [row][k]
            const uint4* src = (const uint4*)(Bw + (size_t)(j0 + row) * C_ + k0 + q4 * 16);
            uint4 v0 = src[0], v1 = src[1];
            unsigned* d = Bs + row * 36 + q4 * 8;
            *(uint4*)(d)     = v0;
            *(uint4*)(d + 4) = v1;
        }
        __syncthreads();

        #pragma unroll
        for (int ks = 0; ks < 4; ++ks) {
            int c = ks * 8 + qd;
            unsigned a[4];
            a[0] = As[(mr + gr    ) * 36 + c];
            a[1] = As[(mr + gr + 8) * 36 + c];
            a[2] = As[(mr + gr    ) * 36 + c + 4];
            a[3] = As[(mr + gr + 8) * 36 + c + 4];
            #pragma unroll
            for (int t = 0; t < 4; ++t) {
                int r = nb + t * 8 + gr;
                mma16816(of[t], a, Bs[r * 36 + c], Bs[r * 36 + c + 4]);
            }
        }
    }
}

// ---------------------------------------------------------------------------
// Kernel 2: QKV GEMM (HMMA). out[m][j] = sum_k tn[m][k] * Wqkv[j][k],
// scattered fp32 to g_q/g_k/g_v in [b][h][n][e] layout.
// ---------------------------------------------------------------------------
__global__ void __launch_bounds__(256) qkv_mma_kernel() {
    __shared__ unsigned As[64 * 36];
    __shared__ unsigned Bs[64 * 36];
    int m0 = blockIdx.y * 64;
    int j0 = blockIdx.x * 64;
    int w = threadIdx.x >> 5, lane = threadIdx.x & 31;
    int mr = (w & 3) * 16, nb = (w >> 2) * 32;
    int gr = lane >> 2,    qd = lane & 3;

    float of[4][4] = {};
    gemm_tile_64(g_tn, M_, g_wqkv, m0, j0, As, Bs, of, mr, nb, gr, qd);

    int s = j0 / C_;
    int h = (j0 % C_) / DH;
    float* outp = (s == 0) ? g_q : ((s == 1) ? g_k : g_v);
    int ma = m0 + mr + gr, mb = ma + 8;
    #pragma unroll
    for (int t = 0; t < 4; ++t) {
        int e = nb + t * 8 + qd * 2;
        if (ma < M_) {
            int b = ma / N_, n = ma % N_;
            *(float2*)(outp + (size_t)((b * NH + h) * N_ + n) * DH + e) =
                make_float2(of[t][0], of[t][1]);
        }
        if (mb < M_) {
            int b = mb / N_, n = mb % N_;
            *(float2*)(outp + (size_t)((b * NH + h) * N_ + n) * DH + e) =
                make_float2(of[t][2], of[t][3]);
        }
    }
}

// ---------------------------------------------------------------------------
// Kernel 3: tensor-core attention (validated round-8 machinery); output bf16.
// ---------------------------------------------------------------------------
__global__ void __launch_bounds__(256) attn_mma_kernel() {
    __shared__ unsigned Qs[64 * 36];
    __shared__ unsigned Ks[64 * 36];
    __shared__ unsigned Vt[64 * 36];
    __shared__ unsigned Ps[64 * 36];
    __shared__ float    Lsm[2][64];

    int bh = blockIdx.x;
    int q0 = blockIdx.y * 64;
    const float* qb = g_q + (size_t)bh * N_ * DH;
    const float* kb = g_k + (size_t)bh * N_ * DH;
    const float* vb = g_v + (size_t)bh * N_ * DH;

    int tid  = threadIdx.x;
    int w    = tid >> 5, lane = tid & 31;
    int mr   = (w & 3) * 16;
    int nb   = (w >> 2) * 32;
    int gr   = lane >> 2;
    int qd   = lane & 3;

    {   // stage Q tile bf16 [q][e]
        int row = tid >> 2, q4 = tid & 3;
        int n = q0 + row;
        unsigned* dst = Qs + row * 36 + q4 * 8;
        if (n < N_) {
            const float4* src = (const float4*)(qb + (size_t)n * DH + q4 * 16);
            #pragma unroll
            for (int r = 0; r < 4; ++r) {
                float4 v = src[r];
                dst[r * 2 + 0] = pack_bf16(v.x, v.y);
                dst[r * 2 + 1] = pack_bf16(v.z, v.w);
            }
        } else {
            #pragma unroll
            for (int r = 0; r < 8; ++r) dst[r] = 0u;
        }
    }
    __syncthreads();

    unsigned qa[4][4];
    #pragma unroll
    for (int ks = 0; ks < 4; ++ks) {
        int c = ks * 8 + qd;
        qa[ks][0] = Qs[(mr + gr    ) * 36 + c];
        qa[ks][1] = Qs[(mr + gr + 8) * 36 + c];
        qa[ks][2] = Qs[(mr + gr    ) * 36 + c + 4];
        qa[ks][3] = Qs[(mr + gr + 8) * 36 + c + 4];
    }

    float of[4][4] = {};
    float lp0 = 0.f, lp1 = 0.f;

    for (int kb0 = 0; kb0 < N_; kb0 += 64) {
        __syncthreads();
        {   // stage K [kk][e] and Vt [e][kk]
            int row = tid >> 2, q4 = tid & 3;
            int n = kb0 + row;
            bool ok = (n < N_);
            unsigned* kd = Ks + row * 36 + q4 * 8;
            __nv_bfloat16* vt16 = reinterpret_cast<__nv_bfloat16*>(Vt);
            const float4* ksrc = (const float4*)(kb + (size_t)n * DH + q4 * 16);
            const float4* vsrc = (const float4*)(vb + (size_t)n * DH + q4 * 16);
            #pragma unroll
            for (int r = 0; r < 4; ++r) {
                float4 kv = make_float4(0.f, 0.f, 0.f, 0.f);
                float4 vv = kv;
                if (ok) { kv = ksrc[r]; vv = vsrc[r]; }
                kd[r * 2 + 0] = pack_bf16(kv.x, kv.y);
                kd[r * 2 + 1] = pack_bf16(kv.z, kv.w);
                int e = q4 * 16 + r * 4;
                vt16[(e + 0) * 72 + row] = __float2bfloat16(vv.x);
                vt16[(e + 1) * 72 + row] = __float2bfloat16(vv.y);
                vt16[(e + 2) * 72 + row] = __float2bfloat16(vv.z);
                vt16[(e + 3) * 72 + row] = __float2bfloat16(vv.w);
            }
        }
        __syncthreads();

        float sf[4][4] = {};
        #pragma unroll
        for (int ks = 0; ks < 4; ++ks) {
            #pragma unroll
            for (int t = 0; t < 4; ++t) {
                int n0 = nb + t * 8 + gr;
                mma16816(sf[t], qa[ks],
                         Ks[n0 * 36 + ks * 8 + qd],
                         Ks[n0 * 36 + ks * 8 + qd + 4]);
            }
        }

        #pragma unroll
        for (int t = 0; t < 4; ++t) {
            int kcol = nb + t * 8 + qd * 2;
            int gk = kb0 + kcol;
            bool v0 = gk < N_, v1 = (gk + 1) < N_;
            float p0 = v0 ? __expf(sf[t][0] * 0.125f) : 0.f;
            float p1 = v1 ? __expf(sf[t][1] * 0.125f) : 0.f;
            float p2 = v0 ? __expf(sf[t][2] * 0.125f) : 0.f;
            float p3 = v1 ? __expf(sf[t][3] * 0.125f) : 0.f;
            lp0 += p0 + p1;
            lp1 += p2 + p3;
            Ps[(mr + gr    ) * 36 + (kcol >> 1)] = pack_bf16(p0, p1);
            Ps[(mr + gr + 8) * 36 + (kcol >> 1)] = pack_bf16(p2, p3);
        }
        __syncthreads();

        #pragma unroll
        for (int ks = 0; ks < 4; ++ks) {
            int c = ks * 8 + qd;
            unsigned a[4];
            a[0] = Ps[(mr + gr    ) * 36 + c];
            a[1] = Ps[(mr + gr + 8) * 36 + c];
            a[2] = Ps[(mr + gr    ) * 36 + c + 4];
            a[3] = Ps[(mr + gr + 8) * 36 + c + 4];
            #pragma unroll
            for (int t = 0; t < 4; ++t) {
                int e0 = nb + t * 8 + gr;
                mma16816(of[t], a,
                         Vt[e0 * 36 + ks * 8 + qd],
                         Vt[e0 * 36 + ks * 8 + qd + 4]);
            }
        }
    }

    lp0 += __shfl_xor_sync(0xffffffffu, lp0, 1);
    lp0 += __shfl_xor_sync(0xffffffffu, lp0, 2);
    lp1 += __shfl_xor_sync(0xffffffffu, lp1, 1);
    lp1 += __shfl_xor_sync(0xffffffffu, lp1, 2);
    if (qd == 0) {
        Lsm[w >> 2][mr + gr]     = lp0;
        Lsm[w >> 2][mr + gr + 8] = lp1;
    }
    __syncthreads();

    int b = bh / NH, h = bh % NH;
    float invl0 = 1.f / (Lsm[0][mr + gr]     + Lsm[1][mr + gr]);
    float invl1 = 1.f / (Lsm[0][mr + gr + 8] + Lsm[1][mr + gr + 8]);
    int n0 = q0 + mr + gr;
    int n1 = n0 + 8;
    unsigned* ao32 = reinterpret_cast<unsigned*>(g_ao);
    #pragma unroll
    for (int t = 0; t < 4; ++t) {
        int e = nb + t * 8 + qd * 2;
        if (n0 < N_)
            ao32[((size_t)(b * N_ + n0) * C_ + h * DH + e) >> 1] =
                pack_bf16(of[t][0] * invl0, of[t][1] * invl0);
        if (n1 < N_)
            ao32[((size_t)(b * N_ + n1) * C_ + h * DH + e) >> 1] =
                pack_bf16(of[t][2] * invl1, of[t][3] * invl1);
    }
}

// ---------------------------------------------------------------------------
// Kernel 4: out projection (HMMA) + bias + residual + transpose to [b][c][n]
// ---------------------------------------------------------------------------
__global__ void __launch_bounds__(256) proj_mma_kernel(
        const float* __restrict__ bout,
        const float* __restrict__ x,
        float* __restrict__ out) {
    __shared__ unsigned As[64 * 36];
    __shared__ unsigned Bs[64 * 36];
    __shared__ float    Ts[64 * 65];    // [token_local][c_local]
    int m0 = blockIdx.y * 64;
    int c0 = blockIdx.x * 64;
    int w = threadIdx.x >> 5, lane = threadIdx.x & 31;
    int mr = (w & 3) * 16, nb = (w >> 2) * 32;
    int gr = lane >> 2,    qd = lane & 3;

    float of[4][4] = {};
    gemm_tile_64(g_ao, M_, g_wout, m0, c0, As, Bs, of, mr, nb, gr, qd);

    #pragma unroll
    for (int t = 0; t < 4; ++t) {
        int cl = nb + t * 8 + qd * 2;
        float b0 = bout[c0 + cl], b1 = bout[c0 + cl + 1];
        Ts[(mr + gr    ) * 65 + cl]     = of[t][0] + b0;
        Ts[(mr + gr    ) * 65 + cl + 1] = of[t][1] + b1;
        Ts[(mr + gr + 8) * 65 + cl]     = of[t][2] + b0;
        Ts[(mr + gr + 8) * 65 + cl + 1] = of[t][3] + b1;
    }
    __syncthreads();

    for (int t = threadIdx.x; t < 64 * 64; t += 256) {
        int cl = t >> 6, ml = t & 63;
        int m = m0 + ml;
        if (m < M_) {
            int b = m / N_, n = m % N_;
            size_t gi = (size_t)(b * C_ + c0 + cl) * N_ + n;
            out[gi] = Ts[ml * 65 + cl] + x[gi];
        }
    }
}

// ---------------------------------------------------------------------------
extern "C" void kernel_launch(void* const* d_in, const int* in_sizes, int n_in,
                              void* d_out, int out_size) {
    const float* x      = nullptr;
    const float* norm_w = nullptr;
    const float* norm_b = nullptr;
    const float* qkv_w  = nullptr;
    const float* out_w  = nullptr;
    const float* out_b  = nullptr;
    int small_seen = 0;
    for (int i = 0; i < n_in; ++i) {
        const float* p = (const float*)d_in[i];
        int sz = in_sizes[i];
        if      (sz == B_ * C_ * N_)     x     = p;
        else if (sz == 3 * C_ * C_)      qkv_w = p;
        else if (sz == C_ * C_)          out_w = p;
        else if (sz == C_) {
            if      (small_seen == 0) norm_w = p;
            else if (small_seen == 1) norm_b = p;
            else                      out_b  = p;
            ++small_seen;
        }
    }
    float* out = (float*)d_out;
    (void)out_size;

    __nv_bfloat16* wqkv_bf = nullptr;
    __nv_bfloat16* wout_bf = nullptr;
    cudaGetSymbolAddress((void**)&wqkv_bf, g_wqkv);
    cudaGetSymbolAddress((void**)&wout_bf, g_wout);

    cvt_kernel<<<(3 * C_ * C_ / 2 + 255) / 256, 256>>>(qkv_w, wqkv_bf, 3 * C_ * C_ / 2);
    cvt_kernel<<<(C_ * C_ / 2 + 255) / 256, 256>>>(out_w, wout_bf, C_ * C_ / 2);
    ln_kernel<<<B_ * 196, 256>>>(x, norm_w, norm_b);
    qkv_mma_kernel<<<dim3(3 * C_ / 64, (M_ + 63) / 64), 256>>>();
    attn_mma_kernel<<<dim3(B_ * NH, (N_ + 63) / 64), 256>>>();
    proj_mma_kernel<<<dim3(C_ / 64, (M_ + 63) / 64), 256>>>(out_b, x, out);
}

// round 10
// speedup vs baseline: 43.0693x; 1.3797x over previous
#include <cuda_runtime.h>
#include <cuda_bf16.h>
#include <math.h>

// Problem constants
constexpr int B_  = 2;
constexpr int C_  = 768;
constexpr int N_  = 2744;          // 14^3 tokens
constexpr int NH  = 12;
constexpr int DH  = 64;
constexpr int M_  = B_ * N_;       // 5488 total tokens

// Scratch (device globals; no allocation allowed)
__device__ __nv_bfloat16 g_tn  [M_ * C_];       // layernormed tokens, bf16 [m][c]
__device__ __nv_bfloat16 g_ao  [M_ * C_];       // attention output, bf16 [m][c]
__device__ __nv_bfloat16 g_wqkv[3 * C_ * C_];   // bf16 weights
__device__ __nv_bfloat16 g_wout[C_ * C_];
__device__ __nv_bfloat16 g_q [B_ * NH * N_ * DH];  // [b][h][n][e] bf16
__device__ __nv_bfloat16 g_k [B_ * NH * N_ * DH];
__device__ __nv_bfloat16 g_v [B_ * NH * N_ * DH];

// ---------------------------------------------------------------------------
// Helpers
// ---------------------------------------------------------------------------
__device__ __forceinline__ unsigned pack_bf16(float lo, float hi) {
    unsigned r;
    asm("cvt.rn.bf16x2.f32 %0, %1, %2;" : "=r"(r) : "f"(hi), "f"(lo));
    return r;
}

// D(16x8,f32) += A(16x16,bf16,row) * B(16x8,bf16,col)
__device__ __forceinline__ void mma16816(float* d, const unsigned* a,
                                         unsigned b0, unsigned b1) {
    asm volatile(
        "mma.sync.aligned.m16n8k16.row.col.f32.bf16.bf16.f32 "
        "{%0,%1,%2,%3}, {%4,%5,%6,%7}, {%8,%9}, {%0,%1,%2,%3};"
        : "+f"(d[0]), "+f"(d[1]), "+f"(d[2]), "+f"(d[3])
        : "r"(a[0]), "r"(a[1]), "r"(a[2]), "r"(a[3]), "r"(b0), "r"(b1));
}

__device__ __forceinline__ void ldsm_x4(unsigned* r, unsigned addr) {
    asm volatile("ldmatrix.sync.aligned.m8n8.x4.shared.b16 {%0,%1,%2,%3}, [%4];"
                 : "=r"(r[0]), "=r"(r[1]), "=r"(r[2]), "=r"(r[3]) : "r"(addr));
}
__device__ __forceinline__ void ldsm_x4_t(unsigned* r, unsigned addr) {
    asm volatile("ldmatrix.sync.aligned.m8n8.x4.trans.shared.b16 {%0,%1,%2,%3}, [%4];"
                 : "=r"(r[0]), "=r"(r[1]), "=r"(r[2]), "=r"(r[3]) : "r"(addr));
}

// Lane address for a 16x16 bf16 block at (row0, halfcol0); row stride 144B.
// mats: {(r0..r0+7,c0), (r0+8..+15,c0), (r0..r0+7,c0+8), (r0+8..+15,c0+8)}
__device__ __forceinline__ unsigned frag_addr(unsigned base, int row0,
                                              int halfcol0, int lane) {
    int lrow = lane & 7, lm = lane >> 3;
    return base + (unsigned)((row0 + (lm & 1) * 8 + lrow) * 144 +
                             halfcol0 * 2 + (lm >> 1) * 16);
}

// ---------------------------------------------------------------------------
// Kernel 0: fp32 -> bf16 weight conversion
// ---------------------------------------------------------------------------
__global__ void cvt_kernel(const float* __restrict__ src,
                           __nv_bfloat16* __restrict__ dst, int n2) {
    int i = blockIdx.x * blockDim.x + threadIdx.x;
    if (i < n2) {
        float2 v = *(const float2*)(src + i * 2);
        *(unsigned*)((unsigned*)dst + i) = pack_bf16(v.x, v.y);
    }
}

// ---------------------------------------------------------------------------
// Kernel 1: transpose b c n -> (b n) c + LayerNorm over c, bf16 output
// ---------------------------------------------------------------------------
__global__ void ln_kernel(const float* __restrict__ x,
                          const float* __restrict__ w,
                          const float* __restrict__ bnorm) {
    __shared__ float tile[14 * 769];
    int b  = blockIdx.x / 196;
    int t0 = (blockIdx.x % 196) * 14;
    const float* xb = x + (size_t)b * C_ * N_;

    for (int idx = threadIdx.x; idx < C_ * 14; idx += 256) {
        int c = idx / 14, t = idx % 14;
        tile[t * 769 + c] = xb[c * N_ + t0 + t];
    }
    __syncthreads();

    int warp = threadIdx.x >> 5, lane = threadIdx.x & 31;
    for (int t = warp; t < 14; t += 8) {
        float s1 = 0.f, s2 = 0.f;
        for (int c = lane; c < C_; c += 32) {
            float v = tile[t * 769 + c];
            s1 += v; s2 += v * v;
        }
        #pragma unroll
        for (int off = 16; off; off >>= 1) {
            s1 += __shfl_xor_sync(0xffffffffu, s1, off);
            s2 += __shfl_xor_sync(0xffffffffu, s2, off);
        }
        float mu  = s1 * (1.f / C_);
        float var = s2 * (1.f / C_) - mu * mu;
        float inv = rsqrtf(var + 1e-5f);
        __nv_bfloat16* out = g_tn + (size_t)(b * N_ + t0 + t) * C_;
        for (int c = lane; c < C_; c += 32)
            out[c] = __float2bfloat16(
                (tile[t * 769 + c] - mu) * inv * w[c] + bnorm[c]);
    }
}

// ---------------------------------------------------------------------------
// Shared 64x64 HMMA GEMM tile with ldmatrix frag loads.
// ---------------------------------------------------------------------------
__device__ __forceinline__ void gemm_tile_64(
    const __nv_bfloat16* __restrict__ A, int Arows,
    const __nv_bfloat16* __restrict__ Bw,
    int m0, int j0, unsigned* As, unsigned* Bs,
    float of[4][4], int mr, int nb, int lane)
{
    unsigned asb = (unsigned)__cvta_generic_to_shared(As);
    unsigned bsb = (unsigned)__cvta_generic_to_shared(Bs);
    int row = threadIdx.x >> 2, q4 = threadIdx.x & 3;
    for (int k0 = 0; k0 < C_; k0 += 64) {
        __syncthreads();            // protect prev-iter frag reads
        {   // stage A row (64 bf16 = 4 threads x 16 halves)
            int m = m0 + row;
            uint4 v0 = make_uint4(0u,0u,0u,0u), v1 = v0;
            if (m < Arows) {
                const uint4* src = (const uint4*)(A + (size_t)m * C_ + k0 + q4 * 16);
                v0 = src[0]; v1 = src[1];
            }
            unsigned* d = As + row * 36 + q4 * 8;
            *(uint4*)(d)     = v0;
            *(uint4*)(d + 4) = v1;
        }
        {   // stage B row
            const uint4* src = (const uint4*)(Bw + (size_t)(j0 + row) * C_ + k0 + q4 * 16);
            uint4 v0 = src[0], v1 = src[1];
            unsigned* d = Bs + row * 36 + q4 * 8;
            *(uint4*)(d)     = v0;
            *(uint4*)(d + 4) = v1;
        }
        __syncthreads();

        #pragma unroll
        for (int ks = 0; ks < 4; ++ks) {
            unsigned a[4], b0[4], b1[4];
            ldsm_x4(a,  frag_addr(asb, mr,      ks * 16, lane));
            ldsm_x4(b0, frag_addr(bsb, nb,      ks * 16, lane));
            ldsm_x4(b1, frag_addr(bsb, nb + 16, ks * 16, lane));
            // b0 = {b0_t0, b0_t1, b1_t0, b1_t1}
            mma16816(of[0], a, b0[0], b0[2]);
            mma16816(of[1], a, b0[1], b0[3]);
            mma16816(of[2], a, b1[0], b1[2]);
            mma16816(of[3], a, b1[1], b1[3]);
        }
    }
}

// ---------------------------------------------------------------------------
// Kernel 2: QKV GEMM (HMMA+ldmatrix); bf16 output scattered to g_q/g_k/g_v.
// ---------------------------------------------------------------------------
__global__ void __launch_bounds__(256) qkv_mma_kernel() {
    __shared__ unsigned As[64 * 36];
    __shared__ unsigned Bs[64 * 36];
    int m0 = blockIdx.y * 64;
    int j0 = blockIdx.x * 64;
    int w = threadIdx.x >> 5, lane = threadIdx.x & 31;
    int mr = (w & 3) * 16, nb = (w >> 2) * 32;
    int gr = lane >> 2,    qd = lane & 3;

    float of[4][4] = {};
    gemm_tile_64(g_tn, M_, g_wqkv, m0, j0, As, Bs, of, mr, nb, lane);

    int s = j0 / C_;
    int h = (j0 % C_) / DH;
    __nv_bfloat16* outp = (s == 0) ? g_q : ((s == 1) ? g_k : g_v);
    unsigned* o32 = (unsigned*)outp;
    int ma = m0 + mr + gr, mb = ma + 8;
    #pragma unroll
    for (int t = 0; t < 4; ++t) {
        int e = nb + t * 8 + qd * 2;
        if (ma < M_) {
            int b = ma / N_, n = ma % N_;
            o32[((size_t)((b * NH + h) * N_ + n) * DH + e) >> 1] =
                pack_bf16(of[t][0], of[t][1]);
        }
        if (mb < M_) {
            int b = mb / N_, n = mb % N_;
            o32[((size_t)((b * NH + h) * N_ + n) * DH + e) >> 1] =
                pack_bf16(of[t][2], of[t][3]);
        }
    }
}

// ---------------------------------------------------------------------------
// Kernel 3: tensor-core attention; bf16 q/k/v in, ldmatrix frag loads,
// trans-ldmatrix V (no scalar-STS transpose). Output bf16 g_ao.
// ---------------------------------------------------------------------------
__global__ void __launch_bounds__(256) attn_mma_kernel() {
    __shared__ unsigned Qs[64 * 36];
    __shared__ unsigned Ks[64 * 36];
    __shared__ unsigned Vs[64 * 36];     // [kk][e], row-major like Ks
    __shared__ unsigned Ps[64 * 36];
    __shared__ float    Lsm[2][64];

    int bh = blockIdx.x;
    int q0 = blockIdx.y * 64;
    const __nv_bfloat16* qb = g_q + (size_t)bh * N_ * DH;
    const __nv_bfloat16* kb = g_k + (size_t)bh * N_ * DH;
    const __nv_bfloat16* vb = g_v + (size_t)bh * N_ * DH;

    unsigned qsb = (unsigned)__cvta_generic_to_shared(Qs);
    unsigned ksb = (unsigned)__cvta_generic_to_shared(Ks);
    unsigned vsb = (unsigned)__cvta_generic_to_shared(Vs);
    unsigned psb = (unsigned)__cvta_generic_to_shared(Ps);

    int tid  = threadIdx.x;
    int w    = tid >> 5, lane = tid & 31;
    int mr   = (w & 3) * 16;
    int nb   = (w >> 2) * 32;
    int gr   = lane >> 2;
    int qd   = lane & 3;
    int row  = tid >> 2, q4 = tid & 3;

    {   // stage Q tile (row copy)
        int n = q0 + row;
        uint4 v0 = make_uint4(0u,0u,0u,0u), v1 = v0;
        if (n < N_) {
            const uint4* src = (const uint4*)(qb + (size_t)n * DH + q4 * 16);
            v0 = src[0]; v1 = src[1];
        }
        unsigned* d = Qs + row * 36 + q4 * 8;
        *(uint4*)(d)     = v0;
        *(uint4*)(d + 4) = v1;
    }
    __syncthreads();

    unsigned qa[4][4];
    #pragma unroll
    for (int ks = 0; ks < 4; ++ks)
        ldsm_x4(qa[ks], frag_addr(qsb, mr, ks * 16, lane));

    float of[4][4] = {};
    float lp0 = 0.f, lp1 = 0.f;

    for (int kb0 = 0; kb0 < N_; kb0 += 64) {
        __syncthreads();
        {   // stage K and V rows
            int n = kb0 + row;
            uint4 k0v = make_uint4(0u,0u,0u,0u), k1v = k0v, v0v = k0v, v1v = k0v;
            if (n < N_) {
                const uint4* ksrc = (const uint4*)(kb + (size_t)n * DH + q4 * 16);
                const uint4* vsrc = (const uint4*)(vb + (size_t)n * DH + q4 * 16);
                k0v = ksrc[0]; k1v = ksrc[1];
                v0v = vsrc[0]; v1v = vsrc[1];
            }
            unsigned* kd = Ks + row * 36 + q4 * 8;
            unsigned* vd = Vs + row * 36 + q4 * 8;
            *(uint4*)(kd)     = k0v;
            *(uint4*)(kd + 4) = k1v;
            *(uint4*)(vd)     = v0v;
            *(uint4*)(vd + 4) = v1v;
        }
        __syncthreads();

        // ---- S = Q K^T ----
        float sf[4][4] = {};
        #pragma unroll
        for (int ks = 0; ks < 4; ++ks) {
            unsigned b0[4], b1[4];
            ldsm_x4(b0, frag_addr(ksb, nb,      ks * 16, lane));
            ldsm_x4(b1, frag_addr(ksb, nb + 16, ks * 16, lane));
            mma16816(sf[0], qa[ks], b0[0], b0[2]);
            mma16816(sf[1], qa[ks], b0[1], b0[3]);
            mma16816(sf[2], qa[ks], b1[0], b1[2]);
            mma16816(sf[3], qa[ks], b1[1], b1[3]);
        }

        // ---- p = exp(scale*s), mask, accumulate l, store Ps bf16 ----
        #pragma unroll
        for (int t = 0; t < 4; ++t) {
            int kcol = nb + t * 8 + qd * 2;
            int gk = kb0 + kcol;
            bool v0 = gk < N_, v1 = (gk + 1) < N_;
            float p0 = v0 ? __expf(sf[t][0] * 0.125f) : 0.f;
            float p1 = v1 ? __expf(sf[t][1] * 0.125f) : 0.f;
            float p2 = v0 ? __expf(sf[t][2] * 0.125f) : 0.f;
            float p3 = v1 ? __expf(sf[t][3] * 0.125f) : 0.f;
            lp0 += p0 + p1;
            lp1 += p2 + p3;
            Ps[(mr + gr    ) * 36 + (kcol >> 1)] = pack_bf16(p0, p1);
            Ps[(mr + gr + 8) * 36 + (kcol >> 1)] = pack_bf16(p2, p3);
        }
        __syncthreads();

        // ---- O += P V (a from Ps; b via trans-ldmatrix from Vs[kk][e]) ----
        #pragma unroll
        for (int ks = 0; ks < 4; ++ks) {
            unsigned a[4], v0[4], v1[4];
            ldsm_x4(a, frag_addr(psb, mr, ks * 16, lane));
            ldsm_x4_t(v0, frag_addr(vsb, ks * 16, nb,      lane));
            ldsm_x4_t(v1, frag_addr(vsb, ks * 16, nb + 16, lane));
            // v0 = {b0_t0, b1_t0, b0_t1, b1_t1}
            mma16816(of[0], a, v0[0], v0[1]);
            mma16816(of[1], a, v0[2], v0[3]);
            mma16816(of[2], a, v1[0], v1[1]);
            mma16816(of[3], a, v1[2], v1[3]);
        }
    }

    lp0 += __shfl_xor_sync(0xffffffffu, lp0, 1);
    lp0 += __shfl_xor_sync(0xffffffffu, lp0, 2);
    lp1 += __shfl_xor_sync(0xffffffffu, lp1, 1);
    lp1 += __shfl_xor_sync(0xffffffffu, lp1, 2);
    if (qd == 0) {
        Lsm[w >> 2][mr + gr]     = lp0;
        Lsm[w >> 2][mr + gr + 8] = lp1;
    }
    __syncthreads();

    int b = bh / NH, h = bh % NH;
    float invl0 = 1.f / (Lsm[0][mr + gr]     + Lsm[1][mr + gr]);
    float invl1 = 1.f / (Lsm[0][mr + gr + 8] + Lsm[1][mr + gr + 8]);
    int n0 = q0 + mr + gr;
    int n1 = n0 + 8;
    unsigned* ao32 = reinterpret_cast<unsigned*>(g_ao);
    #pragma unroll
    for (int t = 0; t < 4; ++t) {
        int e = nb + t * 8 + qd * 2;
        if (n0 < N_)
            ao32[((size_t)(b * N_ + n0) * C_ + h * DH + e) >> 1] =
                pack_bf16(of[t][0] * invl0, of[t][1] * invl0);
        if (n1 < N_)
            ao32[((size_t)(b * N_ + n1) * C_ + h * DH + e) >> 1] =
                pack_bf16(of[t][2] * invl1, of[t][3] * invl1);
    }
}

// ---------------------------------------------------------------------------
// Kernel 4: out projection (HMMA+ldmatrix) + bias + residual + transpose
// ---------------------------------------------------------------------------
__global__ void __launch_bounds__(256) proj_mma_kernel(
        const float* __restrict__ bout,
        const float* __restrict__ x,
        float* __restrict__ out) {
    __shared__ unsigned As[64 * 36];
    __shared__ unsigned Bs[64 * 36];
    __shared__ float    Ts[64 * 65];
    int m0 = blockIdx.y * 64;
    int c0 = blockIdx.x * 64;
    int w = threadIdx.x >> 5, lane = threadIdx.x & 31;
    int mr = (w & 3) * 16, nb = (w >> 2) * 32;
    int gr = lane >> 2,    qd = lane & 3;

    float of[4][4] = {};
    gemm_tile_64(g_ao, M_, g_wout, m0, c0, As, Bs, of, mr, nb, lane);

    #pragma unroll
    for (int t = 0; t < 4; ++t) {
        int cl = nb + t * 8 + qd * 2;
        float b0 = bout[c0 + cl], b1 = bout[c0 + cl + 1];
        Ts[(mr + gr    ) * 65 + cl]     = of[t][0] + b0;
        Ts[(mr + gr    ) * 65 + cl + 1] = of[t][1] + b1;
        Ts[(mr + gr + 8) * 65 + cl]     = of[t][2] + b0;
        Ts[(mr + gr + 8) * 65 + cl + 1] = of[t][3] + b1;
    }
    __syncthreads();

    for (int t = threadIdx.x; t < 64 * 64; t += 256) {
        int cl = t >> 6, ml = t & 63;
        int m = m0 + ml;
        if (m < M_) {
            int b = m / N_, n = m % N_;
            size_t gi = (size_t)(b * C_ + c0 + cl) * N_ + n;
            out[gi] = Ts[ml * 65 + cl] + x[gi];
        }
    }
}

// ---------------------------------------------------------------------------
extern "C" void kernel_launch(void* const* d_in, const int* in_sizes, int n_in,
                              void* d_out, int out_size) {
    const float* x      = nullptr;
    const float* norm_w = nullptr;
    const float* norm_b = nullptr;
    const float* qkv_w  = nullptr;
    const float* out_w  = nullptr;
    const float* out_b  = nullptr;
    int small_seen = 0;
    for (int i = 0; i < n_in; ++i) {
        const float* p = (const float*)d_in[i];
        int sz = in_sizes[i];
        if      (sz == B_ * C_ * N_)     x     = p;
        else if (sz == 3 * C_ * C_)      qkv_w = p;
        else if (sz == C_ * C_)          out_w = p;
        else if (sz == C_) {
            if      (small_seen == 0) norm_w = p;
            else if (small_seen == 1) norm_b = p;
            else                      out_b  = p;
            ++small_seen;
        }
    }
    float* out = (float*)d_out;
    (void)out_size;

    __nv_bfloat16* wqkv_bf = nullptr;
    __nv_bfloat16* wout_bf = nullptr;
    cudaGetSymbolAddress((void**)&wqkv_bf, g_wqkv);
    cudaGetSymbolAddress((void**)&wout_bf, g_wout);

    cvt_kernel<<<(3 * C_ * C_ / 2 + 255) / 256, 256>>>(qkv_w, wqkv_bf, 3 * C_ * C_ / 2);
    cvt_kernel<<<(C_ * C_ / 2 + 255) / 256, 256>>>(out_w, wout_bf, C_ * C_ / 2);
    ln_kernel<<<B_ * 196, 256>>>(x, norm_w, norm_b);
    qkv_mma_kernel<<<dim3(3 * C_ / 64, (M_ + 63) / 64), 256>>>();
    attn_mma_kernel<<<dim3(B_ * NH, (N_ + 63) / 64), 256>>>();
    proj_mma_kernel<<<dim3(C_ / 64, (M_ + 63) / 64), 256>>>(out_b, x, out);
}

// round 11
// speedup vs baseline: 50.4198x; 1.1707x over previous
#include <cuda_runtime.h>
#include <cuda_bf16.h>
#include <math.h>

// Problem constants
constexpr int B_  = 2;
constexpr int C_  = 768;
constexpr int N_  = 2744;          // 14^3 tokens
constexpr int NH  = 12;
constexpr int DH  = 64;
constexpr int M_  = B_ * N_;       // 5488 total tokens

// Scratch (device globals; no allocation allowed)
__device__ __nv_bfloat16 g_tn  [M_ * C_];       // layernormed tokens, bf16 [m][c]
__device__ __nv_bfloat16 g_ao  [M_ * C_];       // attention output, bf16 [m][c]
__device__ __nv_bfloat16 g_wqkv[3 * C_ * C_];   // bf16 weights
__device__ __nv_bfloat16 g_wout[C_ * C_];
__device__ __nv_bfloat16 g_q [B_ * NH * N_ * DH];  // [b][h][n][e] bf16
__device__ __nv_bfloat16 g_k [B_ * NH * N_ * DH];
__device__ __nv_bfloat16 g_v [B_ * NH * N_ * DH];

// ---------------------------------------------------------------------------
// Helpers
// ---------------------------------------------------------------------------
__device__ __forceinline__ unsigned pack_bf16(float lo, float hi) {
    unsigned r;
    asm("cvt.rn.bf16x2.f32 %0, %1, %2;" : "=r"(r) : "f"(hi), "f"(lo));
    return r;
}

// D(16x8,f32) += A(16x16,bf16,row) * B(16x8,bf16,col)
__device__ __forceinline__ void mma16816(float* d, const unsigned* a,
                                         unsigned b0, unsigned b1) {
    asm volatile(
        "mma.sync.aligned.m16n8k16.row.col.f32.bf16.bf16.f32 "
        "{%0,%1,%2,%3}, {%4,%5,%6,%7}, {%8,%9}, {%0,%1,%2,%3};"
        : "+f"(d[0]), "+f"(d[1]), "+f"(d[2]), "+f"(d[3])
        : "r"(a[0]), "r"(a[1]), "r"(a[2]), "r"(a[3]), "r"(b0), "r"(b1));
}

__device__ __forceinline__ void ldsm_x4(unsigned* r, unsigned addr) {
    asm volatile("ldmatrix.sync.aligned.m8n8.x4.shared.b16 {%0,%1,%2,%3}, [%4];"
                 : "=r"(r[0]), "=r"(r[1]), "=r"(r[2]), "=r"(r[3]) : "r"(addr));
}
__device__ __forceinline__ void ldsm_x4_t(unsigned* r, unsigned addr) {
    asm volatile("ldmatrix.sync.aligned.m8n8.x4.trans.shared.b16 {%0,%1,%2,%3}, [%4];"
                 : "=r"(r[0]), "=r"(r[1]), "=r"(r[2]), "=r"(r[3]) : "r"(addr));
}

// Lane address for a 16x16 bf16 block at (row0, halfcol0); row stride 144B.
// mats: {(r0..r0+7,c0), (r0+8..+15,c0), (r0..r0+7,c0+8), (r0+8..+15,c0+8)}
__device__ __forceinline__ unsigned frag_addr(unsigned base, int row0,
                                              int halfcol0, int lane) {
    int lrow = lane & 7, lm = lane >> 3;
    return base + (unsigned)((row0 + (lm & 1) * 8 + lrow) * 144 +
                             halfcol0 * 2 + (lm >> 1) * 16);
}

// ---------------------------------------------------------------------------
// Kernel 0: fp32 -> bf16 weight conversion
// ---------------------------------------------------------------------------
__global__ void cvt_kernel(const float* __restrict__ src,
                           __nv_bfloat16* __restrict__ dst, int n2) {
    int i = blockIdx.x * blockDim.x + threadIdx.x;
    if (i < n2) {
        float2 v = *(const float2*)(src + i * 2);
        *(unsigned*)((unsigned*)dst + i) = pack_bf16(v.x, v.y);
    }
}

// ---------------------------------------------------------------------------
// Kernel 1: transpose b c n -> (b n) c + LayerNorm over c, bf16 output
// ---------------------------------------------------------------------------
__global__ void ln_kernel(const float* __restrict__ x,
                          const float* __restrict__ w,
                          const float* __restrict__ bnorm) {
    __shared__ float tile[14 * 769];
    int b  = blockIdx.x / 196;
    int t0 = (blockIdx.x % 196) * 14;
    const float* xb = x + (size_t)b * C_ * N_;

    for (int idx = threadIdx.x; idx < C_ * 14; idx += 256) {
        int c = idx / 14, t = idx % 14;
        tile[t * 769 + c] = xb[c * N_ + t0 + t];
    }
    __syncthreads();

    int warp = threadIdx.x >> 5, lane = threadIdx.x & 31;
    for (int t = warp; t < 14; t += 8) {
        float s1 = 0.f, s2 = 0.f;
        for (int c = lane; c < C_; c += 32) {
            float v = tile[t * 769 + c];
            s1 += v; s2 += v * v;
        }
        #pragma unroll
        for (int off = 16; off; off >>= 1) {
            s1 += __shfl_xor_sync(0xffffffffu, s1, off);
            s2 += __shfl_xor_sync(0xffffffffu, s2, off);
        }
        float mu  = s1 * (1.f / C_);
        float var = s2 * (1.f / C_) - mu * mu;
        float inv = rsqrtf(var + 1e-5f);
        __nv_bfloat16* out = g_tn + (size_t)(b * N_ + t0 + t) * C_;
        for (int c = lane; c < C_; c += 32)
            out[c] = __float2bfloat16(
                (tile[t * 769 + c] - mu) * inv * w[c] + bnorm[c]);
    }
}

// ---------------------------------------------------------------------------
// Kernel 2: QKV GEMM, 128x128 block tile, warp tile 32x64.
// out[m][j] = sum_k tn[m][k] * Wqkv[j][k]; bf16 scatter to g_q/g_k/g_v.
// ---------------------------------------------------------------------------
__global__ void __launch_bounds__(256) qkv_mma_kernel() {
    __shared__ unsigned As[128 * 36];
    __shared__ unsigned Bs[128 * 36];
    int m0 = blockIdx.y * 128;
    int j0 = blockIdx.x * 128;
    int tid = threadIdx.x;
    int w = tid >> 5, lane = tid & 31;
    int wm = (w & 3) * 32;          // warp m base (4 strips)
    int wn = (w >> 2) * 64;         // warp n base (2 halves)
    int gr = lane >> 2, qd = lane & 3;
    unsigned asb = (unsigned)__cvta_generic_to_shared(As);
    unsigned bsb = (unsigned)__cvta_generic_to_shared(Bs);

    float of[2][8][4] = {};

    for (int k0 = 0; k0 < C_; k0 += 64) {
        __syncthreads();
        #pragma unroll
        for (int r = 0; r < 4; ++r) {       // stage A & B: 128 rows x 64 halves
            int idx = tid + r * 256;        // 0..1023
            int row = idx >> 3, seg = idx & 7;
            int m = m0 + row;
            uint4 av = make_uint4(0u,0u,0u,0u);
            if (m < M_)
                av = *(const uint4*)(g_tn + (size_t)m * C_ + k0 + seg * 8);
            *(uint4*)(As + row * 36 + seg * 4) = av;
            uint4 bv = *(const uint4*)(g_wqkv + (size_t)(j0 + row) * C_ + k0 + seg * 8);
            *(uint4*)(Bs + row * 36 + seg * 4) = bv;
        }
        __syncthreads();

        #pragma unroll
        for (int ks = 0; ks < 4; ++ks) {
            unsigned a0[4], a1[4];
            ldsm_x4(a0, frag_addr(asb, wm,      ks * 16, lane));
            ldsm_x4(a1, frag_addr(asb, wm + 16, ks * 16, lane));
            #pragma unroll
            for (int nt = 0; nt < 4; ++nt) {
                unsigned b[4];
                ldsm_x4(b, frag_addr(bsb, wn + nt * 16, ks * 16, lane));
                mma16816(of[0][nt * 2    ], a0, b[0], b[2]);
                mma16816(of[0][nt * 2 + 1], a0, b[1], b[3]);
                mma16816(of[1][nt * 2    ], a1, b[0], b[2]);
                mma16816(of[1][nt * 2 + 1], a1, b[1], b[3]);
            }
        }
    }

    // epilogue: warp's 64 cols = exactly one (s, h) slice (j0+wn is 64-aligned)
    int js = j0 + wn;
    int s = js / C_;
    int h = (js % C_) / DH;
    __nv_bfloat16* outp = (s == 0) ? g_q : ((s == 1) ? g_k : g_v);
    unsigned* o32 = (unsigned*)outp;
    #pragma unroll
    for (int mt = 0; mt < 2; ++mt) {
        int ma = m0 + wm + mt * 16 + gr;
        int mb2 = ma + 8;
        #pragma unroll
        for (int j = 0; j < 8; ++j) {
            int e = j * 8 + qd * 2;
            if (ma < M_) {
                int b = ma / N_, n = ma % N_;
                o32[((size_t)((b * NH + h) * N_ + n) * DH + e) >> 1] =
                    pack_bf16(of[mt][j][0], of[mt][j][1]);
            }
            if (mb2 < M_) {
                int b = mb2 / N_, n = mb2 % N_;
                o32[((size_t)((b * NH + h) * N_ + n) * DH + e) >> 1] =
                    pack_bf16(of[mt][j][2], of[mt][j][3]);
            }
        }
    }
}

// ---------------------------------------------------------------------------
// Kernel 3: tensor-core attention (validated round-10 version, unchanged).
// ---------------------------------------------------------------------------
__global__ void __launch_bounds__(256) attn_mma_kernel() {
    __shared__ unsigned Qs[64 * 36];
    __shared__ unsigned Ks[64 * 36];
    __shared__ unsigned Vs[64 * 36];     // [kk][e]
    __shared__ unsigned Ps[64 * 36];
    __shared__ float    Lsm[2][64];

    int bh = blockIdx.x;
    int q0 = blockIdx.y * 64;
    const __nv_bfloat16* qb = g_q + (size_t)bh * N_ * DH;
    const __nv_bfloat16* kb = g_k + (size_t)bh * N_ * DH;
    const __nv_bfloat16* vb = g_v + (size_t)bh * N_ * DH;

    unsigned qsb = (unsigned)__cvta_generic_to_shared(Qs);
    unsigned ksb = (unsigned)__cvta_generic_to_shared(Ks);
    unsigned vsb = (unsigned)__cvta_generic_to_shared(Vs);
    unsigned psb = (unsigned)__cvta_generic_to_shared(Ps);

    int tid  = threadIdx.x;
    int w    = tid >> 5, lane = tid & 31;
    int mr   = (w & 3) * 16;
    int nb   = (w >> 2) * 32;
    int gr   = lane >> 2;
    int qd   = lane & 3;
    int row  = tid >> 2, q4 = tid & 3;

    {   // stage Q tile
        int n = q0 + row;
        uint4 v0 = make_uint4(0u,0u,0u,0u), v1 = v0;
        if (n < N_) {
            const uint4* src = (const uint4*)(qb + (size_t)n * DH + q4 * 16);
            v0 = src[0]; v1 = src[1];
        }
        unsigned* d = Qs + row * 36 + q4 * 8;
        *(uint4*)(d)     = v0;
        *(uint4*)(d + 4) = v1;
    }
    __syncthreads();

    unsigned qa[4][4];
    #pragma unroll
    for (int ks = 0; ks < 4; ++ks)
        ldsm_x4(qa[ks], frag_addr(qsb, mr, ks * 16, lane));

    float of[4][4] = {};
    float lp0 = 0.f, lp1 = 0.f;

    for (int kb0 = 0; kb0 < N_; kb0 += 64) {
        __syncthreads();
        {   // stage K and V rows
            int n = kb0 + row;
            uint4 k0v = make_uint4(0u,0u,0u,0u), k1v = k0v, v0v = k0v, v1v = k0v;
            if (n < N_) {
                const uint4* ksrc = (const uint4*)(kb + (size_t)n * DH + q4 * 16);
                const uint4* vsrc = (const uint4*)(vb + (size_t)n * DH + q4 * 16);
                k0v = ksrc[0]; k1v = ksrc[1];
                v0v = vsrc[0]; v1v = vsrc[1];
            }
            unsigned* kd = Ks + row * 36 + q4 * 8;
            unsigned* vd = Vs + row * 36 + q4 * 8;
            *(uint4*)(kd)     = k0v;
            *(uint4*)(kd + 4) = k1v;
            *(uint4*)(vd)     = v0v;
            *(uint4*)(vd + 4) = v1v;
        }
        __syncthreads();

        float sf[4][4] = {};
        #pragma unroll
        for (int ks = 0; ks < 4; ++ks) {
            unsigned b0[4], b1[4];
            ldsm_x4(b0, frag_addr(ksb, nb,      ks * 16, lane));
            ldsm_x4(b1, frag_addr(ksb, nb + 16, ks * 16, lane));
            mma16816(sf[0], qa[ks], b0[0], b0[2]);
            mma16816(sf[1], qa[ks], b0[1], b0[3]);
            mma16816(sf[2], qa[ks], b1[0], b1[2]);
            mma16816(sf[3], qa[ks], b1[1], b1[3]);
        }

        #pragma unroll
        for (int t = 0; t < 4; ++t) {
            int kcol = nb + t * 8 + qd * 2;
            int gk = kb0 + kcol;
            bool v0 = gk < N_, v1 = (gk + 1) < N_;
            float p0 = v0 ? __expf(sf[t][0] * 0.125f) : 0.f;
            float p1 = v1 ? __expf(sf[t][1] * 0.125f) : 0.f;
            float p2 = v0 ? __expf(sf[t][2] * 0.125f) : 0.f;
            float p3 = v1 ? __expf(sf[t][3] * 0.125f) : 0.f;
            lp0 += p0 + p1;
            lp1 += p2 + p3;
            Ps[(mr + gr    ) * 36 + (kcol >> 1)] = pack_bf16(p0, p1);
            Ps[(mr + gr + 8) * 36 + (kcol >> 1)] = pack_bf16(p2, p3);
        }
        __syncthreads();

        #pragma unroll
        for (int ks = 0; ks < 4; ++ks) {
            unsigned a[4], v0[4], v1[4];
            ldsm_x4(a, frag_addr(psb, mr, ks * 16, lane));
            ldsm_x4_t(v0, frag_addr(vsb, ks * 16, nb,      lane));
            ldsm_x4_t(v1, frag_addr(vsb, ks * 16, nb + 16, lane));
            mma16816(of[0], a, v0[0], v0[1]);
            mma16816(of[1], a, v0[2], v0[3]);
            mma16816(of[2], a, v1[0], v1[1]);
            mma16816(of[3], a, v1[2], v1[3]);
        }
    }

    lp0 += __shfl_xor_sync(0xffffffffu, lp0, 1);
    lp0 += __shfl_xor_sync(0xffffffffu, lp0, 2);
    lp1 += __shfl_xor_sync(0xffffffffu, lp1, 1);
    lp1 += __shfl_xor_sync(0xffffffffu, lp1, 2);
    if (qd == 0) {
        Lsm[w >> 2][mr + gr]     = lp0;
        Lsm[w >> 2][mr + gr + 8] = lp1;
    }
    __syncthreads();

    int b = bh / NH, h = bh % NH;
    float invl0 = 1.f / (Lsm[0][mr + gr]     + Lsm[1][mr + gr]);
    float invl1 = 1.f / (Lsm[0][mr + gr + 8] + Lsm[1][mr + gr + 8]);
    int n0 = q0 + mr + gr;
    int n1 = n0 + 8;
    unsigned* ao32 = reinterpret_cast<unsigned*>(g_ao);
    #pragma unroll
    for (int t = 0; t < 4; ++t) {
        int e = nb + t * 8 + qd * 2;
        if (n0 < N_)
            ao32[((size_t)(b * N_ + n0) * C_ + h * DH + e) >> 1] =
                pack_bf16(of[t][0] * invl0, of[t][1] * invl0);
        if (n1 < N_)
            ao32[((size_t)(b * N_ + n1) * C_ + h * DH + e) >> 1] =
                pack_bf16(of[t][2] * invl1, of[t][3] * invl1);
    }
}

// ---------------------------------------------------------------------------
// Kernel 4: out projection, 128x64 block tile, warp tile 32x32.
// Ts epilogue aliases the As/Bs smem (raw union) to stay under 48KB static.
// ---------------------------------------------------------------------------
constexpr int PROJ_AB_BYTES = (128 * 36 + 64 * 36) * 4;   // 27648
constexpr int PROJ_TS_BYTES = 128 * 65 * 4;               // 33280
constexpr int PROJ_SM_BYTES = PROJ_TS_BYTES > PROJ_AB_BYTES ? PROJ_TS_BYTES
                                                            : PROJ_AB_BYTES;

__global__ void __launch_bounds__(256) proj_mma_kernel(
        const float* __restrict__ bout,
        const float* __restrict__ x,
        float* __restrict__ out) {
    __shared__ __align__(16) char sraw[PROJ_SM_BYTES];
    unsigned* As = (unsigned*)sraw;            // 128 x 36 u32
    unsigned* Bs = As + 128 * 36;              // 64 x 36 u32
    float*    Ts = (float*)sraw;               // 128 x 65 f32 (after GEMM)

    int m0 = blockIdx.y * 128;
    int c0 = blockIdx.x * 64;
    int tid = threadIdx.x;
    int w = tid >> 5, lane = tid & 31;
    int wm = (w & 3) * 32;
    int wn = (w >> 2) * 32;
    int gr = lane >> 2, qd = lane & 3;
    unsigned asb = (unsigned)__cvta_generic_to_shared(As);
    unsigned bsb = (unsigned)__cvta_generic_to_shared(Bs);

    float of[2][4][4] = {};

    for (int k0 = 0; k0 < C_; k0 += 64) {
        __syncthreads();
        #pragma unroll
        for (int r = 0; r < 4; ++r) {       // A: 128 rows
            int idx = tid + r * 256;
            int row = idx >> 3, seg = idx & 7;
            int m = m0 + row;
            uint4 av = make_uint4(0u,0u,0u,0u);
            if (m < M_)
                av = *(const uint4*)(g_ao + (size_t)m * C_ + k0 + seg * 8);
            *(uint4*)(As + row * 36 + seg * 4) = av;
        }
        #pragma unroll
        for (int r = 0; r < 2; ++r) {       // B: 64 rows
            int idx = tid + r * 256;
            int row = idx >> 3, seg = idx & 7;
            uint4 bv = *(const uint4*)(g_wout + (size_t)(c0 + row) * C_ + k0 + seg * 8);
            *(uint4*)(Bs + row * 36 + seg * 4) = bv;
        }
        __syncthreads();

        #pragma unroll
        for (int ks = 0; ks < 4; ++ks) {
            unsigned a0[4], a1[4];
            ldsm_x4(a0, frag_addr(asb, wm,      ks * 16, lane));
            ldsm_x4(a1, frag_addr(asb, wm + 16, ks * 16, lane));
            #pragma unroll
            for (int nt = 0; nt < 2; ++nt) {
                unsigned b[4];
                ldsm_x4(b, frag_addr(bsb, wn + nt * 16, ks * 16, lane));
                mma16816(of[0][nt * 2    ], a0, b[0], b[2]);
                mma16816(of[0][nt * 2 + 1], a0, b[1], b[3]);
                mma16816(of[1][nt * 2    ], a1, b[0], b[2]);
                mma16816(of[1][nt * 2 + 1], a1, b[1], b[3]);
            }
        }
    }
    __syncthreads();                         // all frag reads done; reuse smem as Ts

    #pragma unroll
    for (int mt = 0; mt < 2; ++mt) {
        #pragma unroll
        for (int j = 0; j < 4; ++j) {
            int cl = wn + j * 8 + qd * 2;
            float b0 = bout[c0 + cl], b1 = bout[c0 + cl + 1];
            int r0 = wm + mt * 16 + gr;
            Ts[r0 * 65 + cl]           = of[mt][j][0] + b0;
            Ts[r0 * 65 + cl + 1]       = of[mt][j][1] + b1;
            Ts[(r0 + 8) * 65 + cl]     = of[mt][j][2] + b0;
            Ts[(r0 + 8) * 65 + cl + 1] = of[mt][j][3] + b1;
        }
    }
    __syncthreads();

    for (int t = tid; t < 128 * 64; t += 256) {
        int cl = t >> 7, ml = t & 127;
        int m = m0 + ml;
        if (m < M_) {
            int b = m / N_, n = m % N_;
            size_t gi = (size_t)(b * C_ + c0 + cl) * N_ + n;
            out[gi] = Ts[ml * 65 + cl] + x[gi];
        }
    }
}

// ---------------------------------------------------------------------------
extern "C" void kernel_launch(void* const* d_in, const int* in_sizes, int n_in,
                              void* d_out, int out_size) {
    const float* x      = nullptr;
    const float* norm_w = nullptr;
    const float* norm_b = nullptr;
    const float* qkv_w  = nullptr;
    const float* out_w  = nullptr;
    const float* out_b  = nullptr;
    int small_seen = 0;
    for (int i = 0; i < n_in; ++i) {
        const float* p = (const float*)d_in[i];
        int sz = in_sizes[i];
        if      (sz == B_ * C_ * N_)     x     = p;
        else if (sz == 3 * C_ * C_)      qkv_w = p;
        else if (sz == C_ * C_)          out_w = p;
        else if (sz == C_) {
            if      (small_seen == 0) norm_w = p;
            else if (small_seen == 1) norm_b = p;
            else                      out_b  = p;
            ++small_seen;
        }
    }
    float* out = (float*)d_out;
    (void)out_size;

    __nv_bfloat16* wqkv_bf = nullptr;
    __nv_bfloat16* wout_bf = nullptr;
    cudaGetSymbolAddress((void**)&wqkv_bf, g_wqkv);
    cudaGetSymbolAddress((void**)&wout_bf, g_wout);

    cvt_kernel<<<(3 * C_ * C_ / 2 + 255) / 256, 256>>>(qkv_w, wqkv_bf, 3 * C_ * C_ / 2);
    cvt_kernel<<<(C_ * C_ / 2 + 255) / 256, 256>>>(out_w, wout_bf, C_ * C_ / 2);
    ln_kernel<<<B_ * 196, 256>>>(x, norm_w, norm_b);
    qkv_mma_kernel<<<dim3(3 * C_ / 128, (M_ + 127) / 128), 256>>>();
    attn_mma_kernel<<<dim3(B_ * NH, (N_ + 63) / 64), 256>>>();
    proj_mma_kernel<<<dim3(C_ / 64, (M_ + 127) / 128), 256>>>(out_b, x, out);
}

// round 12
// speedup vs baseline: 57.2626x; 1.1357x over previous
#include <cuda_runtime.h>
#include <cuda_bf16.h>
#include <math.h>

// Problem constants
constexpr int B_  = 2;
constexpr int C_  = 768;
constexpr int N_  = 2744;          // 14^3 tokens
constexpr int NH  = 12;
constexpr int DH  = 64;
constexpr int M_  = B_ * N_;       // 5488 total tokens

// Scratch (device globals; no allocation allowed)
__device__ __nv_bfloat16 g_tn  [M_ * C_];       // layernormed tokens, bf16 [m][c]
__device__ __nv_bfloat16 g_ao  [M_ * C_];       // attention output, bf16 [m][c]
__device__ __nv_bfloat16 g_wqkv[3 * C_ * C_];   // bf16 weights
__device__ __nv_bfloat16 g_wout[C_ * C_];
__device__ __nv_bfloat16 g_q [B_ * NH * N_ * DH];  // [b][h][n][e] bf16
__device__ __nv_bfloat16 g_k [B_ * NH * N_ * DH];
__device__ __nv_bfloat16 g_v [B_ * NH * N_ * DH];

// ---------------------------------------------------------------------------
// Helpers
// ---------------------------------------------------------------------------
__device__ __forceinline__ unsigned pack_bf16(float lo, float hi) {
    unsigned r;
    asm("cvt.rn.bf16x2.f32 %0, %1, %2;" : "=r"(r) : "f"(hi), "f"(lo));
    return r;
}

// D(16x8,f32) += A(16x16,bf16,row) * B(16x8,bf16,col)
__device__ __forceinline__ void mma16816(float* d, const unsigned* a,
                                         unsigned b0, unsigned b1) {
    asm volatile(
        "mma.sync.aligned.m16n8k16.row.col.f32.bf16.bf16.f32 "
        "{%0,%1,%2,%3}, {%4,%5,%6,%7}, {%8,%9}, {%0,%1,%2,%3};"
        : "+f"(d[0]), "+f"(d[1]), "+f"(d[2]), "+f"(d[3])
        : "r"(a[0]), "r"(a[1]), "r"(a[2]), "r"(a[3]), "r"(b0), "r"(b1));
}

__device__ __forceinline__ void ldsm_x4(unsigned* r, unsigned addr) {
    asm volatile("ldmatrix.sync.aligned.m8n8.x4.shared.b16 {%0,%1,%2,%3}, [%4];"
                 : "=r"(r[0]), "=r"(r[1]), "=r"(r[2]), "=r"(r[3]) : "r"(addr));
}
__device__ __forceinline__ void ldsm_x4_t(unsigned* r, unsigned addr) {
    asm volatile("ldmatrix.sync.aligned.m8n8.x4.trans.shared.b16 {%0,%1,%2,%3}, [%4];"
                 : "=r"(r[0]), "=r"(r[1]), "=r"(r[2]), "=r"(r[3]) : "r"(addr));
}

// cp.async helpers (16B, L2-cached; pred=false zero-fills destination)
__device__ __forceinline__ void cp16(unsigned dst, const void* src, bool pred) {
    unsigned sz = pred ? 16u : 0u;
    asm volatile("cp.async.cg.shared.global [%0], [%1], 16, %2;"
                 :: "r"(dst), "l"(src), "r"(sz));
}
__device__ __forceinline__ void cp_commit() {
    asm volatile("cp.async.commit_group;" ::: "memory");
}
__device__ __forceinline__ void cp_wait1() {
    asm volatile("cp.async.wait_group 1;" ::: "memory");
}
__device__ __forceinline__ void cp_wait0() {
    asm volatile("cp.async.wait_group 0;" ::: "memory");
}

// Lane address for a 16x16 bf16 block at (row0, halfcol0); row stride 144B.
// mats: {(r0..r0+7,c0), (r0+8..+15,c0), (r0..r0+7,c0+8), (r0+8..+15,c0+8)}
__device__ __forceinline__ unsigned frag_addr(unsigned base, int row0,
                                              int halfcol0, int lane) {
    int lrow = lane & 7, lm = lane >> 3;
    return base + (unsigned)((row0 + (lm & 1) * 8 + lrow) * 144 +
                             halfcol0 * 2 + (lm >> 1) * 16);
}

// ---------------------------------------------------------------------------
// Kernel 0: fp32 -> bf16 weight conversion
// ---------------------------------------------------------------------------
__global__ void cvt_kernel(const float* __restrict__ src,
                           __nv_bfloat16* __restrict__ dst, int n2) {
    int i = blockIdx.x * blockDim.x + threadIdx.x;
    if (i < n2) {
        float2 v = *(const float2*)(src + i * 2);
        *(unsigned*)((unsigned*)dst + i) = pack_bf16(v.x, v.y);
    }
}

// ---------------------------------------------------------------------------
// Kernel 1: transpose b c n -> (b n) c + LayerNorm over c, bf16 output
// ---------------------------------------------------------------------------
__global__ void ln_kernel(const float* __restrict__ x,
                          const float* __restrict__ w,
                          const float* __restrict__ bnorm) {
    __shared__ float tile[14 * 769];
    int b  = blockIdx.x / 196;
    int t0 = (blockIdx.x % 196) * 14;
    const float* xb = x + (size_t)b * C_ * N_;

    for (int idx = threadIdx.x; idx < C_ * 14; idx += 256) {
        int c = idx / 14, t = idx % 14;
        tile[t * 769 + c] = xb[c * N_ + t0 + t];
    }
    __syncthreads();

    int warp = threadIdx.x >> 5, lane = threadIdx.x & 31;
    for (int t = warp; t < 14; t += 8) {
        float s1 = 0.f, s2 = 0.f;
        for (int c = lane; c < C_; c += 32) {
            float v = tile[t * 769 + c];
            s1 += v; s2 += v * v;
        }
        #pragma unroll
        for (int off = 16; off; off >>= 1) {
            s1 += __shfl_xor_sync(0xffffffffu, s1, off);
            s2 += __shfl_xor_sync(0xffffffffu, s2, off);
        }
        float mu  = s1 * (1.f / C_);
        float var = s2 * (1.f / C_) - mu * mu;
        float inv = rsqrtf(var + 1e-5f);
        __nv_bfloat16* out = g_tn + (size_t)(b * N_ + t0 + t) * C_;
        for (int c = lane; c < C_; c += 32)
            out[c] = __float2bfloat16(
                (tile[t * 769 + c] - mu) * inv * w[c] + bnorm[c]);
    }
}

// ---------------------------------------------------------------------------
// Kernel 2: QKV GEMM, 128x128 tile, cp.async double-buffered K-chunks.
// Dynamic smem: 2 x (As 18432B + Bs 18432B) = 73728B.
// ---------------------------------------------------------------------------
constexpr unsigned QKV_BUF = 36864u;       // one (As,Bs) pair
constexpr unsigned QKV_SMEM = 2 * QKV_BUF;

__global__ void __launch_bounds__(256) qkv_mma_kernel() {
    extern __shared__ __align__(16) char dsm[];
    unsigned smb = (unsigned)__cvta_generic_to_shared(dsm);

    int m0 = blockIdx.y * 128;
    int j0 = blockIdx.x * 128;
    int tid = threadIdx.x;
    int w = tid >> 5, lane = tid & 31;
    int wm = (w & 3) * 32;
    int wn = (w >> 2) * 64;
    int gr = lane >> 2, qd = lane & 3;
    int srow = tid >> 3, sseg = tid & 7;   // staging: wait, 256 threads / 8 segs = 32 rows per pass

    // stage one 128x64-half chunk of A and B into buffer `buf`
    auto stage = [&](int buf, int k0) {
        unsigned ab = smb + buf * QKV_BUF;
        unsigned bb = ab + 18432u;
        #pragma unroll
        for (int r = 0; r < 4; ++r) {
            int idx = tid + r * 256;
            int row = idx >> 3, seg = idx & 7;
            int m = m0 + row;
            cp16(ab + row * 144 + seg * 16,
                 g_tn + (size_t)m * C_ + k0 + seg * 8, m < M_);
            cp16(bb + row * 144 + seg * 16,
                 g_wqkv + (size_t)(j0 + row) * C_ + k0 + seg * 8, true);
        }
        cp_commit();
    };

    float of[2][8][4] = {};
    constexpr int NC = C_ / 64;            // 12 chunks

    stage(0, 0);
    for (int kc = 0; kc < NC; ++kc) {
        if (kc + 1 < NC) { stage((kc + 1) & 1, (kc + 1) * 64); cp_wait1(); }
        else             { cp_wait0(); }
        __syncthreads();                   // buffer kc&1 visible to all

        unsigned ab = smb + (kc & 1) * QKV_BUF;
        unsigned bb = ab + 18432u;
        #pragma unroll
        for (int ks = 0; ks < 4; ++ks) {
            unsigned a0[4], a1[4];
            ldsm_x4(a0, frag_addr(ab, wm,      ks * 16, lane));
            ldsm_x4(a1, frag_addr(ab, wm + 16, ks * 16, lane));
            #pragma unroll
            for (int nt = 0; nt < 4; ++nt) {
                unsigned b[4];
                ldsm_x4(b, frag_addr(bb, wn + nt * 16, ks * 16, lane));
                mma16816(of[0][nt * 2    ], a0, b[0], b[2]);
                mma16816(of[0][nt * 2 + 1], a0, b[1], b[3]);
                mma16816(of[1][nt * 2    ], a1, b[0], b[2]);
                mma16816(of[1][nt * 2 + 1], a1, b[1], b[3]);
            }
        }
        __syncthreads();                   // frag reads done; buffer reusable
    }
    (void)srow; (void)sseg;

    // epilogue: warp's 64 cols = exactly one (s, h) slice
    int js = j0 + wn;
    int s = js / C_;
    int h = (js % C_) / DH;
    __nv_bfloat16* outp = (s == 0) ? g_q : ((s == 1) ? g_k : g_v);
    unsigned* o32 = (unsigned*)outp;
    #pragma unroll
    for (int mt = 0; mt < 2; ++mt) {
        int ma = m0 + wm + mt * 16 + gr;
        int mb2 = ma + 8;
        #pragma unroll
        for (int j = 0; j < 8; ++j) {
            int e = j * 8 + qd * 2;
            if (ma < M_) {
                int b = ma / N_, n = ma % N_;
                o32[((size_t)((b * NH + h) * N_ + n) * DH + e) >> 1] =
                    pack_bf16(of[mt][j][0], of[mt][j][1]);
            }
            if (mb2 < M_) {
                int b = mb2 / N_, n = mb2 % N_;
                o32[((size_t)((b * NH + h) * N_ + n) * DH + e) >> 1] =
                    pack_bf16(of[mt][j][2], of[mt][j][3]);
            }
        }
    }
}

// ---------------------------------------------------------------------------
// Kernel 3: tensor-core attention, cp.async double-buffered K/V tiles.
// Dynamic smem layout (bytes):
//   Qs @ 0      (9216)
//   Ks[buf] @ 9216  + buf*9216   (x2)
//   Vs[buf] @ 27648 + buf*9216   (x2)
//   Ps @ 46080  (9216)
//   Lsm @ 55296 (512)   -> total 55808
// ---------------------------------------------------------------------------
constexpr unsigned ATT_QS = 0u;
constexpr unsigned ATT_KS = 9216u;
constexpr unsigned ATT_VS = 27648u;
constexpr unsigned ATT_PS = 46080u;
constexpr unsigned ATT_LS = 55296u;
constexpr unsigned ATT_SMEM = 55808u;

__global__ void __launch_bounds__(256) attn_mma_kernel() {
    extern __shared__ __align__(16) char dsm[];
    unsigned smb = (unsigned)__cvta_generic_to_shared(dsm);
    float* Lsm = (float*)(dsm + ATT_LS);   // [2][64]

    int bh = blockIdx.x;
    int q0 = blockIdx.y * 64;
    const __nv_bfloat16* qb = g_q + (size_t)bh * N_ * DH;
    const __nv_bfloat16* kb = g_k + (size_t)bh * N_ * DH;
    const __nv_bfloat16* vb = g_v + (size_t)bh * N_ * DH;

    int tid  = threadIdx.x;
    int w    = tid >> 5, lane = tid & 31;
    int mr   = (w & 3) * 16;
    int nb   = (w >> 2) * 32;
    int gr   = lane >> 2;
    int qd   = lane & 3;
    int row  = tid >> 2, q4 = tid & 3;

    // stage one 64-key K/V tile into buffer `buf`
    auto stage = [&](int buf, int kb0) {
        int n = kb0 + row;
        bool ok = n < N_;
        unsigned kdst = smb + ATT_KS + buf * 9216u + row * 144 + q4 * 32;
        unsigned vdst = smb + ATT_VS + buf * 9216u + row * 144 + q4 * 32;
        const char* ksrc = (const char*)(kb + (size_t)n * DH + q4 * 16);
        const char* vsrc = (const char*)(vb + (size_t)n * DH + q4 * 16);
        cp16(kdst,      ksrc,      ok);
        cp16(kdst + 16, ksrc + 16, ok);
        cp16(vdst,      vsrc,      ok);
        cp16(vdst + 16, vsrc + 16, ok);
        cp_commit();
    };

    {   // stage Q tile (plain stores, once)
        int n = q0 + row;
        uint4 v0 = make_uint4(0u,0u,0u,0u), v1 = v0;
        if (n < N_) {
            const uint4* src = (const uint4*)(qb + (size_t)n * DH + q4 * 16);
            v0 = src[0]; v1 = src[1];
        }
        unsigned* d = (unsigned*)(dsm + ATT_QS) + row * 36 + q4 * 8;
        *(uint4*)(d)     = v0;
        *(uint4*)(d + 4) = v1;
    }

    constexpr int NT = (N_ + 63) / 64;     // 43 tiles
    stage(0, 0);
    __syncthreads();                       // Qs visible

    unsigned qa[4][4];
    #pragma unroll
    for (int ks = 0; ks < 4; ++ks)
        ldsm_x4(qa[ks], frag_addr(smb + ATT_QS, mr, ks * 16, lane));

    float of[4][4] = {};
    float lp0 = 0.f, lp1 = 0.f;

    for (int kc = 0; kc < NT; ++kc) {
        int kb0 = kc * 64;
        if (kc + 1 < NT) { stage((kc + 1) & 1, kb0 + 64); cp_wait1(); }
        else             { cp_wait0(); }
        __syncthreads();                   // K/V buffer kc&1 visible; Ps reusable

        unsigned ksb = smb + ATT_KS + (kc & 1) * 9216u;
        unsigned vsb = smb + ATT_VS + (kc & 1) * 9216u;
        unsigned psb = smb + ATT_PS;

        // ---- S = Q K^T ----
        float sf[4][4] = {};
        #pragma unroll
        for (int ks = 0; ks < 4; ++ks) {
            unsigned b0[4], b1[4];
            ldsm_x4(b0, frag_addr(ksb, nb,      ks * 16, lane));
            ldsm_x4(b1, frag_addr(ksb, nb + 16, ks * 16, lane));
            mma16816(sf[0], qa[ks], b0[0], b0[2]);
            mma16816(sf[1], qa[ks], b0[1], b0[3]);
            mma16816(sf[2], qa[ks], b1[0], b1[2]);
            mma16816(sf[3], qa[ks], b1[1], b1[3]);
        }

        // ---- p = exp(scale*s), mask, accumulate l, store Ps bf16 ----
        unsigned* Ps = (unsigned*)(dsm + ATT_PS);
        #pragma unroll
        for (int t = 0; t < 4; ++t) {
            int kcol = nb + t * 8 + qd * 2;
            int gk = kb0 + kcol;
            bool v0 = gk < N_, v1 = (gk + 1) < N_;
            float p0 = v0 ? __expf(sf[t][0] * 0.125f) : 0.f;
            float p1 = v1 ? __expf(sf[t][1] * 0.125f) : 0.f;
            float p2 = v0 ? __expf(sf[t][2] * 0.125f) : 0.f;
            float p3 = v1 ? __expf(sf[t][3] * 0.125f) : 0.f;
            lp0 += p0 + p1;
            lp1 += p2 + p3;
            Ps[(mr + gr    ) * 36 + (kcol >> 1)] = pack_bf16(p0, p1);
            Ps[(mr + gr + 8) * 36 + (kcol >> 1)] = pack_bf16(p2, p3);
        }
        __syncthreads();                   // Ps visible to all warps

        // ---- O += P V ----
        #pragma unroll
        for (int ks = 0; ks < 4; ++ks) {
            unsigned a[4], v0[4], v1[4];
            ldsm_x4(a, frag_addr(psb, mr, ks * 16, lane));
            ldsm_x4_t(v0, frag_addr(vsb, ks * 16, nb,      lane));
            ldsm_x4_t(v1, frag_addr(vsb, ks * 16, nb + 16, lane));
            mma16816(of[0], a, v0[0], v0[1]);
            mma16816(of[1], a, v0[2], v0[3]);
            mma16816(of[2], a, v1[0], v1[1]);
            mma16816(of[3], a, v1[2], v1[3]);
        }
        __syncthreads();                   // PV reads done; buffers reusable
    }

    lp0 += __shfl_xor_sync(0xffffffffu, lp0, 1);
    lp0 += __shfl_xor_sync(0xffffffffu, lp0, 2);
    lp1 += __shfl_xor_sync(0xffffffffu, lp1, 1);
    lp1 += __shfl_xor_sync(0xffffffffu, lp1, 2);
    if (qd == 0) {
        Lsm[(w >> 2) * 64 + mr + gr]     = lp0;
        Lsm[(w >> 2) * 64 + mr + gr + 8] = lp1;
    }
    __syncthreads();

    int b = bh / NH, h = bh % NH;
    float invl0 = 1.f / (Lsm[mr + gr]     + Lsm[64 + mr + gr]);
    float invl1 = 1.f / (Lsm[mr + gr + 8] + Lsm[64 + mr + gr + 8]);
    int n0 = q0 + mr + gr;
    int n1 = n0 + 8;
    unsigned* ao32 = reinterpret_cast<unsigned*>(g_ao);
    #pragma unroll
    for (int t = 0; t < 4; ++t) {
        int e = nb + t * 8 + qd * 2;
        if (n0 < N_)
            ao32[((size_t)(b * N_ + n0) * C_ + h * DH + e) >> 1] =
                pack_bf16(of[t][0] * invl0, of[t][1] * invl0);
        if (n1 < N_)
            ao32[((size_t)(b * N_ + n1) * C_ + h * DH + e) >> 1] =
                pack_bf16(of[t][2] * invl1, of[t][3] * invl1);
    }
}

// ---------------------------------------------------------------------------
// Kernel 4: out projection, 128x64 block tile, warp tile 32x32 (unchanged).
// ---------------------------------------------------------------------------
constexpr int PROJ_AB_BYTES = (128 * 36 + 64 * 36) * 4;   // 27648
constexpr int PROJ_TS_BYTES = 128 * 65 * 4;               // 33280
constexpr int PROJ_SM_BYTES = PROJ_TS_BYTES > PROJ_AB_BYTES ? PROJ_TS_BYTES
                                                            : PROJ_AB_BYTES;

__global__ void __launch_bounds__(256) proj_mma_kernel(
        const float* __restrict__ bout,
        const float* __restrict__ x,
        float* __restrict__ out) {
    __shared__ __align__(16) char sraw[PROJ_SM_BYTES];
    unsigned* As = (unsigned*)sraw;
    unsigned* Bs = As + 128 * 36;
    float*    Ts = (float*)sraw;

    int m0 = blockIdx.y * 128;
    int c0 = blockIdx.x * 64;
    int tid = threadIdx.x;
    int w = tid >> 5, lane = tid & 31;
    int wm = (w & 3) * 32;
    int wn = (w >> 2) * 32;
    int gr = lane >> 2, qd = lane & 3;
    unsigned asb = (unsigned)__cvta_generic_to_shared(As);
    unsigned bsb = (unsigned)__cvta_generic_to_shared(Bs);

    float of[2][4][4] = {};

    for (int k0 = 0; k0 < C_; k0 += 64) {
        __syncthreads();
        #pragma unroll
        for (int r = 0; r < 4; ++r) {
            int idx = tid + r * 256;
            int row = idx >> 3, seg = idx & 7;
            int m = m0 + row;
            uint4 av = make_uint4(0u,0u,0u,0u);
            if (m < M_)
                av = *(const uint4*)(g_ao + (size_t)m * C_ + k0 + seg * 8);
            *(uint4*)(As + row * 36 + seg * 4) = av;
        }
        #pragma unroll
        for (int r = 0; r < 2; ++r) {
            int idx = tid + r * 256;
            int row = idx >> 3, seg = idx & 7;
            uint4 bv = *(const uint4*)(g_wout + (size_t)(c0 + row) * C_ + k0 + seg * 8);
            *(uint4*)(Bs + row * 36 + seg * 4) = bv;
        }
        __syncthreads();

        #pragma unroll
        for (int ks = 0; ks < 4; ++ks) {
            unsigned a0[4], a1[4];
            ldsm_x4(a0, frag_addr(asb, wm,      ks * 16, lane));
            ldsm_x4(a1, frag_addr(asb, wm + 16, ks * 16, lane));
            #pragma unroll
            for (int nt = 0; nt < 2; ++nt) {
                unsigned b[4];
                ldsm_x4(b, frag_addr(bsb, wn + nt * 16, ks * 16, lane));
                mma16816(of[0][nt * 2    ], a0, b[0], b[2]);
                mma16816(of[0][nt * 2 + 1], a0, b[1], b[3]);
                mma16816(of[1][nt * 2    ], a1, b[0], b[2]);
                mma16816(of[1][nt * 2 + 1], a1, b[1], b[3]);
            }
        }
    }
    __syncthreads();

    #pragma unroll
    for (int mt = 0; mt < 2; ++mt) {
        #pragma unroll
        for (int j = 0; j < 4; ++j) {
            int cl = wn + j * 8 + qd * 2;
            float b0 = bout[c0 + cl], b1 = bout[c0 + cl + 1];
            int r0 = wm + mt * 16 + gr;
            Ts[r0 * 65 + cl]           = of[mt][j][0] + b0;
            Ts[r0 * 65 + cl + 1]       = of[mt][j][1] + b1;
            Ts[(r0 + 8) * 65 + cl]     = of[mt][j][2] + b0;
            Ts[(r0 + 8) * 65 + cl + 1] = of[mt][j][3] + b1;
        }
    }
    __syncthreads();

    for (int t = tid; t < 128 * 64; t += 256) {
        int cl = t >> 7, ml = t & 127;
        int m = m0 + ml;
        if (m < M_) {
            int b = m / N_, n = m % N_;
            size_t gi = (size_t)(b * C_ + c0 + cl) * N_ + n;
            out[gi] = Ts[ml * 65 + cl] + x[gi];
        }
    }
}

// ---------------------------------------------------------------------------
extern "C" void kernel_launch(void* const* d_in, const int* in_sizes, int n_in,
                              void* d_out, int out_size) {
    const float* x      = nullptr;
    const float* norm_w = nullptr;
    const float* norm_b = nullptr;
    const float* qkv_w  = nullptr;
    const float* out_w  = nullptr;
    const float* out_b  = nullptr;
    int small_seen = 0;
    for (int i = 0; i < n_in; ++i) {
        const float* p = (const float*)d_in[i];
        int sz = in_sizes[i];
        if      (sz == B_ * C_ * N_)     x     = p;
        else if (sz == 3 * C_ * C_)      qkv_w = p;
        else if (sz == C_ * C_)          out_w = p;
        else if (sz == C_) {
            if      (small_seen == 0) norm_w = p;
            else if (small_seen == 1) norm_b = p;
            else                      out_b  = p;
            ++small_seen;
        }
    }
    float* out = (float*)d_out;
    (void)out_size;

    __nv_bfloat16* wqkv_bf = nullptr;
    __nv_bfloat16* wout_bf = nullptr;
    cudaGetSymbolAddress((void**)&wqkv_bf, g_wqkv);
    cudaGetSymbolAddress((void**)&wout_bf, g_wout);

    // Idempotent, host-side, capture-safe.
    cudaFuncSetAttribute(qkv_mma_kernel,
                         cudaFuncAttributeMaxDynamicSharedMemorySize, QKV_SMEM);
    cudaFuncSetAttribute(attn_mma_kernel,
                         cudaFuncAttributeMaxDynamicSharedMemorySize, ATT_SMEM);

    cvt_kernel<<<(3 * C_ * C_ / 2 + 255) / 256, 256>>>(qkv_w, wqkv_bf, 3 * C_ * C_ / 2);
    cvt_kernel<<<(C_ * C_ / 2 + 255) / 256, 256>>>(out_w, wout_bf, C_ * C_ / 2);
    ln_kernel<<<B_ * 196, 256>>>(x, norm_w, norm_b);
    qkv_mma_kernel<<<dim3(3 * C_ / 128, (M_ + 127) / 128), 256, QKV_SMEM>>>();
    attn_mma_kernel<<<dim3(B_ * NH, (N_ + 63) / 64), 256, ATT_SMEM>>>();
    proj_mma_kernel<<<dim3(C_ / 64, (M_ + 127) / 128), 256>>>(out_b, x, out);
}

// round 13
// speedup vs baseline: 58.3790x; 1.0195x over previous
#include <cuda_runtime.h>
#include <cuda_bf16.h>
#include <math.h>

// Problem constants
constexpr int B_  = 2;
constexpr int C_  = 768;
constexpr int N_  = 2744;          // 14^3 tokens
constexpr int NH  = 12;
constexpr int DH  = 64;
constexpr int M_  = B_ * N_;       // 5488 total tokens

// Scratch (device globals; no allocation allowed)
__device__ __nv_bfloat16 g_tn  [M_ * C_];       // layernormed tokens, bf16 [m][c]
__device__ __nv_bfloat16 g_ao  [M_ * C_];       // attention output, bf16 [m][c]
__device__ __nv_bfloat16 g_wqkv[3 * C_ * C_];   // bf16 weights
__device__ __nv_bfloat16 g_wout[C_ * C_];
__device__ __nv_bfloat16 g_q [B_ * NH * N_ * DH];  // [b][h][n][e] bf16
__device__ __nv_bfloat16 g_k [B_ * NH * N_ * DH];
__device__ __nv_bfloat16 g_v [B_ * NH * N_ * DH];

// ---------------------------------------------------------------------------
// Helpers
// ---------------------------------------------------------------------------
__device__ __forceinline__ unsigned pack_bf16(float lo, float hi) {
    unsigned r;
    asm("cvt.rn.bf16x2.f32 %0, %1, %2;" : "=r"(r) : "f"(hi), "f"(lo));
    return r;
}

// D(16x8,f32) += A(16x16,bf16,row) * B(16x8,bf16,col)
__device__ __forceinline__ void mma16816(float* d, const unsigned* a,
                                         unsigned b0, unsigned b1) {
    asm volatile(
        "mma.sync.aligned.m16n8k16.row.col.f32.bf16.bf16.f32 "
        "{%0,%1,%2,%3}, {%4,%5,%6,%7}, {%8,%9}, {%0,%1,%2,%3};"
        : "+f"(d[0]), "+f"(d[1]), "+f"(d[2]), "+f"(d[3])
        : "r"(a[0]), "r"(a[1]), "r"(a[2]), "r"(a[3]), "r"(b0), "r"(b1));
}

__device__ __forceinline__ void ldsm_x4(unsigned* r, unsigned addr) {
    asm volatile("ldmatrix.sync.aligned.m8n8.x4.shared.b16 {%0,%1,%2,%3}, [%4];"
                 : "=r"(r[0]), "=r"(r[1]), "=r"(r[2]), "=r"(r[3]) : "r"(addr));
}
__device__ __forceinline__ void ldsm_x4_t(unsigned* r, unsigned addr) {
    asm volatile("ldmatrix.sync.aligned.m8n8.x4.trans.shared.b16 {%0,%1,%2,%3}, [%4];"
                 : "=r"(r[0]), "=r"(r[1]), "=r"(r[2]), "=r"(r[3]) : "r"(addr));
}

// cp.async helpers (16B, L2-cached; pred=false zero-fills destination)
__device__ __forceinline__ void cp16(unsigned dst, const void* src, bool pred) {
    unsigned sz = pred ? 16u : 0u;
    asm volatile("cp.async.cg.shared.global [%0], [%1], 16, %2;"
                 :: "r"(dst), "l"(src), "r"(sz));
}
__device__ __forceinline__ void cp_commit() {
    asm volatile("cp.async.commit_group;" ::: "memory");
}
__device__ __forceinline__ void cp_wait1() {
    asm volatile("cp.async.wait_group 1;" ::: "memory");
}
__device__ __forceinline__ void cp_wait0() {
    asm volatile("cp.async.wait_group 0;" ::: "memory");
}

// Lane address for a 16x16 bf16 block at (row0, halfcol0); row stride 144B.
// mats: {(r0..r0+7,c0), (r0+8..+15,c0), (r0..r0+7,c0+8), (r0+8..+15,c0+8)}
__device__ __forceinline__ unsigned frag_addr(unsigned base, int row0,
                                              int halfcol0, int lane) {
    int lrow = lane & 7, lm = lane >> 3;
    return base + (unsigned)((row0 + (lm & 1) * 8 + lrow) * 144 +
                             halfcol0 * 2 + (lm >> 1) * 16);
}

// ---------------------------------------------------------------------------
// Kernel 0: fp32 -> bf16 weight conversion
// ---------------------------------------------------------------------------
__global__ void cvt_kernel(const float* __restrict__ src,
                           __nv_bfloat16* __restrict__ dst, int n2) {
    int i = blockIdx.x * blockDim.x + threadIdx.x;
    if (i < n2) {
        float2 v = *(const float2*)(src + i * 2);
        *(unsigned*)((unsigned*)dst + i) = pack_bf16(v.x, v.y);
    }
}

// ---------------------------------------------------------------------------
// Kernel 1: LayerNorm, coalesced two-pass. Block = 32 tokens, 256 threads.
// Warp w = c-phase (c ≡ w mod 8), lane = token → every x load is a 128B line.
// ---------------------------------------------------------------------------
__global__ void __launch_bounds__(256) ln_kernel(
        const float* __restrict__ x,
        const float* __restrict__ w,
        const float* __restrict__ bnorm) {
    __shared__ float s1s[8][32], s2s[8][32];
    __shared__ float smu[32], sinv[32];
    __shared__ float tile[32][66];          // [token][c_local], padded

    int tid = threadIdx.x, wrp = tid >> 5, lane = tid & 31;
    int m  = blockIdx.x * 32 + lane;
    int mc = m < M_ ? m : M_ - 1;           // clamp for addressing
    int b = mc / N_, n = mc % N_;
    const float* xb = x + (size_t)b * C_ * N_ + n;

    // pass 1: mean/var
    float s1 = 0.f, s2 = 0.f;
    for (int c = wrp; c < C_; c += 8) {
        float v = xb[(size_t)c * N_];
        s1 += v; s2 += v * v;
    }
    s1s[wrp][lane] = s1; s2s[wrp][lane] = s2;
    __syncthreads();
    if (wrp == 0) {
        float a = 0.f, q = 0.f;
        #pragma unroll
        for (int i = 0; i < 8; ++i) { a += s1s[i][lane]; q += s2s[i][lane]; }
        float mu = a * (1.f / C_);
        float var = q * (1.f / C_) - mu * mu;
        smu[lane] = mu;
        sinv[lane] = rsqrtf(var + 1e-5f);
    }
    __syncthreads();
    float mu = smu[lane], inv = sinv[lane];

    // pass 2: normalize 64-channel chunks through smem, write packed bf16
    for (int ch = 0; ch < C_ / 64; ++ch) {
        #pragma unroll
        for (int j = 0; j < 8; ++j) {
            int cl = wrp + 8 * j;           // 0..63 across warps
            int c = ch * 64 + cl;
            float v = xb[(size_t)c * N_];
            tile[lane][cl] = (v - mu) * inv * w[c] + bnorm[c];
        }
        __syncthreads();
        #pragma unroll
        for (int r = 0; r < 4; ++r) {
            int idx = tid + r * 256;        // 1024 bf16-pairs
            int tok = idx >> 5, chalf = idx & 31;
            int mm = blockIdx.x * 32 + tok;
            if (mm < M_) {
                float lo = tile[tok][chalf * 2];
                float hi = tile[tok][chalf * 2 + 1];
                ((unsigned*)g_tn)[((size_t)mm * C_ + ch * 64) / 2 + chalf] =
                    pack_bf16(lo, hi);
            }
        }
        __syncthreads();
    }
}

// ---------------------------------------------------------------------------
// Kernel 2: QKV GEMM, 128x128 tile, cp.async double-buffered K-chunks.
// ---------------------------------------------------------------------------
constexpr unsigned QKV_BUF = 36864u;       // one (As,Bs) pair
constexpr unsigned QKV_SMEM = 2 * QKV_BUF;

__global__ void __launch_bounds__(256) qkv_mma_kernel() {
    extern __shared__ __align__(16) char dsm[];
    unsigned smb = (unsigned)__cvta_generic_to_shared(dsm);

    int m0 = blockIdx.y * 128;
    int j0 = blockIdx.x * 128;
    int tid = threadIdx.x;
    int w = tid >> 5, lane = tid & 31;
    int wm = (w & 3) * 32;
    int wn = (w >> 2) * 64;
    int gr = lane >> 2, qd = lane & 3;

    auto stage = [&](int buf, int k0) {
        unsigned ab = smb + buf * QKV_BUF;
        unsigned bb = ab + 18432u;
        #pragma unroll
        for (int r = 0; r < 4; ++r) {
            int idx = tid + r * 256;
            int row = idx >> 3, seg = idx & 7;
            int m = m0 + row;
            cp16(ab + row * 144 + seg * 16,
                 g_tn + (size_t)m * C_ + k0 + seg * 8, m < M_);
            cp16(bb + row * 144 + seg * 16,
                 g_wqkv + (size_t)(j0 + row) * C_ + k0 + seg * 8, true);
        }
        cp_commit();
    };

    float of[2][8][4] = {};
    constexpr int NC = C_ / 64;

    stage(0, 0);
    for (int kc = 0; kc < NC; ++kc) {
        if (kc + 1 < NC) { stage((kc + 1) & 1, (kc + 1) * 64); cp_wait1(); }
        else             { cp_wait0(); }
        __syncthreads();

        unsigned ab = smb + (kc & 1) * QKV_BUF;
        unsigned bb = ab + 18432u;
        #pragma unroll
        for (int ks = 0; ks < 4; ++ks) {
            unsigned a0[4], a1[4];
            ldsm_x4(a0, frag_addr(ab, wm,      ks * 16, lane));
            ldsm_x4(a1, frag_addr(ab, wm + 16, ks * 16, lane));
            #pragma unroll
            for (int nt = 0; nt < 4; ++nt) {
                unsigned b[4];
                ldsm_x4(b, frag_addr(bb, wn + nt * 16, ks * 16, lane));
                mma16816(of[0][nt * 2    ], a0, b[0], b[2]);
                mma16816(of[0][nt * 2 + 1], a0, b[1], b[3]);
                mma16816(of[1][nt * 2    ], a1, b[0], b[2]);
                mma16816(of[1][nt * 2 + 1], a1, b[1], b[3]);
            }
        }
        __syncthreads();
    }

    int js = j0 + wn;
    int s = js / C_;
    int h = (js % C_) / DH;
    __nv_bfloat16* outp = (s == 0) ? g_q : ((s == 1) ? g_k : g_v);
    unsigned* o32 = (unsigned*)outp;
    #pragma unroll
    for (int mt = 0; mt < 2; ++mt) {
        int ma = m0 + wm + mt * 16 + gr;
        int mb2 = ma + 8;
        #pragma unroll
        for (int j = 0; j < 8; ++j) {
            int e = j * 8 + qd * 2;
            if (ma < M_) {
                int b = ma / N_, n = ma % N_;
                o32[((size_t)((b * NH + h) * N_ + n) * DH + e) >> 1] =
                    pack_bf16(of[mt][j][0], of[mt][j][1]);
            }
            if (mb2 < M_) {
                int b = mb2 / N_, n = mb2 % N_;
                o32[((size_t)((b * NH + h) * N_ + n) * DH + e) >> 1] =
                    pack_bf16(of[mt][j][2], of[mt][j][3]);
            }
        }
    }
}

// ---------------------------------------------------------------------------
// Kernel 3: attention with register-resident P.
// Block = 128 queries x full key range; warp owns 16 queries x 64 keys, so
// the S fragments it computes ARE the PV A-fragments (no Ps smem, no Lsm,
// 1 barrier per tile). K/V cp.async triple-buffer ring.
// smem: Qs @0 (18432) + ring[3] x (K 9216 | V 9216) = 73728B.
// ---------------------------------------------------------------------------
constexpr unsigned ATT_RING = 18432u;
constexpr unsigned ATT_SMEM = 18432u + 3 * 18432u;

__global__ void __launch_bounds__(256) attn_mma_kernel() {
    extern __shared__ __align__(16) char dsm[];
    unsigned smb = (unsigned)__cvta_generic_to_shared(dsm);

    int bh = blockIdx.x;
    int q0 = blockIdx.y * 128;
    const __nv_bfloat16* qb = g_q + (size_t)bh * N_ * DH;
    const __nv_bfloat16* kb = g_k + (size_t)bh * N_ * DH;
    const __nv_bfloat16* vb = g_v + (size_t)bh * N_ * DH;

    int tid  = threadIdx.x;
    int w    = tid >> 5, lane = tid & 31;
    int wq   = w * 16;                 // warp's query strip
    int gr   = lane >> 2;
    int qd   = lane & 3;
    int row4 = tid >> 2, q4 = tid & 3; // staging coords

    auto stage = [&](int buf, int kb0) {
        int n = kb0 + row4;
        bool ok = n < N_;
        unsigned base = smb + ATT_RING + buf * 18432u;
        unsigned kdst = base + row4 * 144 + q4 * 32;
        unsigned vdst = base + 9216u + row4 * 144 + q4 * 32;
        const char* ksrc = (const char*)(kb + (size_t)n * DH + q4 * 16);
        const char* vsrc = (const char*)(vb + (size_t)n * DH + q4 * 16);
        cp16(kdst,      ksrc,      ok);
        cp16(kdst + 16, ksrc + 16, ok);
        cp16(vdst,      vsrc,      ok);
        cp16(vdst + 16, vsrc + 16, ok);
        cp_commit();
    };

    {   // stage Q tile: 128 rows x 64 bf16
        #pragma unroll
        for (int r = 0; r < 4; ++r) {
            int idx = tid + r * 256;
            int row = idx >> 3, seg = idx & 7;
            int n = q0 + row;
            uint4 v = make_uint4(0u,0u,0u,0u);
            if (n < N_)
                v = *(const uint4*)(qb + (size_t)n * DH + seg * 8);
            *(uint4*)((unsigned*)dsm + row * 36 + seg * 4) = v;
        }
    }

    constexpr int NT = (N_ + 63) / 64;  // 43 tiles
    stage(0, 0);
    __syncthreads();                    // Qs visible

    unsigned qa[4][4];
    #pragma unroll
    for (int ks = 0; ks < 4; ++ks)
        ldsm_x4(qa[ks], frag_addr(smb, wq, ks * 16, lane));

    float of[8][4] = {};
    float lp0 = 0.f, lp1 = 0.f;

    for (int kc = 0; kc < NT; ++kc) {
        int kb0 = kc * 64;
        if (kc + 1 < NT) { stage((kc + 1) % 3, kb0 + 64); cp_wait1(); }
        else             { cp_wait0(); }
        __syncthreads();                // ring buffer kc%3 visible (sole barrier)

        unsigned ksb = smb + ATT_RING + (kc % 3) * 18432u;
        unsigned vsb = ksb + 9216u;

        // ---- S = Q K^T : 16 queries x all 64 keys ----
        float sf[8][4] = {};
        #pragma unroll
        for (int ks = 0; ks < 4; ++ks) {
            #pragma unroll
            for (int p = 0; p < 4; ++p) {
                unsigned bb[4];
                ldsm_x4(bb, frag_addr(ksb, p * 16, ks * 16, lane));
                mma16816(sf[2 * p    ], qa[ks], bb[0], bb[2]);
                mma16816(sf[2 * p + 1], qa[ks], bb[1], bb[3]);
            }
        }

        // ---- p = exp(scale*s), mask, accumulate l (full rows in-warp) ----
        float pf[8][4];
        #pragma unroll
        for (int t = 0; t < 8; ++t) {
            int gk = kb0 + t * 8 + qd * 2;
            bool v0 = gk < N_, v1 = (gk + 1) < N_;
            pf[t][0] = v0 ? __expf(sf[t][0] * 0.125f) : 0.f;
            pf[t][1] = v1 ? __expf(sf[t][1] * 0.125f) : 0.f;
            pf[t][2] = v0 ? __expf(sf[t][2] * 0.125f) : 0.f;
            pf[t][3] = v1 ? __expf(sf[t][3] * 0.125f) : 0.f;
            lp0 += pf[t][0] + pf[t][1];
            lp1 += pf[t][2] + pf[t][3];
        }

        // ---- O += P V : P already in A-fragment layout ----
        #pragma unroll
        for (int ks = 0; ks < 4; ++ks) {
            unsigned a[4];
            a[0] = pack_bf16(pf[2 * ks][0],     pf[2 * ks][1]);
            a[1] = pack_bf16(pf[2 * ks][2],     pf[2 * ks][3]);
            a[2] = pack_bf16(pf[2 * ks + 1][0], pf[2 * ks + 1][1]);
            a[3] = pack_bf16(pf[2 * ks + 1][2], pf[2 * ks + 1][3]);
            #pragma unroll
            for (int g = 0; g < 4; ++g) {
                unsigned v[4];
                ldsm_x4_t(v, frag_addr(vsb, ks * 16, g * 16, lane));
                mma16816(of[2 * g    ], a, v[0], v[1]);
                mma16816(of[2 * g + 1], a, v[2], v[3]);
            }
        }
    }

    // l: quad-lane reduction only (warp owns full key range)
    lp0 += __shfl_xor_sync(0xffffffffu, lp0, 1);
    lp0 += __shfl_xor_sync(0xffffffffu, lp0, 2);
    lp1 += __shfl_xor_sync(0xffffffffu, lp1, 1);
    lp1 += __shfl_xor_sync(0xffffffffu, lp1, 2);
    float invl0 = 1.f / lp0;
    float invl1 = 1.f / lp1;

    int b = bh / NH, h = bh % NH;
    int n0 = q0 + wq + gr;
    int n1 = n0 + 8;
    unsigned* ao32 = reinterpret_cast<unsigned*>(g_ao);
    #pragma unroll
    for (int t = 0; t < 8; ++t) {
        int e = t * 8 + qd * 2;
        if (n0 < N_)
            ao32[((size_t)(b * N_ + n0) * C_ + h * DH + e) >> 1] =
                pack_bf16(of[t][0] * invl0, of[t][1] * invl0);
        if (n1 < N_)
            ao32[((size_t)(b * N_ + n1) * C_ + h * DH + e) >> 1] =
                pack_bf16(of[t][2] * invl1, of[t][3] * invl1);
    }
}

// ---------------------------------------------------------------------------
// Kernel 4: out projection, 128x64 block tile, warp tile 32x32 (unchanged).
// ---------------------------------------------------------------------------
constexpr int PROJ_AB_BYTES = (128 * 36 + 64 * 36) * 4;
constexpr int PROJ_TS_BYTES = 128 * 65 * 4;
constexpr int PROJ_SM_BYTES = PROJ_TS_BYTES > PROJ_AB_BYTES ? PROJ_TS_BYTES
                                                            : PROJ_AB_BYTES;

__global__ void __launch_bounds__(256) proj_mma_kernel(
        const float* __restrict__ bout,
        const float* __restrict__ x,
        float* __restrict__ out) {
    __shared__ __align__(16) char sraw[PROJ_SM_BYTES];
    unsigned* As = (unsigned*)sraw;
    unsigned* Bs = As + 128 * 36;
    float*    Ts = (float*)sraw;

    int m0 = blockIdx.y * 128;
    int c0 = blockIdx.x * 64;
    int tid = threadIdx.x;
    int w = tid >> 5, lane = tid & 31;
    int wm = (w & 3) * 32;
    int wn = (w >> 2) * 32;
    int gr = lane >> 2, qd = lane & 3;
    unsigned asb = (unsigned)__cvta_generic_to_shared(As);
    unsigned bsb = (unsigned)__cvta_generic_to_shared(Bs);

    float of[2][4][4] = {};

    for (int k0 = 0; k0 < C_; k0 += 64) {
        __syncthreads();
        #pragma unroll
        for (int r = 0; r < 4; ++r) {
            int idx = tid + r * 256;
            int row = idx >> 3, seg = idx & 7;
            int m = m0 + row;
            uint4 av = make_uint4(0u,0u,0u,0u);
            if (m < M_)
                av = *(const uint4*)(g_ao + (size_t)m * C_ + k0 + seg * 8);
            *(uint4*)(As + row * 36 + seg * 4) = av;
        }
        #pragma unroll
        for (int r = 0; r < 2; ++r) {
            int idx = tid + r * 256;
            int row = idx >> 3, seg = idx & 7;
            uint4 bv = *(const uint4*)(g_wout + (size_t)(c0 + row) * C_ + k0 + seg * 8);
            *(uint4*)(Bs + row * 36 + seg * 4) = bv;
        }
        __syncthreads();

        #pragma unroll
        for (int ks = 0; ks < 4; ++ks) {
            unsigned a0[4], a1[4];
            ldsm_x4(a0, frag_addr(asb, wm,      ks * 16, lane));
            ldsm_x4(a1, frag_addr(asb, wm + 16, ks * 16, lane));
            #pragma unroll
            for (int nt = 0; nt < 2; ++nt) {
                unsigned b[4];
                ldsm_x4(b, frag_addr(bsb, wn + nt * 16, ks * 16, lane));
                mma16816(of[0][nt * 2    ], a0, b[0], b[2]);
                mma16816(of[0][nt * 2 + 1], a0, b[1], b[3]);
                mma16816(of[1][nt * 2    ], a1, b[0], b[2]);
                mma16816(of[1][nt * 2 + 1], a1, b[1], b[3]);
            }
        }
    }
    __syncthreads();

    #pragma unroll
    for (int mt = 0; mt < 2; ++mt) {
        #pragma unroll
        for (int j = 0; j < 4; ++j) {
            int cl = wn + j * 8 + qd * 2;
            float b0 = bout[c0 + cl], b1 = bout[c0 + cl + 1];
            int r0 = wm + mt * 16 + gr;
            Ts[r0 * 65 + cl]           = of[mt][j][0] + b0;
            Ts[r0 * 65 + cl + 1]       = of[mt][j][1] + b1;
            Ts[(r0 + 8) * 65 + cl]     = of[mt][j][2] + b0;
            Ts[(r0 + 8) * 65 + cl + 1] = of[mt][j][3] + b1;
        }
    }
    __syncthreads();

    for (int t = tid; t < 128 * 64; t += 256) {
        int cl = t >> 7, ml = t & 127;
        int m = m0 + ml;
        if (m < M_) {
            int b = m / N_, n = m % N_;
            size_t gi = (size_t)(b * C_ + c0 + cl) * N_ + n;
            out[gi] = Ts[ml * 65 + cl] + x[gi];
        }
    }
}

// ---------------------------------------------------------------------------
extern "C" void kernel_launch(void* const* d_in, const int* in_sizes, int n_in,
                              void* d_out, int out_size) {
    const float* x      = nullptr;
    const float* norm_w = nullptr;
    const float* norm_b = nullptr;
    const float* qkv_w  = nullptr;
    const float* out_w  = nullptr;
    const float* out_b  = nullptr;
    int small_seen = 0;
    for (int i = 0; i < n_in; ++i) {
        const float* p = (const float*)d_in[i];
        int sz = in_sizes[i];
        if      (sz == B_ * C_ * N_)     x     = p;
        else if (sz == 3 * C_ * C_)      qkv_w = p;
        else if (sz == C_ * C_)          out_w = p;
        else if (sz == C_) {
            if      (small_seen == 0) norm_w = p;
            else if (small_seen == 1) norm_b = p;
            else                      out_b  = p;
            ++small_seen;
        }
    }
    float* out = (float*)d_out;
    (void)out_size;

    __nv_bfloat16* wqkv_bf = nullptr;
    __nv_bfloat16* wout_bf = nullptr;
    cudaGetSymbolAddress((void**)&wqkv_bf, g_wqkv);
    cudaGetSymbolAddress((void**)&wout_bf, g_wout);

    // Idempotent, host-side, capture-safe.
    cudaFuncSetAttribute(qkv_mma_kernel,
                         cudaFuncAttributeMaxDynamicSharedMemorySize, QKV_SMEM);
    cudaFuncSetAttribute(attn_mma_kernel,
                         cudaFuncAttributeMaxDynamicSharedMemorySize, ATT_SMEM);

    cvt_kernel<<<(3 * C_ * C_ / 2 + 255) / 256, 256>>>(qkv_w, wqkv_bf, 3 * C_ * C_ / 2);
    cvt_kernel<<<(C_ * C_ / 2 + 255) / 256, 256>>>(out_w, wout_bf, C_ * C_ / 2);
    ln_kernel<<<(M_ + 31) / 32, 256>>>(x, norm_w, norm_b);
    qkv_mma_kernel<<<dim3(3 * C_ / 128, (M_ + 127) / 128), 256, QKV_SMEM>>>();
    attn_mma_kernel<<<dim3(B_ * NH, (N_ + 127) / 128), 256, ATT_SMEM>>>();
    proj_mma_kernel<<<dim3(C_ / 64, (M_ + 127) / 128), 256>>>(out_b, x, out);
}

// round 14
// speedup vs baseline: 62.1987x; 1.0654x over previous
#include <cuda_runtime.h>
#include <cuda_bf16.h>
#include <math.h>

// Problem constants
constexpr int B_  = 2;
constexpr int C_  = 768;
constexpr int N_  = 2744;          // 14^3 tokens
constexpr int NH  = 12;
constexpr int DH  = 64;
constexpr int M_  = B_ * N_;       // 5488 total tokens

// Scratch (device globals; no allocation allowed)
__device__ __nv_bfloat16 g_tn  [M_ * C_];       // layernormed tokens, bf16 [m][c]
__device__ __nv_bfloat16 g_ao  [M_ * C_];       // attention output, bf16 [m][c]
__device__ __nv_bfloat16 g_wqkv[3 * C_ * C_];   // bf16 weights
__device__ __nv_bfloat16 g_wout[C_ * C_];
__device__ __nv_bfloat16 g_q [B_ * NH * N_ * DH];  // [b][h][n][e] bf16
__device__ __nv_bfloat16 g_k [B_ * NH * N_ * DH];
__device__ __nv_bfloat16 g_v [B_ * NH * N_ * DH];

// ---------------------------------------------------------------------------
// Helpers
// ---------------------------------------------------------------------------
__device__ __forceinline__ unsigned pack_bf16(float lo, float hi) {
    unsigned r;
    asm("cvt.rn.bf16x2.f32 %0, %1, %2;" : "=r"(r) : "f"(hi), "f"(lo));
    return r;
}

// D(16x8,f32) += A(16x16,bf16,row) * B(16x8,bf16,col)
__device__ __forceinline__ void mma16816(float* d, const unsigned* a,
                                         unsigned b0, unsigned b1) {
    asm volatile(
        "mma.sync.aligned.m16n8k16.row.col.f32.bf16.bf16.f32 "
        "{%0,%1,%2,%3}, {%4,%5,%6,%7}, {%8,%9}, {%0,%1,%2,%3};"
        : "+f"(d[0]), "+f"(d[1]), "+f"(d[2]), "+f"(d[3])
        : "r"(a[0]), "r"(a[1]), "r"(a[2]), "r"(a[3]), "r"(b0), "r"(b1));
}

__device__ __forceinline__ void ldsm_x4(unsigned* r, unsigned addr) {
    asm volatile("ldmatrix.sync.aligned.m8n8.x4.shared.b16 {%0,%1,%2,%3}, [%4];"
                 : "=r"(r[0]), "=r"(r[1]), "=r"(r[2]), "=r"(r[3]) : "r"(addr));
}
__device__ __forceinline__ void ldsm_x4_t(unsigned* r, unsigned addr) {
    asm volatile("ldmatrix.sync.aligned.m8n8.x4.trans.shared.b16 {%0,%1,%2,%3}, [%4];"
                 : "=r"(r[0]), "=r"(r[1]), "=r"(r[2]), "=r"(r[3]) : "r"(addr));
}

// cp.async helpers (16B, L2-cached; pred=false zero-fills destination)
__device__ __forceinline__ void cp16(unsigned dst, const void* src, bool pred) {
    unsigned sz = pred ? 16u : 0u;
    asm volatile("cp.async.cg.shared.global [%0], [%1], 16, %2;"
                 :: "r"(dst), "l"(src), "r"(sz));
}
__device__ __forceinline__ void cp_commit() {
    asm volatile("cp.async.commit_group;" ::: "memory");
}
__device__ __forceinline__ void cp_wait1() {
    asm volatile("cp.async.wait_group 1;" ::: "memory");
}
__device__ __forceinline__ void cp_wait0() {
    asm volatile("cp.async.wait_group 0;" ::: "memory");
}

// Lane address for a 16x16 bf16 block at (row0, halfcol0); row stride 144B.
__device__ __forceinline__ unsigned frag_addr(unsigned base, int row0,
                                              int halfcol0, int lane) {
    int lrow = lane & 7, lm = lane >> 3;
    return base + (unsigned)((row0 + (lm & 1) * 8 + lrow) * 144 +
                             halfcol0 * 2 + (lm >> 1) * 16);
}

// ---------------------------------------------------------------------------
// Kernel 0: fp32 -> bf16 conversion of BOTH weight matrices in one launch.
// ---------------------------------------------------------------------------
constexpr int CVT_NQ = 3 * C_ * C_ / 2;      // qkv pairs
constexpr int CVT_NO = C_ * C_ / 2;          // out pairs
__global__ void cvt_kernel(const float* __restrict__ qkvw,
                           const float* __restrict__ outw) {
    int i = blockIdx.x * blockDim.x + threadIdx.x;
    if (i < CVT_NQ) {
        float2 v = *(const float2*)(qkvw + (size_t)i * 2);
        ((unsigned*)g_wqkv)[i] = pack_bf16(v.x, v.y);
    } else if (i < CVT_NQ + CVT_NO) {
        int j = i - CVT_NQ;
        float2 v = *(const float2*)(outw + (size_t)j * 2);
        ((unsigned*)g_wout)[j] = pack_bf16(v.x, v.y);
    }
}

// ---------------------------------------------------------------------------
// Kernel 1: LayerNorm, coalesced two-pass. Block = 32 tokens, 256 threads.
// ---------------------------------------------------------------------------
__global__ void __launch_bounds__(256) ln_kernel(
        const float* __restrict__ x,
        const float* __restrict__ w,
        const float* __restrict__ bnorm) {
    __shared__ float s1s[8][32], s2s[8][32];
    __shared__ float smu[32], sinv[32];
    __shared__ float tile[32][66];

    int tid = threadIdx.x, wrp = tid >> 5, lane = tid & 31;
    int m  = blockIdx.x * 32 + lane;
    int mc = m < M_ ? m : M_ - 1;
    int b = mc / N_, n = mc % N_;
    const float* xb = x + (size_t)b * C_ * N_ + n;

    float s1 = 0.f, s2 = 0.f;
    for (int c = wrp; c < C_; c += 8) {
        float v = xb[(size_t)c * N_];
        s1 += v; s2 += v * v;
    }
    s1s[wrp][lane] = s1; s2s[wrp][lane] = s2;
    __syncthreads();
    if (wrp == 0) {
        float a = 0.f, q = 0.f;
        #pragma unroll
        for (int i = 0; i < 8; ++i) { a += s1s[i][lane]; q += s2s[i][lane]; }
        float mu = a * (1.f / C_);
        float var = q * (1.f / C_) - mu * mu;
        smu[lane] = mu;
        sinv[lane] = rsqrtf(var + 1e-5f);
    }
    __syncthreads();
    float mu = smu[lane], inv = sinv[lane];

    for (int ch = 0; ch < C_ / 64; ++ch) {
        #pragma unroll
        for (int j = 0; j < 8; ++j) {
            int cl = wrp + 8 * j;
            int c = ch * 64 + cl;
            float v = xb[(size_t)c * N_];
            tile[lane][cl] = (v - mu) * inv * w[c] + bnorm[c];
        }
        __syncthreads();
        #pragma unroll
        for (int r = 0; r < 4; ++r) {
            int idx = tid + r * 256;
            int tok = idx >> 5, chalf = idx & 31;
            int mm = blockIdx.x * 32 + tok;
            if (mm < M_) {
                float lo = tile[tok][chalf * 2];
                float hi = tile[tok][chalf * 2 + 1];
                ((unsigned*)g_tn)[((size_t)mm * C_ + ch * 64) / 2 + chalf] =
                    pack_bf16(lo, hi);
            }
        }
        __syncthreads();
    }
}

// ---------------------------------------------------------------------------
// Kernel 2: QKV GEMM, 128x128 tile, cp.async double-buffered K-chunks.
// ---------------------------------------------------------------------------
constexpr unsigned QKV_BUF = 36864u;
constexpr unsigned QKV_SMEM = 2 * QKV_BUF;

__global__ void __launch_bounds__(256) qkv_mma_kernel() {
    extern __shared__ __align__(16) char dsm[];
    unsigned smb = (unsigned)__cvta_generic_to_shared(dsm);

    int m0 = blockIdx.y * 128;
    int j0 = blockIdx.x * 128;
    int tid = threadIdx.x;
    int w = tid >> 5, lane = tid & 31;
    int wm = (w & 3) * 32;
    int wn = (w >> 2) * 64;
    int gr = lane >> 2, qd = lane & 3;

    auto stage = [&](int buf, int k0) {
        unsigned ab = smb + buf * QKV_BUF;
        unsigned bb = ab + 18432u;
        #pragma unroll
        for (int r = 0; r < 4; ++r) {
            int idx = tid + r * 256;
            int row = idx >> 3, seg = idx & 7;
            int m = m0 + row;
            cp16(ab + row * 144 + seg * 16,
                 g_tn + (size_t)m * C_ + k0 + seg * 8, m < M_);
            cp16(bb + row * 144 + seg * 16,
                 g_wqkv + (size_t)(j0 + row) * C_ + k0 + seg * 8, true);
        }
        cp_commit();
    };

    float of[2][8][4] = {};
    constexpr int NC = C_ / 64;

    stage(0, 0);
    for (int kc = 0; kc < NC; ++kc) {
        if (kc + 1 < NC) { stage((kc + 1) & 1, (kc + 1) * 64); cp_wait1(); }
        else             { cp_wait0(); }
        __syncthreads();

        unsigned ab = smb + (kc & 1) * QKV_BUF;
        unsigned bb = ab + 18432u;
        #pragma unroll
        for (int ks = 0; ks < 4; ++ks) {
            unsigned a0[4], a1[4];
            ldsm_x4(a0, frag_addr(ab, wm,      ks * 16, lane));
            ldsm_x4(a1, frag_addr(ab, wm + 16, ks * 16, lane));
            #pragma unroll
            for (int nt = 0; nt < 4; ++nt) {
                unsigned b[4];
                ldsm_x4(b, frag_addr(bb, wn + nt * 16, ks * 16, lane));
                mma16816(of[0][nt * 2    ], a0, b[0], b[2]);
                mma16816(of[0][nt * 2 + 1], a0, b[1], b[3]);
                mma16816(of[1][nt * 2    ], a1, b[0], b[2]);
                mma16816(of[1][nt * 2 + 1], a1, b[1], b[3]);
            }
        }
        __syncthreads();
    }

    int js = j0 + wn;
    int s = js / C_;
    int h = (js % C_) / DH;
    __nv_bfloat16* outp = (s == 0) ? g_q : ((s == 1) ? g_k : g_v);
    unsigned* o32 = (unsigned*)outp;
    #pragma unroll
    for (int mt = 0; mt < 2; ++mt) {
        int ma = m0 + wm + mt * 16 + gr;
        int mb2 = ma + 8;
        #pragma unroll
        for (int j = 0; j < 8; ++j) {
            int e = j * 8 + qd * 2;
            if (ma < M_) {
                int b = ma / N_, n = ma % N_;
                o32[((size_t)((b * NH + h) * N_ + n) * DH + e) >> 1] =
                    pack_bf16(of[mt][j][0], of[mt][j][1]);
            }
            if (mb2 < M_) {
                int b = mb2 / N_, n = mb2 % N_;
                o32[((size_t)((b * NH + h) * N_ + n) * DH + e) >> 1] =
                    pack_bf16(of[mt][j][2], of[mt][j][3]);
            }
        }
    }
}

// ---------------------------------------------------------------------------
// Kernel 3: attention, register-resident P, register-dieted.
// pf[] eliminated: exp + l-accumulate + pack fused into the PV ks-loop.
// __launch_bounds__(256,2) pins <=128 regs -> 2 CTAs/SM.
// ---------------------------------------------------------------------------
constexpr unsigned ATT_RING = 18432u;
constexpr unsigned ATT_SMEM = 18432u + 3 * 18432u;

__global__ void __launch_bounds__(256, 2) attn_mma_kernel() {
    extern __shared__ __align__(16) char dsm[];
    unsigned smb = (unsigned)__cvta_generic_to_shared(dsm);

    int bh = blockIdx.x;
    int q0 = blockIdx.y * 128;
    const __nv_bfloat16* qb = g_q + (size_t)bh * N_ * DH;
    const __nv_bfloat16* kb = g_k + (size_t)bh * N_ * DH;
    const __nv_bfloat16* vb = g_v + (size_t)bh * N_ * DH;

    int tid  = threadIdx.x;
    int w    = tid >> 5, lane = tid & 31;
    int wq   = w * 16;
    int gr   = lane >> 2;
    int qd   = lane & 3;
    int row4 = tid >> 2, q4 = tid & 3;

    auto stage = [&](int buf, int kb0) {
        int n = kb0 + row4;
        bool ok = n < N_;
        unsigned base = smb + ATT_RING + buf * 18432u;
        unsigned kdst = base + row4 * 144 + q4 * 32;
        unsigned vdst = base + 9216u + row4 * 144 + q4 * 32;
        const char* ksrc = (const char*)(kb + (size_t)n * DH + q4 * 16);
        const char* vsrc = (const char*)(vb + (size_t)n * DH + q4 * 16);
        cp16(kdst,      ksrc,      ok);
        cp16(kdst + 16, ksrc + 16, ok);
        cp16(vdst,      vsrc,      ok);
        cp16(vdst + 16, vsrc + 16, ok);
        cp_commit();
    };

    {   // stage Q tile: 128 rows x 64 bf16
        #pragma unroll
        for (int r = 0; r < 4; ++r) {
            int idx = tid + r * 256;
            int row = idx >> 3, seg = idx & 7;
            int n = q0 + row;
            uint4 v = make_uint4(0u,0u,0u,0u);
            if (n < N_)
                v = *(const uint4*)(qb + (size_t)n * DH + seg * 8);
            *(uint4*)((unsigned*)dsm + row * 36 + seg * 4) = v;
        }
    }

    constexpr int NT = (N_ + 63) / 64;
    stage(0, 0);
    __syncthreads();

    unsigned qa[4][4];
    #pragma unroll
    for (int ks = 0; ks < 4; ++ks)
        ldsm_x4(qa[ks], frag_addr(smb, wq, ks * 16, lane));

    float of[8][4] = {};
    float lp0 = 0.f, lp1 = 0.f;

    for (int kc = 0; kc < NT; ++kc) {
        int kb0 = kc * 64;
        if (kc + 1 < NT) { stage((kc + 1) % 3, kb0 + 64); cp_wait1(); }
        else             { cp_wait0(); }
        __syncthreads();

        unsigned ksb = smb + ATT_RING + (kc % 3) * 18432u;
        unsigned vsb = ksb + 9216u;

        // ---- S = Q K^T : 16 queries x all 64 keys ----
        float sf[8][4] = {};
        #pragma unroll
        for (int ks = 0; ks < 4; ++ks) {
            #pragma unroll
            for (int p = 0; p < 4; ++p) {
                unsigned bb[4];
                ldsm_x4(bb, frag_addr(ksb, p * 16, ks * 16, lane));
                mma16816(sf[2 * p    ], qa[ks], bb[0], bb[2]);
                mma16816(sf[2 * p + 1], qa[ks], bb[1], bb[3]);
            }
        }

        // ---- fused softmax + PV: exp, l-accumulate, pack into A-frags ----
        #pragma unroll
        for (int ks = 0; ks < 4; ++ks) {
            unsigned a[4];
            #pragma unroll
            for (int hh = 0; hh < 2; ++hh) {
                int t = 2 * ks + hh;
                int gk = kb0 + t * 8 + qd * 2;
                bool v0 = gk < N_, v1 = (gk + 1) < N_;
                float p0 = v0 ? __expf(sf[t][0] * 0.125f) : 0.f;
                float p1 = v1 ? __expf(sf[t][1] * 0.125f) : 0.f;
                float p2 = v0 ? __expf(sf[t][2] * 0.125f) : 0.f;
                float p3 = v1 ? __expf(sf[t][3] * 0.125f) : 0.f;
                lp0 += p0 + p1;
                lp1 += p2 + p3;
                a[2 * hh]     = pack_bf16(p0, p1);
                a[2 * hh + 1] = pack_bf16(p2, p3);
            }
            #pragma unroll
            for (int g = 0; g < 4; ++g) {
                unsigned v[4];
                ldsm_x4_t(v, frag_addr(vsb, ks * 16, g * 16, lane));
                mma16816(of[2 * g    ], a, v[0], v[1]);
                mma16816(of[2 * g + 1], a, v[2], v[3]);
            }
        }
    }

    lp0 += __shfl_xor_sync(0xffffffffu, lp0, 1);
    lp0 += __shfl_xor_sync(0xffffffffu, lp0, 2);
    lp1 += __shfl_xor_sync(0xffffffffu, lp1, 1);
    lp1 += __shfl_xor_sync(0xffffffffu, lp1, 2);
    float invl0 = 1.f / lp0;
    float invl1 = 1.f / lp1;

    int b = bh / NH, h = bh % NH;
    int n0 = q0 + wq + gr;
    int n1 = n0 + 8;
    unsigned* ao32 = reinterpret_cast<unsigned*>(g_ao);
    #pragma unroll
    for (int t = 0; t < 8; ++t) {
        int e = t * 8 + qd * 2;
        if (n0 < N_)
            ao32[((size_t)(b * N_ + n0) * C_ + h * DH + e) >> 1] =
                pack_bf16(of[t][0] * invl0, of[t][1] * invl0);
        if (n1 < N_)
            ao32[((size_t)(b * N_ + n1) * C_ + h * DH + e) >> 1] =
                pack_bf16(of[t][2] * invl1, of[t][3] * invl1);
    }
}

// ---------------------------------------------------------------------------
// Kernel 4: out projection, 128x64 tile, cp.async double-buffered.
// Dynamic smem: 2 x (A 18432 + B 9216) = 55296B; Ts (33280B) aliases it.
// ---------------------------------------------------------------------------
constexpr unsigned PROJ_BUF  = 27648u;
constexpr unsigned PROJ_SMEM = 2 * PROJ_BUF;   // 55296 >= Ts 33280

__global__ void __launch_bounds__(256) proj_mma_kernel(
        const float* __restrict__ bout,
        const float* __restrict__ x,
        float* __restrict__ out) {
    extern __shared__ __align__(16) char dsm[];
    unsigned smb = (unsigned)__cvta_generic_to_shared(dsm);
    float* Ts = (float*)dsm;

    int m0 = blockIdx.y * 128;
    int c0 = blockIdx.x * 64;
    int tid = threadIdx.x;
    int w = tid >> 5, lane = tid & 31;
    int wm = (w & 3) * 32;
    int wn = (w >> 2) * 32;
    int gr = lane >> 2, qd = lane & 3;

    auto stage = [&](int buf, int k0) {
        unsigned ab = smb + buf * PROJ_BUF;
        unsigned bb = ab + 18432u;
        #pragma unroll
        for (int r = 0; r < 4; ++r) {       // A: 128 rows
            int idx = tid + r * 256;
            int row = idx >> 3, seg = idx & 7;
            int m = m0 + row;
            cp16(ab + row * 144 + seg * 16,
                 g_ao + (size_t)m * C_ + k0 + seg * 8, m < M_);
        }
        #pragma unroll
        for (int r = 0; r < 2; ++r) {       // B: 64 rows
            int idx = tid + r * 256;
            int row = idx >> 3, seg = idx & 7;
            cp16(bb + row * 144 + seg * 16,
                 g_wout + (size_t)(c0 + row) * C_ + k0 + seg * 8, true);
        }
        cp_commit();
    };

    float of[2][4][4] = {};
    constexpr int NC = C_ / 64;

    stage(0, 0);
    for (int kc = 0; kc < NC; ++kc) {
        if (kc + 1 < NC) { stage((kc + 1) & 1, (kc + 1) * 64); cp_wait1(); }
        else             { cp_wait0(); }
        __syncthreads();

        unsigned ab = smb + (kc & 1) * PROJ_BUF;
        unsigned bb = ab + 18432u;
        #pragma unroll
        for (int ks = 0; ks < 4; ++ks) {
            unsigned a0[4], a1[4];
            ldsm_x4(a0, frag_addr(ab, wm,      ks * 16, lane));
            ldsm_x4(a1, frag_addr(ab, wm + 16, ks * 16, lane));
            #pragma unroll
            for (int nt = 0; nt < 2; ++nt) {
                unsigned b[4];
                ldsm_x4(b, frag_addr(bb, wn + nt * 16, ks * 16, lane));
                mma16816(of[0][nt * 2    ], a0, b[0], b[2]);
                mma16816(of[0][nt * 2 + 1], a0, b[1], b[3]);
                mma16816(of[1][nt * 2    ], a1, b[0], b[2]);
                mma16816(of[1][nt * 2 + 1], a1, b[1], b[3]);
            }
        }
        __syncthreads();
    }

    // epilogue: bias into Ts (aliases the staging smem; synced above)
    #pragma unroll
    for (int mt = 0; mt < 2; ++mt) {
        #pragma unroll
        for (int j = 0; j < 4; ++j) {
            int cl = wn + j * 8 + qd * 2;
            float b0 = bout[c0 + cl], b1 = bout[c0 + cl + 1];
            int r0 = wm + mt * 16 + gr;
            Ts[r0 * 65 + cl]           = of[mt][j][0] + b0;
            Ts[r0 * 65 + cl + 1]       = of[mt][j][1] + b1;
            Ts[(r0 + 8) * 65 + cl]     = of[mt][j][2] + b0;
            Ts[(r0 + 8) * 65 + cl + 1] = of[mt][j][3] + b1;
        }
    }
    __syncthreads();

    for (int t = tid; t < 128 * 64; t += 256) {
        int cl = t >> 7, ml = t & 127;
        int m = m0 + ml;
        if (m < M_) {
            int b = m / N_, n = m % N_;
            size_t gi = (size_t)(b * C_ + c0 + cl) * N_ + n;
            out[gi] = Ts[ml * 65 + cl] + x[gi];
        }
    }
}

// ---------------------------------------------------------------------------
extern "C" void kernel_launch(void* const* d_in, const int* in_sizes, int n_in,
                              void* d_out, int out_size) {
    const float* x      = nullptr;
    const float* norm_w = nullptr;
    const float* norm_b = nullptr;
    const float* qkv_w  = nullptr;
    const float* out_w  = nullptr;
    const float* out_b  = nullptr;
    int small_seen = 0;
    for (int i = 0; i < n_in; ++i) {
        const float* p = (const float*)d_in[i];
        int sz = in_sizes[i];
        if      (sz == B_ * C_ * N_)     x     = p;
        else if (sz == 3 * C_ * C_)      qkv_w = p;
        else if (sz == C_ * C_)          out_w = p;
        else if (sz == C_) {
            if      (small_seen == 0) norm_w = p;
            else if (small_seen == 1) norm_b = p;
            else                      out_b  = p;
            ++small_seen;
        }
    }
    float* out = (float*)d_out;
    (void)out_size;

    // Idempotent, host-side, capture-safe.
    cudaFuncSetAttribute(qkv_mma_kernel,
                         cudaFuncAttributeMaxDynamicSharedMemorySize, QKV_SMEM);
    cudaFuncSetAttribute(attn_mma_kernel,
                         cudaFuncAttributeMaxDynamicSharedMemorySize, ATT_SMEM);
    cudaFuncSetAttribute(proj_mma_kernel,
                         cudaFuncAttributeMaxDynamicSharedMemorySize, PROJ_SMEM);

    cvt_kernel<<<(CVT_NQ + CVT_NO + 255) / 256, 256>>>(qkv_w, out_w);
    ln_kernel<<<(M_ + 31) / 32, 256>>>(x, norm_w, norm_b);
    qkv_mma_kernel<<<dim3(3 * C_ / 128, (M_ + 127) / 128), 256, QKV_SMEM>>>();
    attn_mma_kernel<<<dim3(B_ * NH, (N_ + 127) / 128), 256, ATT_SMEM>>>();
    proj_mma_kernel<<<dim3(C_ / 64, (M_ + 127) / 128), 256, PROJ_SMEM>>>(out_b, x, out);
}

// round 15
// speedup vs baseline: 67.9467x; 1.0924x over previous
#include <cuda_runtime.h>
#include <cuda_bf16.h>
#include <math.h>

// Problem constants
constexpr int B_  = 2;
constexpr int C_  = 768;
constexpr int N_  = 2744;          // 14^3 tokens
constexpr int NH  = 12;
constexpr int DH  = 64;
constexpr int M_  = B_ * N_;       // 5488 total tokens

// Q pre-scale folded into qkv epilogue: 0.125 * log2(e)
constexpr float QSCALE = 0.18033688f;

// Scratch (device globals; no allocation allowed)
__device__ __nv_bfloat16 g_tn  [M_ * C_];
__device__ __nv_bfloat16 g_ao  [M_ * C_];
__device__ __nv_bfloat16 g_wqkv[3 * C_ * C_];
__device__ __nv_bfloat16 g_wout[C_ * C_];
__device__ __nv_bfloat16 g_q [B_ * NH * N_ * DH];
__device__ __nv_bfloat16 g_k [B_ * NH * N_ * DH];
__device__ __nv_bfloat16 g_v [B_ * NH * N_ * DH];

// ---------------------------------------------------------------------------
// Helpers
// ---------------------------------------------------------------------------
__device__ __forceinline__ unsigned pack_bf16(float lo, float hi) {
    unsigned r;
    asm("cvt.rn.bf16x2.f32 %0, %1, %2;" : "=r"(r) : "f"(hi), "f"(lo));
    return r;
}
__device__ __forceinline__ float ex2f(float x) {
    float y;
    asm("ex2.approx.f32 %0, %1;" : "=f"(y) : "f"(x));
    return y;
}

__device__ __forceinline__ void mma16816(float* d, const unsigned* a,
                                         unsigned b0, unsigned b1) {
    asm volatile(
        "mma.sync.aligned.m16n8k16.row.col.f32.bf16.bf16.f32 "
        "{%0,%1,%2,%3}, {%4,%5,%6,%7}, {%8,%9}, {%0,%1,%2,%3};"
        : "+f"(d[0]), "+f"(d[1]), "+f"(d[2]), "+f"(d[3])
        : "r"(a[0]), "r"(a[1]), "r"(a[2]), "r"(a[3]), "r"(b0), "r"(b1));
}

__device__ __forceinline__ void ldsm_x4(unsigned* r, unsigned addr) {
    asm volatile("ldmatrix.sync.aligned.m8n8.x4.shared.b16 {%0,%1,%2,%3}, [%4];"
                 : "=r"(r[0]), "=r"(r[1]), "=r"(r[2]), "=r"(r[3]) : "r"(addr));
}
__device__ __forceinline__ void ldsm_x4_t(unsigned* r, unsigned addr) {
    asm volatile("ldmatrix.sync.aligned.m8n8.x4.trans.shared.b16 {%0,%1,%2,%3}, [%4];"
                 : "=r"(r[0]), "=r"(r[1]), "=r"(r[2]), "=r"(r[3]) : "r"(addr));
}

__device__ __forceinline__ void cp16(unsigned dst, const void* src, bool pred) {
    unsigned sz = pred ? 16u : 0u;
    asm volatile("cp.async.cg.shared.global [%0], [%1], 16, %2;"
                 :: "r"(dst), "l"(src), "r"(sz));
}
__device__ __forceinline__ void cp_commit() {
    asm volatile("cp.async.commit_group;" ::: "memory");
}
__device__ __forceinline__ void cp_wait1() {
    asm volatile("cp.async.wait_group 1;" ::: "memory");
}
__device__ __forceinline__ void cp_wait0() {
    asm volatile("cp.async.wait_group 0;" ::: "memory");
}

// Lane address for a 16x16 bf16 block at (row0, halfcol0); row stride 144B.
__device__ __forceinline__ unsigned frag_addr(unsigned base, int row0,
                                              int halfcol0, int lane) {
    int lrow = lane & 7, lm = lane >> 3;
    return base + (unsigned)((row0 + (lm & 1) * 8 + lrow) * 144 +
                             halfcol0 * 2 + (lm >> 1) * 16);
}

// ---------------------------------------------------------------------------
// Kernel 0: fp32 -> bf16 conversion of both weight matrices in one launch.
// ---------------------------------------------------------------------------
constexpr int CVT_NQ = 3 * C_ * C_ / 2;
constexpr int CVT_NO = C_ * C_ / 2;
__global__ void cvt_kernel(const float* __restrict__ qkvw,
                           const float* __restrict__ outw) {
    int i = blockIdx.x * blockDim.x + threadIdx.x;
    if (i < CVT_NQ) {
        float2 v = *(const float2*)(qkvw + (size_t)i * 2);
        ((unsigned*)g_wqkv)[i] = pack_bf16(v.x, v.y);
    } else if (i < CVT_NQ + CVT_NO) {
        int j = i - CVT_NQ;
        float2 v = *(const float2*)(outw + (size_t)j * 2);
        ((unsigned*)g_wout)[j] = pack_bf16(v.x, v.y);
    }
}

// ---------------------------------------------------------------------------
// Kernel 1: LayerNorm, coalesced two-pass.
// ---------------------------------------------------------------------------
__global__ void __launch_bounds__(256) ln_kernel(
        const float* __restrict__ x,
        const float* __restrict__ w,
        const float* __restrict__ bnorm) {
    __shared__ float s1s[8][32], s2s[8][32];
    __shared__ float smu[32], sinv[32];
    __shared__ float tile[32][66];

    int tid = threadIdx.x, wrp = tid >> 5, lane = tid & 31;
    int m  = blockIdx.x * 32 + lane;
    int mc = m < M_ ? m : M_ - 1;
    int b = mc / N_, n = mc % N_;
    const float* xb = x + (size_t)b * C_ * N_ + n;

    float s1 = 0.f, s2 = 0.f;
    for (int c = wrp; c < C_; c += 8) {
        float v = xb[(size_t)c * N_];
        s1 += v; s2 += v * v;
    }
    s1s[wrp][lane] = s1; s2s[wrp][lane] = s2;
    __syncthreads();
    if (wrp == 0) {
        float a = 0.f, q = 0.f;
        #pragma unroll
        for (int i = 0; i < 8; ++i) { a += s1s[i][lane]; q += s2s[i][lane]; }
        float mu = a * (1.f / C_);
        float var = q * (1.f / C_) - mu * mu;
        smu[lane] = mu;
        sinv[lane] = rsqrtf(var + 1e-5f);
    }
    __syncthreads();
    float mu = smu[lane], inv = sinv[lane];

    for (int ch = 0; ch < C_ / 64; ++ch) {
        #pragma unroll
        for (int j = 0; j < 8; ++j) {
            int cl = wrp + 8 * j;
            int c = ch * 64 + cl;
            float v = xb[(size_t)c * N_];
            tile[lane][cl] = (v - mu) * inv * w[c] + bnorm[c];
        }
        __syncthreads();
        #pragma unroll
        for (int r = 0; r < 4; ++r) {
            int idx = tid + r * 256;
            int tok = idx >> 5, chalf = idx & 31;
            int mm = blockIdx.x * 32 + tok;
            if (mm < M_) {
                float lo = tile[tok][chalf * 2];
                float hi = tile[tok][chalf * 2 + 1];
                ((unsigned*)g_tn)[((size_t)mm * C_ + ch * 64) / 2 + chalf] =
                    pack_bf16(lo, hi);
            }
        }
        __syncthreads();
    }
}

// ---------------------------------------------------------------------------
// Kernel 2: QKV GEMM, 128x128 tile, cp.async double-buffered.
// Q output pre-scaled by QSCALE (folds softmax scale + log2e into q).
// ---------------------------------------------------------------------------
constexpr unsigned QKV_BUF = 36864u;
constexpr unsigned QKV_SMEM = 2 * QKV_BUF;

__global__ void __launch_bounds__(256) qkv_mma_kernel() {
    extern __shared__ __align__(16) char dsm[];
    unsigned smb = (unsigned)__cvta_generic_to_shared(dsm);

    int m0 = blockIdx.y * 128;
    int j0 = blockIdx.x * 128;
    int tid = threadIdx.x;
    int w = tid >> 5, lane = tid & 31;
    int wm = (w & 3) * 32;
    int wn = (w >> 2) * 64;
    int gr = lane >> 2, qd = lane & 3;

    auto stage = [&](int buf, int k0) {
        unsigned ab = smb + buf * QKV_BUF;
        unsigned bb = ab + 18432u;
        #pragma unroll
        for (int r = 0; r < 4; ++r) {
            int idx = tid + r * 256;
            int row = idx >> 3, seg = idx & 7;
            int m = m0 + row;
            cp16(ab + row * 144 + seg * 16,
                 g_tn + (size_t)m * C_ + k0 + seg * 8, m < M_);
            cp16(bb + row * 144 + seg * 16,
                 g_wqkv + (size_t)(j0 + row) * C_ + k0 + seg * 8, true);
        }
        cp_commit();
    };

    float of[2][8][4] = {};
    constexpr int NC = C_ / 64;

    stage(0, 0);
    for (int kc = 0; kc < NC; ++kc) {
        if (kc + 1 < NC) { stage((kc + 1) & 1, (kc + 1) * 64); cp_wait1(); }
        else             { cp_wait0(); }
        __syncthreads();

        unsigned ab = smb + (kc & 1) * QKV_BUF;
        unsigned bb = ab + 18432u;
        #pragma unroll
        for (int ks = 0; ks < 4; ++ks) {
            unsigned a0[4], a1[4];
            ldsm_x4(a0, frag_addr(ab, wm,      ks * 16, lane));
            ldsm_x4(a1, frag_addr(ab, wm + 16, ks * 16, lane));
            #pragma unroll
            for (int nt = 0; nt < 4; ++nt) {
                unsigned b[4];
                ldsm_x4(b, frag_addr(bb, wn + nt * 16, ks * 16, lane));
                mma16816(of[0][nt * 2    ], a0, b[0], b[2]);
                mma16816(of[0][nt * 2 + 1], a0, b[1], b[3]);
                mma16816(of[1][nt * 2    ], a1, b[0], b[2]);
                mma16816(of[1][nt * 2 + 1], a1, b[1], b[3]);
            }
        }
        __syncthreads();
    }

    int js = j0 + wn;
    int s = js / C_;
    int h = (js % C_) / DH;
    __nv_bfloat16* outp = (s == 0) ? g_q : ((s == 1) ? g_k : g_v);
    float sc = (s == 0) ? QSCALE : 1.0f;     // pre-scale Q only
    unsigned* o32 = (unsigned*)outp;
    #pragma unroll
    for (int mt = 0; mt < 2; ++mt) {
        int ma = m0 + wm + mt * 16 + gr;
        int mb2 = ma + 8;
        #pragma unroll
        for (int j = 0; j < 8; ++j) {
            int e = j * 8 + qd * 2;
            if (ma < M_) {
                int b = ma / N_, n = ma % N_;
                o32[((size_t)((b * NH + h) * N_ + n) * DH + e) >> 1] =
                    pack_bf16(of[mt][j][0] * sc, of[mt][j][1] * sc);
            }
            if (mb2 < M_) {
                int b = mb2 / N_, n = mb2 % N_;
                o32[((size_t)((b * NH + h) * N_ + n) * DH + e) >> 1] =
                    pack_bf16(of[mt][j][2] * sc, of[mt][j][3] * sc);
            }
        }
    }
}

// ---------------------------------------------------------------------------
// Kernel 3: attention, per-key-group fused loop (low register pressure).
// For each 16-key group: S-MMAs (8 live regs) -> ex2 -> pack -> PV update.
// Accumulation order identical to previous rounds. Mask code only on the
// final partial tile (uniform branch). 3 CTAs/SM target.
// ---------------------------------------------------------------------------
constexpr unsigned ATT_RING = 18432u;
constexpr unsigned ATT_SMEM = 18432u + 3 * 18432u;

__global__ void __launch_bounds__(256, 3) attn_mma_kernel() {
    extern __shared__ __align__(16) char dsm[];
    unsigned smb = (unsigned)__cvta_generic_to_shared(dsm);

    int bh = blockIdx.x;
    int q0 = blockIdx.y * 128;
    const __nv_bfloat16* qb = g_q + (size_t)bh * N_ * DH;
    const __nv_bfloat16* kb = g_k + (size_t)bh * N_ * DH;
    const __nv_bfloat16* vb = g_v + (size_t)bh * N_ * DH;

    int tid  = threadIdx.x;
    int w    = tid >> 5, lane = tid & 31;
    int wq   = w * 16;
    int gr   = lane >> 2;
    int qd   = lane & 3;
    int row4 = tid >> 2, q4 = tid & 3;

    auto stage = [&](unsigned roff, int kb0) {
        int n = kb0 + row4;
        bool ok = n < N_;
        unsigned base = smb + ATT_RING + roff;
        unsigned kdst = base + row4 * 144 + q4 * 32;
        unsigned vdst = base + 9216u + row4 * 144 + q4 * 32;
        const char* ksrc = (const char*)(kb + (size_t)n * DH + q4 * 16);
        const char* vsrc = (const char*)(vb + (size_t)n * DH + q4 * 16);
        cp16(kdst,      ksrc,      ok);
        cp16(kdst + 16, ksrc + 16, ok);
        cp16(vdst,      vsrc,      ok);
        cp16(vdst + 16, vsrc + 16, ok);
        cp_commit();
    };

    {   // stage Q tile: 128 rows x 64 bf16
        #pragma unroll
        for (int r = 0; r < 4; ++r) {
            int idx = tid + r * 256;
            int row = idx >> 3, seg = idx & 7;
            int n = q0 + row;
            uint4 v = make_uint4(0u,0u,0u,0u);
            if (n < N_)
                v = *(const uint4*)(qb + (size_t)n * DH + seg * 8);
            *(uint4*)((unsigned*)dsm + row * 36 + seg * 4) = v;
        }
    }

    constexpr int NT = (N_ + 63) / 64;
    stage(0u, 0);
    __syncthreads();

    unsigned qa[4][4];
    #pragma unroll
    for (int ks = 0; ks < 4; ++ks)
        ldsm_x4(qa[ks], frag_addr(smb, wq, ks * 16, lane));

    float of[8][4] = {};
    float lp0 = 0.f, lp1 = 0.f;

    unsigned roff = 0u, rnext = 18432u;      // manual ring offsets (mod 3*18432)
    for (int kc = 0; kc < NT; ++kc) {
        int kb0 = kc * 64;
        if (kc + 1 < NT) { stage(rnext, kb0 + 64); cp_wait1(); }
        else             { cp_wait0(); }
        __syncthreads();

        unsigned ksb = smb + ATT_RING + roff;
        unsigned vsb = ksb + 9216u;
        bool full = (kb0 + 64 <= N_);        // uniform across block

        #pragma unroll
        for (int p = 0; p < 4; ++p) {        // 16-key group
            // ---- S for this key group ----
            float s0[4] = {}, s1[4] = {};
            #pragma unroll
            for (int ks = 0; ks < 4; ++ks) {
                unsigned bb[4];
                ldsm_x4(bb, frag_addr(ksb, p * 16, ks * 16, lane));
                mma16816(s0, qa[ks], bb[0], bb[2]);
                mma16816(s1, qa[ks], bb[1], bb[3]);
            }

            // ---- ex2 + pack (mask only on last partial tile) ----
            unsigned a[4];
            if (full) {
                float p0 = ex2f(s0[0]), p1 = ex2f(s0[1]);
                float p2 = ex2f(s0[2]), p3 = ex2f(s0[3]);
                float p4 = ex2f(s1[0]), p5 = ex2f(s1[1]);
                float p6 = ex2f(s1[2]), p7 = ex2f(s1[3]);
                lp0 += (p0 + p1) + (p4 + p5);
                lp1 += (p2 + p3) + (p6 + p7);
                a[0] = pack_bf16(p0, p1); a[1] = pack_bf16(p2, p3);
                a[2] = pack_bf16(p4, p5); a[3] = pack_bf16(p6, p7);
            } else {
                int gk0 = kb0 + p * 16 + qd * 2;
                int gk1 = gk0 + 8;
                bool u0 = gk0 < N_, u1 = (gk0 + 1) < N_;
                bool u2 = gk1 < N_, u3 = (gk1 + 1) < N_;
                float p0 = u0 ? ex2f(s0[0]) : 0.f;
                float p1 = u1 ? ex2f(s0[1]) : 0.f;
                float p2 = u0 ? ex2f(s0[2]) : 0.f;
                float p3 = u1 ? ex2f(s0[3]) : 0.f;
                float p4 = u2 ? ex2f(s1[0]) : 0.f;
                float p5 = u3 ? ex2f(s1[1]) : 0.f;
                float p6 = u2 ? ex2f(s1[2]) : 0.f;
                float p7 = u3 ? ex2f(s1[3]) : 0.f;
                lp0 += (p0 + p1) + (p4 + p5);
                lp1 += (p2 + p3) + (p6 + p7);
                a[0] = pack_bf16(p0, p1); a[1] = pack_bf16(p2, p3);
                a[2] = pack_bf16(p4, p5); a[3] = pack_bf16(p6, p7);
            }

            // ---- PV partial update for this key group ----
            #pragma unroll
            for (int g = 0; g < 4; ++g) {
                unsigned v[4];
                ldsm_x4_t(v, frag_addr(vsb, p * 16, g * 16, lane));
                mma16816(of[2 * g    ], a, v[0], v[1]);
                mma16816(of[2 * g + 1], a, v[2], v[3]);
            }
        }

        roff = rnext;
        rnext += 18432u;
        if (rnext == 3 * 18432u) rnext = 0u;
    }

    lp0 += __shfl_xor_sync(0xffffffffu, lp0, 1);
    lp0 += __shfl_xor_sync(0xffffffffu, lp0, 2);
    lp1 += __shfl_xor_sync(0xffffffffu, lp1, 1);
    lp1 += __shfl_xor_sync(0xffffffffu, lp1, 2);
    float invl0 = 1.f / lp0;
    float invl1 = 1.f / lp1;

    int b = bh / NH, h = bh % NH;
    int n0 = q0 + wq + gr;
    int n1 = n0 + 8;
    unsigned* ao32 = reinterpret_cast<unsigned*>(g_ao);
    #pragma unroll
    for (int t = 0; t < 8; ++t) {
        int e = t * 8 + qd * 2;
        if (n0 < N_)
            ao32[((size_t)(b * N_ + n0) * C_ + h * DH + e) >> 1] =
                pack_bf16(of[t][0] * invl0, of[t][1] * invl0);
        if (n1 < N_)
            ao32[((size_t)(b * N_ + n1) * C_ + h * DH + e) >> 1] =
                pack_bf16(of[t][2] * invl1, of[t][3] * invl1);
    }
}

// ---------------------------------------------------------------------------
// Kernel 4: out projection, 128x64 tile, cp.async double-buffered.
// ---------------------------------------------------------------------------
constexpr unsigned PROJ_BUF  = 27648u;
constexpr unsigned PROJ_SMEM = 2 * PROJ_BUF;

__global__ void __launch_bounds__(256) proj_mma_kernel(
        const float* __restrict__ bout,
        const float* __restrict__ x,
        float* __restrict__ out) {
    extern __shared__ __align__(16) char dsm[];
    unsigned smb = (unsigned)__cvta_generic_to_shared(dsm);
    float* Ts = (float*)dsm;

    int m0 = blockIdx.y * 128;
    int c0 = blockIdx.x * 64;
    int tid = threadIdx.x;
    int w = tid >> 5, lane = tid & 31;
    int wm = (w & 3) * 32;
    int wn = (w >> 2) * 32;
    int gr = lane >> 2, qd = lane & 3;

    auto stage = [&](int buf, int k0) {
        unsigned ab = smb + buf * PROJ_BUF;
        unsigned bb = ab + 18432u;
        #pragma unroll
        for (int r = 0; r < 4; ++r) {
            int idx = tid + r * 256;
            int row = idx >> 3, seg = idx & 7;
            int m = m0 + row;
            cp16(ab + row * 144 + seg * 16,
                 g_ao + (size_t)m * C_ + k0 + seg * 8, m < M_);
        }
        #pragma unroll
        for (int r = 0; r < 2; ++r) {
            int idx = tid + r * 256;
            int row = idx >> 3, seg = idx & 7;
            cp16(bb + row * 144 + seg * 16,
                 g_wout + (size_t)(c0 + row) * C_ + k0 + seg * 8, true);
        }
        cp_commit();
    };

    float of[2][4][4] = {};
    constexpr int NC = C_ / 64;

    stage(0, 0);
    for (int kc = 0; kc < NC; ++kc) {
        if (kc + 1 < NC) { stage((kc + 1) & 1, (kc + 1) * 64); cp_wait1(); }
        else             { cp_wait0(); }
        __syncthreads();

        unsigned ab = smb + (kc & 1) * PROJ_BUF;
        unsigned bb = ab + 18432u;
        #pragma unroll
        for (int ks = 0; ks < 4; ++ks) {
            unsigned a0[4], a1[4];
            ldsm_x4(a0, frag_addr(ab, wm,      ks * 16, lane));
            ldsm_x4(a1, frag_addr(ab, wm + 16, ks * 16, lane));
            #pragma unroll
            for (int nt = 0; nt < 2; ++nt) {
                unsigned b[4];
                ldsm_x4(b, frag_addr(bb, wn + nt * 16, ks * 16, lane));
                mma16816(of[0][nt * 2    ], a0, b[0], b[2]);
                mma16816(of[0][nt * 2 + 1], a0, b[1], b[3]);
                mma16816(of[1][nt * 2    ], a1, b[0], b[2]);
                mma16816(of[1][nt * 2 + 1], a1, b[1], b[3]);
            }
        }
        __syncthreads();
    }

    #pragma unroll
    for (int mt = 0; mt < 2; ++mt) {
        #pragma unroll
        for (int j = 0; j < 4; ++j) {
            int cl = wn + j * 8 + qd * 2;
            float b0 = bout[c0 + cl], b1 = bout[c0 + cl + 1];
            int r0 = wm + mt * 16 + gr;
            Ts[r0 * 65 + cl]           = of[mt][j][0] + b0;
            Ts[r0 * 65 + cl + 1]       = of[mt][j][1] + b1;
            Ts[(r0 + 8) * 65 + cl]     = of[mt][j][2] + b0;
            Ts[(r0 + 8) * 65 + cl + 1] = of[mt][j][3] + b1;
        }
    }
    __syncthreads();

    for (int t = tid; t < 128 * 64; t += 256) {
        int cl = t >> 7, ml = t & 127;
        int m = m0 + ml;
        if (m < M_) {
            int b = m / N_, n = m % N_;
            size_t gi = (size_t)(b * C_ + c0 + cl) * N_ + n;
            out[gi] = Ts[ml * 65 + cl] + x[gi];
        }
    }
}

// ---------------------------------------------------------------------------
extern "C" void kernel_launch(void* const* d_in, const int* in_sizes, int n_in,
                              void* d_out, int out_size) {
    const float* x      = nullptr;
    const float* norm_w = nullptr;
    const float* norm_b = nullptr;
    const float* qkv_w  = nullptr;
    const float* out_w  = nullptr;
    const float* out_b  = nullptr;
    int small_seen = 0;
    for (int i = 0; i < n_in; ++i) {
        const float* p = (const float*)d_in[i];
        int sz = in_sizes[i];
        if      (sz == B_ * C_ * N_)     x     = p;
        else if (sz == 3 * C_ * C_)      qkv_w = p;
        else if (sz == C_ * C_)          out_w = p;
        else if (sz == C_) {
            if      (small_seen == 0) norm_w = p;
            else if (small_seen == 1) norm_b = p;
            else                      out_b  = p;
            ++small_seen;
        }
    }
    float* out = (float*)d_out;
    (void)out_size;

    // Idempotent, host-side, capture-safe.
    cudaFuncSetAttribute(qkv_mma_kernel,
                         cudaFuncAttributeMaxDynamicSharedMemorySize, QKV_SMEM);
    cudaFuncSetAttribute(attn_mma_kernel,
                         cudaFuncAttributeMaxDynamicSharedMemorySize, ATT_SMEM);
    cudaFuncSetAttribute(proj_mma_kernel,
                         cudaFuncAttributeMaxDynamicSharedMemorySize, PROJ_SMEM);

    cvt_kernel<<<(CVT_NQ + CVT_NO + 255) / 256, 256>>>(qkv_w, out_w);
    ln_kernel<<<(M_ + 31) / 32, 256>>>(x, norm_w, norm_b);
    qkv_mma_kernel<<<dim3(3 * C_ / 128, (M_ + 127) / 128), 256, QKV_SMEM>>>();
    attn_mma_kernel<<<dim3(B_ * NH, (N_ + 127) / 128), 256, ATT_SMEM>>>();
    proj_mma_kernel<<<dim3(C_ / 64, (M_ + 127) / 128), 256, PROJ_SMEM>>>(out_b, x, out);
}